// round 7
// baseline (speedup 1.0000x reference)
#include <cuda_runtime.h>
#include <cuda_bf16.h>
#include <cstdint>
#include <math.h>

// Problem constants
#define Bz   16
#define LC   512
#define LQ   64
#define Hd   256
#define ROWS (Bz*LC)     // 8192

// Split-K padded strides (K'' = 3 * K), all in bf16 elements
#define KX   3072        // x'' / W1''  (K=1024)
#define KH   1536        // h1'' / W2'' (K=512)
#define KS   3072        // s1''/e1''/T''/wbt (K=1024, exact)

// -------------------- device scratch (zero-init .bss) --------------------
__device__ float g_q2[Bz*LQ];
__device__ float g_rowmax[ROWS];
__device__ float g_q2c[Bz*Hd];
__device__ float g_w01[3*1024];
__device__ float g_w10[3*1024];
__device__ float g_w11[3];
__device__ float g_u[48*512];
__device__ float g_v[48*512];
__device__ __align__(16) __nv_bfloat16 g_xs [(size_t)ROWS*KX];
__device__ __align__(16) __nv_bfloat16 g_h1s[(size_t)ROWS*KH];
__device__ __align__(16) __nv_bfloat16 g_s1s[(size_t)ROWS*KS];
__device__ __align__(16) __nv_bfloat16 g_e1s[(size_t)ROWS*KS];
__device__ __align__(16) __nv_bfloat16 g_Ts [(size_t)48*LC*KS];
__device__ __align__(16) __nv_bfloat16 g_w1s[(size_t)512*KX];
__device__ __align__(16) __nv_bfloat16 g_w1e[(size_t)512*KX];
__device__ __align__(16) __nv_bfloat16 g_w2s[(size_t)1024*KH];
__device__ __align__(16) __nv_bfloat16 g_w2e[(size_t)1024*KH];
__device__ __align__(16) __nv_bfloat16 g_wbt[(size_t)3*1024*KS];

// -------------------- helpers --------------------
__device__ __forceinline__ uint32_t smem_u32(const void* p) {
    uint32_t a;
    asm("{ .reg .u64 t; cvta.to.shared.u64 t, %1; cvt.u32.u64 %0, t; }" : "=r"(a) : "l"(p));
    return a;
}
__device__ __forceinline__ void cp16(uint32_t saddr, const void* g) {
    asm volatile("cp.async.ca.shared.global [%0], [%1], 16;" :: "r"(saddr), "l"(g) : "memory");
}
__device__ __forceinline__ void cp_commit() { asm volatile("cp.async.commit_group;" ::: "memory"); }
__device__ __forceinline__ void cp_wait0()  { asm volatile("cp.async.wait_group 0;" ::: "memory"); }
__device__ __forceinline__ void cp_wait1()  { asm volatile("cp.async.wait_group 1;" ::: "memory"); }

__device__ __forceinline__ void split2(float v, __nv_bfloat16& hi, __nv_bfloat16& lo) {
    hi = __float2bfloat16(v);
    lo = __float2bfloat16(v - __bfloat162float(hi));
}
__device__ __forceinline__ unsigned short b16bits(__nv_bfloat16 h) {
    return *reinterpret_cast<unsigned short*>(&h);
}
__device__ __forceinline__ void ldm4(uint32_t* r, uint32_t saddr) {
    asm volatile("ldmatrix.sync.aligned.m8n8.x4.shared.b16 {%0,%1,%2,%3}, [%4];"
                 : "=r"(r[0]), "=r"(r[1]), "=r"(r[2]), "=r"(r[3]) : "r"(saddr));
}
__device__ __forceinline__ void mma16816(float* c, const uint32_t* a, const uint32_t* b) {
    asm volatile(
        "mma.sync.aligned.m16n8k16.row.col.f32.bf16.bf16.f32 "
        "{%0,%1,%2,%3}, {%4,%5,%6,%7}, {%8,%9}, {%0,%1,%2,%3};"
        : "+f"(c[0]), "+f"(c[1]), "+f"(c[2]), "+f"(c[3])
        : "r"(a[0]), "r"(a[1]), "r"(a[2]), "r"(a[3]), "r"(b[0]), "r"(b[1]));
}

// -------------------- attention front-end --------------------
__device__ __forceinline__ void xsplit_store(__nv_bfloat16* xr, int col, float v) {
    __nv_bfloat16 hi, lo; split2(v, hi, lo);
    xr[col] = hi; xr[col + 1024] = lo; xr[col + 2048] = hi;   // A-layout: hi, lo, hi
}

__global__ void qdot_kernel(const float* __restrict__ ques, const float* __restrict__ wsim,
                            float* __restrict__ q2) {
    int b = blockIdx.x, j = blockIdx.y, l = threadIdx.x;
    const float* q = ques + ((size_t)(b*LQ + j))*Hd;
    float s = 0.f;
    #pragma unroll
    for (int u = 0; u < Hd/32; u++) s += q[l + u*32] * wsim[Hd + l + u*32];
    #pragma unroll
    for (int o = 16; o > 0; o >>= 1) s += __shfl_down_sync(0xffffffffu, s, o);
    if (l == 0) q2[b*LQ + j] = s;
}

__global__ void sim_softmax_c2q_kernel(const float* __restrict__ ctx,
                                       const float* __restrict__ ques,
                                       const float* __restrict__ wsim,
                                       const float* __restrict__ q2,
                                       __nv_bfloat16* __restrict__ xs,
                                       float* __restrict__ rowmax) {
    int row = blockIdx.x, b = row >> 9;
    int t = threadIdx.x, w = t >> 5, l = t & 31;
    __shared__ float ctxs[Hd], cw3[Hd], simv[LQ], sred[8];
    __shared__ float c1s;

    const float* crow = ctx + (size_t)row * Hd;
    float cv = crow[t];
    ctxs[t] = cv;
    cw3[t]  = cv * wsim[2*Hd + t];

    float v = cv * wsim[t];
    #pragma unroll
    for (int o = 16; o > 0; o >>= 1) v += __shfl_down_sync(0xffffffffu, v, o);
    if (l == 0) sred[w] = v;
    __syncthreads();
    if (t == 0) { float s = 0.f; for (int u = 0; u < 8; u++) s += sred[u]; c1s = s; }
    __syncthreads();

    const float* qb = ques + (size_t)b * LQ * Hd;
    #pragma unroll
    for (int jj = 0; jj < 8; jj++) {
        int j = w * 8 + jj;
        const float* q = qb + (size_t)j * Hd;
        float s = 0.f;
        #pragma unroll
        for (int u = 0; u < Hd/32; u++) s += cw3[l + u*32] * q[l + u*32];
        #pragma unroll
        for (int o = 16; o > 0; o >>= 1) s += __shfl_down_sync(0xffffffffu, s, o);
        if (l == 0) simv[j] = c1s + q2[b*LQ + j] + s;
    }
    __syncthreads();

    if (t < 32) {
        float s0 = simv[t], s1v = simv[t + 32];
        float m = fmaxf(s0, s1v);
        #pragma unroll
        for (int o = 16; o > 0; o >>= 1) m = fmaxf(m, __shfl_xor_sync(0xffffffffu, m, o));
        if (t == 0) rowmax[row] = m;
        float e0 = expf(s0 - m), e1v = expf(s1v - m);
        float sum = e0 + e1v;
        #pragma unroll
        for (int o = 16; o > 0; o >>= 1) sum += __shfl_xor_sync(0xffffffffu, sum, o);
        float inv = 1.f / sum;
        simv[t] = e0 * inv; simv[t + 32] = e1v * inv;
    }
    __syncthreads();

    float acc = 0.f;
    #pragma unroll 8
    for (int j = 0; j < LQ; j++) acc += simv[j] * qb[(size_t)j*Hd + t];

    __nv_bfloat16* xr = xs + (size_t)row * KX;
    xsplit_store(xr, t,        ctxs[t]);
    xsplit_store(xr, Hd + t,   acc);
    xsplit_store(xr, 2*Hd + t, ctxs[t] * acc);
}

__global__ void bsoftmax_q2c_kernel(const float* __restrict__ ctx,
                                    const float* __restrict__ rowmax,
                                    float* __restrict__ q2c) {
    int b = blockIdx.x, t = threadIdx.x;
    __shared__ float w[LC]; __shared__ float sred[8]; __shared__ float mshared, sshared;
    w[t] = rowmax[b*LC + t]; w[t + 256] = rowmax[b*LC + t + 256];
    __syncthreads();
    float m = fmaxf(w[t], w[t + 256]);
    #pragma unroll
    for (int o = 16; o > 0; o >>= 1) m = fmaxf(m, __shfl_xor_sync(0xffffffffu, m, o));
    if ((t & 31) == 0) sred[t >> 5] = m;
    __syncthreads();
    if (t == 0) { float mm = sred[0]; for (int u = 1; u < 8; u++) mm = fmaxf(mm, sred[u]); mshared = mm; }
    __syncthreads();
    m = mshared;
    float e0 = expf(w[t] - m), e1v = expf(w[t + 256] - m);
    float s = e0 + e1v;
    #pragma unroll
    for (int o = 16; o > 0; o >>= 1) s += __shfl_xor_sync(0xffffffffu, s, o);
    if ((t & 31) == 0) sred[t >> 5] = s;
    __syncthreads();
    if (t == 0) { float ss = 0.f; for (int u = 0; u < 8; u++) ss += sred[u]; sshared = ss; }
    __syncthreads();
    float inv = 1.f / sshared;
    w[t] = e0 * inv; w[t + 256] = e1v * inv;
    __syncthreads();
    float acc = 0.f;
    const float* cb = ctx + (size_t)b * LC * Hd;
    for (int i = 0; i < LC; i++) acc += w[i] * cb[(size_t)i*Hd + t];
    q2c[b*Hd + t] = acc;
}

__global__ void fillx4_kernel(const float* __restrict__ ctx,
                              const float* __restrict__ q2c,
                              __nv_bfloat16* __restrict__ xs) {
    int row = blockIdx.x, t = threadIdx.x, b = row >> 9;
    float c = ctx[(size_t)row*Hd + t];
    xsplit_store(xs + (size_t)row*KX, 3*Hd + t, c * q2c[b*Hd + t]);
}

// extract rank-1 parts of Wb: w01[c][i]=Wb[i,c,1024], w10[c][j]=Wb[1024,c,j], w11[c]
__global__ void extract_w_kernel(const float* __restrict__ Wb,
                                 float* __restrict__ w01, float* __restrict__ w10,
                                 float* __restrict__ w11) {
    int i = blockIdx.x*256 + threadIdx.x;   // 0..1023
    #pragma unroll
    for (int c = 0; c < 3; c++) {
        w01[c*1024 + i] = Wb[(size_t)i*3075 + c*1025 + 1024];
        w10[c*1024 + i] = Wb[(size_t)1024*3075 + c*1025 + i];
    }
    if (i < 3) w11[i] = Wb[(size_t)1024*3075 + (size_t)i*1025 + 1024];
}

// u[z=b*3+c][x] = start[b,x]·w01[c] + w11[c] ; v[z][y] = end[b,y]·w10[c]
__global__ void uv_kernel(const __nv_bfloat16* __restrict__ s1s,
                          const __nv_bfloat16* __restrict__ e1s,
                          const float* __restrict__ w01, const float* __restrict__ w10,
                          const float* __restrict__ w11,
                          float* __restrict__ u, float* __restrict__ v) {
    int row = blockIdx.x, t = threadIdx.x, w = t >> 5, l = t & 31;
    int b = row >> 9, x = row & 511;
    const __nv_bfloat16* sr = s1s + (size_t)row*KS;
    const __nv_bfloat16* er = e1s + (size_t)row*KS;
    float a[6] = {0,0,0,0,0,0};
    for (int i = t; i < 1024; i += 256) {
        float sv = __bfloat162float(sr[i]) + __bfloat162float(sr[i + 1024]);  // A-layout: hi,lo,hi
        float ev = __bfloat162float(er[i]) + __bfloat162float(er[i + 2048]);  // B-layout: hi,hi,lo
        #pragma unroll
        for (int c = 0; c < 3; c++) {
            a[c]     += sv * w01[c*1024 + i];
            a[3 + c] += ev * w10[c*1024 + i];
        }
    }
    __shared__ float red[6][8];
    #pragma unroll
    for (int q = 0; q < 6; q++) {
        float s = a[q];
        #pragma unroll
        for (int o = 16; o > 0; o >>= 1) s += __shfl_down_sync(0xffffffffu, s, o);
        if (l == 0) red[q][w] = s;
    }
    __syncthreads();
    if (t < 6) {
        float s = 0.f;
        #pragma unroll
        for (int k = 0; k < 8; k++) s += red[t][k];
        if (t < 3) u[(b*3 + t)*512 + x] = s + w11[t];
        else       v[(b*3 + (t - 3))*512 + x] = s;
    }
}

// Transpose + split weights into B-layout [N rows x 3*Kpad]: blocks (hi, hi, lo)
__global__ void prep_bsplit(const float* __restrict__ src, int srcLd,
                            __nv_bfloat16* __restrict__ dst,
                            int Kreal, int Kpad, int Nrows) {
    __shared__ float tile[32][33];
    int k0 = blockIdx.y*32, n0 = blockIdx.x*32;
    int tx = threadIdx.x, ty = threadIdx.y;
    #pragma unroll
    for (int i = 0; i < 32; i += 8) {
        int k = k0 + ty + i, n = n0 + tx;
        tile[ty + i][tx] = (k < Kreal && n < Nrows) ? src[(size_t)k*srcLd + n] : 0.f;
    }
    __syncthreads();
    int ldd = 3*Kpad;
    #pragma unroll
    for (int i = 0; i < 32; i += 8) {
        int n = n0 + ty + i, k = k0 + tx;
        if (n < Nrows) {
            __nv_bfloat16 hi, lo; split2(tile[tx][ty + i], hi, lo);
            size_t base = (size_t)n*ldd + k;
            dst[base] = hi; dst[base + Kpad] = hi; dst[base + 2*Kpad] = lo;
        }
    }
}

// ------------- warp-mma GEMM: 128M x 256N tile, 8 warps (64x64), occ 1 -------
// D = A @ B^T ; A [M,K''] K-major, B [N,K''] K-major. All dims exact multiples
// of the block tile -> no bounds checks. ldmatrix batched, 3-stage cp.async.
#define LDR 40   // smem row stride in bf16 (80 bytes) -> conflict-free
#define STAGES 3
#define ASTG (128*LDR)                    // A per-stage elems
#define BSTG (256*LDR)                    // B per-stage elems
#define SMEM_BYTES (STAGES*(ASTG+BSTG)*2) // 92160

__device__ __forceinline__ void store_pair_split(
    __nv_bfloat16* p, int n, float v0, float v1,
    int blk1, int blk2, int b1lo, const float* bias, int relu)
{
    if (bias) { v0 += bias[n]; v1 += bias[n + 1]; }
    if (relu) { v0 = fmaxf(v0, 0.f); v1 = fmaxf(v1, 0.f); }
    __nv_bfloat16 h0, l0, h1, l1;
    split2(v0, h0, l0); split2(v1, h1, l1);
    uint32_t H = (uint32_t)b16bits(h0) | ((uint32_t)b16bits(h1) << 16);
    uint32_t L = (uint32_t)b16bits(l0) | ((uint32_t)b16bits(l1) << 16);
    *reinterpret_cast<uint32_t*>(p + n) = H;
    *reinterpret_cast<uint32_t*>(p + blk1 + n) = b1lo ? L : H;
    *reinterpret_cast<uint32_t*>(p + blk2 + n) = b1lo ? H : L;
}

__global__ __launch_bounds__(256, 1)
void mma_gemm(const __nv_bfloat16* __restrict__ A, int lda, long long aZb, long long aZc,
              const __nv_bfloat16* __restrict__ B, int ldb, long long bZb, long long bZc,
              int nch, int zdiv, int mode,
              __nv_bfloat16* outS, int ldo, int blk1, int blk2, int b1lo,
              const float* bias, int relu,
              float* outF, int ldcM, long long cZb, long long cZc,
              const float* uArr, const float* vArr)
{
    extern __shared__ __nv_bfloat16 smem_dyn[];
    const int LDR2 = LDR*2;

    int tid = threadIdx.x;
    int z = blockIdx.z, zb = z / zdiv, zc = z - zb * zdiv;
    const __nv_bfloat16* Ab = A + (size_t)zb*aZb + (size_t)zc*aZc + (size_t)(blockIdx.y*128)*lda;
    const __nv_bfloat16* Bb = B + (size_t)zb*bZb + (size_t)zc*bZc + (size_t)(blockIdx.x*256)*ldb;
    int m0 = blockIdx.y * 128, n0 = blockIdx.x * 256;

    int lane = tid & 31, wid = tid >> 5;
    int wm = (wid & 1) * 64, wn = (wid >> 1) * 64;   // 2 x 4 warps -> 64x64 tiles
    int ar = lane >> 2, ac = (lane & 3) * 2;

    int lrow = tid >> 2, lseg = tid & 3;             // loader: 4 threads/row, 64 rows
    uint32_t sAu = smem_u32(smem_dyn);
    uint32_t sBu = sAu + STAGES*ASTG*2;
    uint32_t lso = lrow*LDR2 + lseg*16;

    uint32_t aoff = (uint32_t)(wm + (lane & 15))*LDR2 + (lane >> 4)*16;
    uint32_t boff = (uint32_t)(wn + (lane & 7))*LDR2 + (lane >> 3)*16;

    float acc[4][8][4];
    #pragma unroll
    for (int i = 0; i < 4; i++)
        #pragma unroll
        for (int j = 0; j < 8; j++)
            #pragma unroll
            for (int q = 0; q < 4; q++) acc[i][j][q] = 0.f;

    // prologue: chunks 0,1 into slots 0,1
    #pragma unroll
    for (int p = 0; p < 2; p++) {
        int k0 = p * 32;
        const __nv_bfloat16* ga = Ab + (size_t)lrow*lda + k0 + lseg*8;
        const __nv_bfloat16* gb = Bb + (size_t)lrow*ldb + k0 + lseg*8;
        uint32_t da = sAu + p*(ASTG*2), db = sBu + p*(BSTG*2);
        cp16(da + lso, ga);
        cp16(da + lso + 64*LDR2, ga + (size_t)64*lda);
        #pragma unroll
        for (int r = 0; r < 4; r++)
            cp16(db + lso + r*64*LDR2, gb + (size_t)(r*64)*ldb);
        cp_commit();
    }

    int slot = 0, lslot = 2;
    for (int c = 0; c < nch; c++) {
        if (c >= nch - 1) cp_wait0(); else cp_wait1();
        __syncthreads();

        if (c + 2 < nch) {
            int k0 = (c + 2) * 32;
            const __nv_bfloat16* ga = Ab + (size_t)lrow*lda + k0 + lseg*8;
            const __nv_bfloat16* gb = Bb + (size_t)lrow*ldb + k0 + lseg*8;
            uint32_t da = sAu + lslot*(ASTG*2), db = sBu + lslot*(BSTG*2);
            cp16(da + lso, ga);
            cp16(da + lso + 64*LDR2, ga + (size_t)64*lda);
            #pragma unroll
            for (int r = 0; r < 4; r++)
                cp16(db + lso + r*64*LDR2, gb + (size_t)(r*64)*ldb);
            cp_commit();
            lslot++; if (lslot == STAGES) lslot = 0;
        }

        uint32_t sa = sAu + slot*(ASTG*2);
        uint32_t sbb = sBu + slot*(BSTG*2);
        slot++; if (slot == STAGES) slot = 0;

        // B fragments for the whole chunk (8 n-groups x both ksteps): 8 LDSM
        uint32_t bf[8][4];
        #pragma unroll
        for (int nt = 0; nt < 8; nt++) ldm4(bf[nt], sbb + boff + nt*(8*LDR2));

        #pragma unroll
        for (int ks = 0; ks < 2; ks++) {
            uint32_t af[4][4];
            #pragma unroll
            for (int mt = 0; mt < 4; mt++)
                ldm4(af[mt], sa + aoff + mt*(16*LDR2) + ks*32);
            #pragma unroll
            for (int mt = 0; mt < 4; mt++)
                #pragma unroll
                for (int nt = 0; nt < 8; nt++)
                    mma16816(acc[mt][nt], af[mt], &bf[nt][ks*2]);
        }
    }
    __syncthreads();

    // -------- epilogue --------
    if (mode == 0) {
        __nv_bfloat16* base = outS + (size_t)zb*cZb + (size_t)zc*cZc;
        #pragma unroll
        for (int mt = 0; mt < 4; mt++) {
            int m = m0 + wm + mt*16 + ar;
            __nv_bfloat16* p0 = base + (size_t)m*ldo;
            __nv_bfloat16* p1 = p0 + (size_t)8*ldo;
            #pragma unroll
            for (int nt = 0; nt < 8; nt++) {
                int n = n0 + wn + nt*8 + ac;
                store_pair_split(p0, n, acc[mt][nt][0], acc[mt][nt][1], blk1, blk2, b1lo, bias, relu);
                store_pair_split(p1, n, acc[mt][nt][2], acc[mt][nt][3], blk1, blk2, b1lo, bias, relu);
            }
        }
    } else {
        float* base = outF + (size_t)zb*cZb + (size_t)zc*cZc;
        const float* uz = uArr + (size_t)z*512;
        const float* vz = vArr + (size_t)z*512;
        #pragma unroll
        for (int mt = 0; mt < 4; mt++) {
            int m = m0 + wm + mt*16 + ar;
            float u0 = uz[m], u1 = uz[m + 8];
            float* p0 = base + (size_t)m*ldcM;
            float* p1 = p0 + (size_t)8*ldcM;
            #pragma unroll
            for (int nt = 0; nt < 8; nt++) {
                int n = n0 + wn + nt*8 + ac;
                float vn0 = vz[n], vn1 = vz[n + 1];
                p0[(size_t)n*3]     = acc[mt][nt][0] + u0 + vn0;
                p0[(size_t)(n+1)*3] = acc[mt][nt][1] + u0 + vn1;
                p1[(size_t)n*3]     = acc[mt][nt][2] + u1 + vn0;
                p1[(size_t)(n+1)*3] = acc[mt][nt][3] + u1 + vn1;
            }
        }
    }
}

// -------------------- launcher --------------------
extern "C" void kernel_launch(void* const* d_in, const int* in_sizes, int n_in,
                              void* d_out, int out_size) {
    const float* ctx  = (const float*)d_in[0];
    const float* ques = (const float*)d_in[1];
    const float* wsim = (const float*)d_in[2];
    const float* W1s  = (const float*)d_in[3];
    const float* b1s  = (const float*)d_in[4];
    const float* W2s  = (const float*)d_in[5];
    const float* b2s  = (const float*)d_in[6];
    const float* W1e  = (const float*)d_in[7];
    const float* b1e  = (const float*)d_in[8];
    const float* W2e  = (const float*)d_in[9];
    const float* b2e  = (const float*)d_in[10];
    const float* Wb   = (const float*)d_in[11];
    float* out = (float*)d_out;

    float *q2, *rowmax, *q2c, *w01, *w10, *w11, *u, *v;
    __nv_bfloat16 *xs, *h1s, *s1s, *e1s, *Ts, *w1s, *w1e, *w2s, *w2e, *wbt;
    cudaGetSymbolAddress((void**)&q2, g_q2);
    cudaGetSymbolAddress((void**)&rowmax, g_rowmax);
    cudaGetSymbolAddress((void**)&q2c, g_q2c);
    cudaGetSymbolAddress((void**)&w01, g_w01);
    cudaGetSymbolAddress((void**)&w10, g_w10);
    cudaGetSymbolAddress((void**)&w11, g_w11);
    cudaGetSymbolAddress((void**)&u, g_u);
    cudaGetSymbolAddress((void**)&v, g_v);
    cudaGetSymbolAddress((void**)&xs, g_xs);
    cudaGetSymbolAddress((void**)&h1s, g_h1s);
    cudaGetSymbolAddress((void**)&s1s, g_s1s);
    cudaGetSymbolAddress((void**)&e1s, g_e1s);
    cudaGetSymbolAddress((void**)&Ts, g_Ts);
    cudaGetSymbolAddress((void**)&w1s, g_w1s);
    cudaGetSymbolAddress((void**)&w1e, g_w1e);
    cudaGetSymbolAddress((void**)&w2s, g_w2s);
    cudaGetSymbolAddress((void**)&w2e, g_w2e);
    cudaGetSymbolAddress((void**)&wbt, g_wbt);

    cudaFuncSetAttribute(mma_gemm, cudaFuncAttributeMaxDynamicSharedMemorySize, SMEM_BYTES);

    // front-end
    qdot_kernel<<<dim3(Bz, LQ), 32>>>(ques, wsim, q2);
    sim_softmax_c2q_kernel<<<ROWS, 256>>>(ctx, ques, wsim, q2, xs, rowmax);
    bsoftmax_q2c_kernel<<<Bz, 256>>>(ctx, rowmax, q2c);
    fillx4_kernel<<<ROWS, 256>>>(ctx, q2c, xs);
    extract_w_kernel<<<4, 256>>>(Wb, w01, w10, w11);

    // weight prep (transpose + hi/lo split, B-layout hi,hi,lo)
    prep_bsplit<<<dim3(16, 32), dim3(32, 8)>>>(W1s, 512, w1s, 1024, 1024, 512);
    prep_bsplit<<<dim3(16, 32), dim3(32, 8)>>>(W1e, 512, w1e, 1024, 1024, 512);
    prep_bsplit<<<dim3(32, 16), dim3(32, 8)>>>(W2s, 1024, w2s, 512, 512, 1024);
    prep_bsplit<<<dim3(32, 16), dim3(32, 8)>>>(W2e, 1024, w2e, 512, 512, 1024);
    for (int c = 0; c < 3; c++)
        prep_bsplit<<<dim3(32, 32), dim3(32, 8)>>>(Wb + (size_t)c*1025, 3075,
                                                   wbt + (size_t)c*1024*KS, 1024, 1024, 1024);

    long long zero = 0;
    // FFW start: h1 = relu(x@W1s + b1s)  (A-layout out: hi,lo,hi)
    mma_gemm<<<dim3(2, 64, 1), 256, SMEM_BYTES>>>(xs, KX, zero, zero, w1s, KX, zero, zero,
        96, 1, 0, h1s, KH, 512, 1024, 1, b1s, 1, nullptr, 0, zero, zero, nullptr, nullptr);
    // start = h1@W2s + b2s  (A-layout hi,lo,hi)
    mma_gemm<<<dim3(4, 64, 1), 256, SMEM_BYTES>>>(h1s, KH, zero, zero, w2s, KH, zero, zero,
        48, 1, 0, s1s, KS, 1024, 2048, 1, b2s, 0, nullptr, 0, zero, zero, nullptr, nullptr);
    // FFW end
    mma_gemm<<<dim3(2, 64, 1), 256, SMEM_BYTES>>>(xs, KX, zero, zero, w1e, KX, zero, zero,
        96, 1, 0, h1s, KH, 512, 1024, 1, b1e, 1, nullptr, 0, zero, zero, nullptr, nullptr);
    // end = h1@W2e + b2e  (B-layout hi,hi,lo)
    mma_gemm<<<dim3(4, 64, 1), 256, SMEM_BYTES>>>(h1s, KH, zero, zero, w2e, KH, zero, zero,
        48, 1, 0, e1s, KS, 1024, 2048, 0, b2e, 0, nullptr, 0, zero, zero, nullptr, nullptr);

    // rank-1 terms
    uv_kernel<<<ROWS, 256>>>(s1s, e1s, w01, w10, w11, u, v);

    // Biaffine stage 1: T[z=b*3+c] = start_b @ wbt_c^T  (A-layout out)
    mma_gemm<<<dim3(4, 4, 48), 256, SMEM_BYTES>>>(
        s1s, KS, (long long)LC*KS, zero,
        wbt, KS, zero, (long long)1024*KS,
        96, 3,
        0, Ts, KS, 1024, 2048, 1, nullptr, 0,
        nullptr, 0, (long long)3*LC*KS, (long long)LC*KS, nullptr, nullptr);

    // Biaffine stage 2: out[b,:,:,c] = T[z] @ end_b^T + u[z][x] + v[z][y]
    mma_gemm<<<dim3(2, 4, 48), 256, SMEM_BYTES>>>(
        Ts, KS, (long long)3*LC*KS, (long long)LC*KS,
        e1s, KS, (long long)LC*KS, zero,
        96, 3,
        1, nullptr, 0, 0, 0, 0, nullptr, 0,
        out, LC*3, (long long)LC*LC*3, 1ll, u, v);
}

// round 8
// speedup vs baseline: 1.1214x; 1.1214x over previous
#include <cuda_runtime.h>
#include <cuda_bf16.h>
#include <cstdint>
#include <math.h>

// Problem constants
#define Bz   16
#define LC   512
#define LQ   64
#define Hd   256
#define ROWS (Bz*LC)     // 8192

// Split-K padded strides (K'' = 3 * K), all in bf16 elements
#define KX   3072        // x'' / W1''  (K=1024)
#define KH   1536        // h1'' / W2'' (K=512)
#define KS   3072        // s1''/e1''/T''/wbt (K=1024, exact)

// -------------------- device scratch (zero-init .bss) --------------------
__device__ float g_q2[Bz*LQ];
__device__ float g_rowmax[ROWS];
__device__ float g_q2c[Bz*Hd];
__device__ float g_w01[3*1024];
__device__ float g_w10[3*1024];
__device__ float g_w11[3];
__device__ float g_u[48*512];
__device__ float g_v[48*512];
__device__ __align__(16) __nv_bfloat16 g_xs [(size_t)ROWS*KX];
__device__ __align__(16) __nv_bfloat16 g_h1 [(size_t)2*ROWS*KH];   // [start,end]
__device__ __align__(16) __nv_bfloat16 g_se [(size_t)2*ROWS*KS];   // [s1'', e1'']
__device__ __align__(16) __nv_bfloat16 g_Ts [(size_t)48*LC*KS];
__device__ __align__(16) __nv_bfloat16 g_w1 [(size_t)2*512*KX];    // [W1s'',W1e'']
__device__ __align__(16) __nv_bfloat16 g_w2 [(size_t)2*1024*KH];   // [W2s'',W2e'']
__device__ __align__(16) __nv_bfloat16 g_wbt[(size_t)3*1024*KS];

// -------------------- helpers --------------------
__device__ __forceinline__ uint32_t smem_u32(const void* p) {
    uint32_t a;
    asm("{ .reg .u64 t; cvta.to.shared.u64 t, %1; cvt.u32.u64 %0, t; }" : "=r"(a) : "l"(p));
    return a;
}
__device__ __forceinline__ void cp16(uint32_t saddr, const void* g) {
    asm volatile("cp.async.ca.shared.global [%0], [%1], 16;" :: "r"(saddr), "l"(g) : "memory");
}
__device__ __forceinline__ void cp_commit() { asm volatile("cp.async.commit_group;" ::: "memory"); }
__device__ __forceinline__ void cp_wait0()  { asm volatile("cp.async.wait_group 0;" ::: "memory"); }
__device__ __forceinline__ void cp_wait1()  { asm volatile("cp.async.wait_group 1;" ::: "memory"); }

__device__ __forceinline__ void split2(float v, __nv_bfloat16& hi, __nv_bfloat16& lo) {
    hi = __float2bfloat16(v);
    lo = __float2bfloat16(v - __bfloat162float(hi));
}
__device__ __forceinline__ unsigned short b16bits(__nv_bfloat16 h) {
    return *reinterpret_cast<unsigned short*>(&h);
}
__device__ __forceinline__ void ldm4(uint32_t* r, uint32_t saddr) {
    asm volatile("ldmatrix.sync.aligned.m8n8.x4.shared.b16 {%0,%1,%2,%3}, [%4];"
                 : "=r"(r[0]), "=r"(r[1]), "=r"(r[2]), "=r"(r[3]) : "r"(saddr));
}
__device__ __forceinline__ void mma16816(float* c, const uint32_t* a, const uint32_t* b) {
    asm volatile(
        "mma.sync.aligned.m16n8k16.row.col.f32.bf16.bf16.f32 "
        "{%0,%1,%2,%3}, {%4,%5,%6,%7}, {%8,%9}, {%0,%1,%2,%3};"
        : "+f"(c[0]), "+f"(c[1]), "+f"(c[2]), "+f"(c[3])
        : "r"(a[0]), "r"(a[1]), "r"(a[2]), "r"(a[3]), "r"(b[0]), "r"(b[1]));
}

// -------------------- attention front-end --------------------
__device__ __forceinline__ void xsplit_store(__nv_bfloat16* xr, int col, float v) {
    __nv_bfloat16 hi, lo; split2(v, hi, lo);
    xr[col] = hi; xr[col + 1024] = lo; xr[col + 2048] = hi;   // A-layout: hi, lo, hi
}

__global__ void qdot_kernel(const float* __restrict__ ques, const float* __restrict__ wsim,
                            float* __restrict__ q2) {
    int b = blockIdx.x, j = blockIdx.y, l = threadIdx.x;
    const float* q = ques + ((size_t)(b*LQ + j))*Hd;
    float s = 0.f;
    #pragma unroll
    for (int u = 0; u < Hd/32; u++) s += q[l + u*32] * wsim[Hd + l + u*32];
    #pragma unroll
    for (int o = 16; o > 0; o >>= 1) s += __shfl_down_sync(0xffffffffu, s, o);
    if (l == 0) q2[b*LQ + j] = s;
}

__global__ void sim_softmax_c2q_kernel(const float* __restrict__ ctx,
                                       const float* __restrict__ ques,
                                       const float* __restrict__ wsim,
                                       const float* __restrict__ q2,
                                       __nv_bfloat16* __restrict__ xs,
                                       float* __restrict__ rowmax) {
    int row = blockIdx.x, b = row >> 9;
    int t = threadIdx.x, w = t >> 5, l = t & 31;
    __shared__ float ctxs[Hd], cw3[Hd], simv[LQ], sred[8];
    __shared__ float c1s;

    const float* crow = ctx + (size_t)row * Hd;
    float cv = crow[t];
    ctxs[t] = cv;
    cw3[t]  = cv * wsim[2*Hd + t];

    float v = cv * wsim[t];
    #pragma unroll
    for (int o = 16; o > 0; o >>= 1) v += __shfl_down_sync(0xffffffffu, v, o);
    if (l == 0) sred[w] = v;
    __syncthreads();
    if (t == 0) { float s = 0.f; for (int u = 0; u < 8; u++) s += sred[u]; c1s = s; }
    __syncthreads();

    const float* qb = ques + (size_t)b * LQ * Hd;
    #pragma unroll
    for (int jj = 0; jj < 8; jj++) {
        int j = w * 8 + jj;
        const float* q = qb + (size_t)j * Hd;
        float s = 0.f;
        #pragma unroll
        for (int u = 0; u < Hd/32; u++) s += cw3[l + u*32] * q[l + u*32];
        #pragma unroll
        for (int o = 16; o > 0; o >>= 1) s += __shfl_down_sync(0xffffffffu, s, o);
        if (l == 0) simv[j] = c1s + q2[b*LQ + j] + s;
    }
    __syncthreads();

    if (t < 32) {
        float s0 = simv[t], s1v = simv[t + 32];
        float m = fmaxf(s0, s1v);
        #pragma unroll
        for (int o = 16; o > 0; o >>= 1) m = fmaxf(m, __shfl_xor_sync(0xffffffffu, m, o));
        if (t == 0) rowmax[row] = m;
        float e0 = expf(s0 - m), e1v = expf(s1v - m);
        float sum = e0 + e1v;
        #pragma unroll
        for (int o = 16; o > 0; o >>= 1) sum += __shfl_xor_sync(0xffffffffu, sum, o);
        float inv = 1.f / sum;
        simv[t] = e0 * inv; simv[t + 32] = e1v * inv;
    }
    __syncthreads();

    float acc = 0.f;
    #pragma unroll 8
    for (int j = 0; j < LQ; j++) acc += simv[j] * qb[(size_t)j*Hd + t];

    __nv_bfloat16* xr = xs + (size_t)row * KX;
    xsplit_store(xr, t,        ctxs[t]);
    xsplit_store(xr, Hd + t,   acc);
    xsplit_store(xr, 2*Hd + t, ctxs[t] * acc);
}

__global__ void bsoftmax_q2c_kernel(const float* __restrict__ ctx,
                                    const float* __restrict__ rowmax,
                                    float* __restrict__ q2c) {
    int b = blockIdx.x, t = threadIdx.x;
    __shared__ float w[LC]; __shared__ float sred[8]; __shared__ float mshared, sshared;
    w[t] = rowmax[b*LC + t]; w[t + 256] = rowmax[b*LC + t + 256];
    __syncthreads();
    float m = fmaxf(w[t], w[t + 256]);
    #pragma unroll
    for (int o = 16; o > 0; o >>= 1) m = fmaxf(m, __shfl_xor_sync(0xffffffffu, m, o));
    if ((t & 31) == 0) sred[t >> 5] = m;
    __syncthreads();
    if (t == 0) { float mm = sred[0]; for (int u = 1; u < 8; u++) mm = fmaxf(mm, sred[u]); mshared = mm; }
    __syncthreads();
    m = mshared;
    float e0 = expf(w[t] - m), e1v = expf(w[t + 256] - m);
    float s = e0 + e1v;
    #pragma unroll
    for (int o = 16; o > 0; o >>= 1) s += __shfl_xor_sync(0xffffffffu, s, o);
    if ((t & 31) == 0) sred[t >> 5] = s;
    __syncthreads();
    if (t == 0) { float ss = 0.f; for (int u = 0; u < 8; u++) ss += sred[u]; sshared = ss; }
    __syncthreads();
    float inv = 1.f / sshared;
    w[t] = e0 * inv; w[t + 256] = e1v * inv;
    __syncthreads();
    float acc = 0.f;
    const float* cb = ctx + (size_t)b * LC * Hd;
    for (int i = 0; i < LC; i++) acc += w[i] * cb[(size_t)i*Hd + t];
    q2c[b*Hd + t] = acc;
}

__global__ void fillx4_kernel(const float* __restrict__ ctx,
                              const float* __restrict__ q2c,
                              __nv_bfloat16* __restrict__ xs) {
    int row = blockIdx.x, t = threadIdx.x, b = row >> 9;
    float c = ctx[(size_t)row*Hd + t];
    xsplit_store(xs + (size_t)row*KX, 3*Hd + t, c * q2c[b*Hd + t]);
}

// extract rank-1 parts of Wb: w01[c][i]=Wb[i,c,1024], w10[c][j]=Wb[1024,c,j], w11[c]
__global__ void extract_w_kernel(const float* __restrict__ Wb,
                                 float* __restrict__ w01, float* __restrict__ w10,
                                 float* __restrict__ w11) {
    int i = blockIdx.x*256 + threadIdx.x;   // 0..1023
    #pragma unroll
    for (int c = 0; c < 3; c++) {
        w01[c*1024 + i] = Wb[(size_t)i*3075 + c*1025 + 1024];
        w10[c*1024 + i] = Wb[(size_t)1024*3075 + c*1025 + i];
    }
    if (i < 3) w11[i] = Wb[(size_t)1024*3075 + (size_t)i*1025 + 1024];
}

// u[z=b*3+c][x] = start[b,x]·w01[c] + w11[c] ; v[z][y] = end[b,y]·w10[c]
__global__ void uv_kernel(const __nv_bfloat16* __restrict__ s1s,
                          const __nv_bfloat16* __restrict__ e1s,
                          const float* __restrict__ w01, const float* __restrict__ w10,
                          const float* __restrict__ w11,
                          float* __restrict__ u, float* __restrict__ v) {
    int row = blockIdx.x, t = threadIdx.x, w = t >> 5, l = t & 31;
    int b = row >> 9, x = row & 511;
    const __nv_bfloat16* sr = s1s + (size_t)row*KS;
    const __nv_bfloat16* er = e1s + (size_t)row*KS;
    float a[6] = {0,0,0,0,0,0};
    for (int i = t; i < 1024; i += 256) {
        float sv = __bfloat162float(sr[i]) + __bfloat162float(sr[i + 1024]);  // A-layout: hi,lo,hi
        float ev = __bfloat162float(er[i]) + __bfloat162float(er[i + 2048]);  // B-layout: hi,hi,lo
        #pragma unroll
        for (int c = 0; c < 3; c++) {
            a[c]     += sv * w01[c*1024 + i];
            a[3 + c] += ev * w10[c*1024 + i];
        }
    }
    __shared__ float red[6][8];
    #pragma unroll
    for (int q = 0; q < 6; q++) {
        float s = a[q];
        #pragma unroll
        for (int o = 16; o > 0; o >>= 1) s += __shfl_down_sync(0xffffffffu, s, o);
        if (l == 0) red[q][w] = s;
    }
    __syncthreads();
    if (t < 6) {
        float s = 0.f;
        #pragma unroll
        for (int k = 0; k < 8; k++) s += red[t][k];
        if (t < 3) u[(b*3 + t)*512 + x] = s + w11[t];
        else       v[(b*3 + (t - 3))*512 + x] = s;
    }
}

// Transpose + split weights into B-layout [N rows x 3*Kpad]: blocks (hi, hi, lo)
// z-batched: up to 3 sources, dst stride dstZ per z.
__global__ void prep_bsplit3(const float* __restrict__ a0, const float* __restrict__ a1,
                             const float* __restrict__ a2, int srcLd,
                             __nv_bfloat16* __restrict__ dst, size_t dstZ,
                             int Kreal, int Kpad, int Nrows) {
    const float* src = (blockIdx.z == 0) ? a0 : ((blockIdx.z == 1) ? a1 : a2);
    dst += blockIdx.z * dstZ;
    __shared__ float tile[32][33];
    int k0 = blockIdx.y*32, n0 = blockIdx.x*32;
    int tx = threadIdx.x, ty = threadIdx.y;
    #pragma unroll
    for (int i = 0; i < 32; i += 8) {
        int k = k0 + ty + i, n = n0 + tx;
        tile[ty + i][tx] = (k < Kreal && n < Nrows) ? src[(size_t)k*srcLd + n] : 0.f;
    }
    __syncthreads();
    int ldd = 3*Kpad;
    #pragma unroll
    for (int i = 0; i < 32; i += 8) {
        int n = n0 + ty + i, k = k0 + tx;
        if (n < Nrows) {
            __nv_bfloat16 hi, lo; split2(tile[tx][ty + i], hi, lo);
            size_t base = (size_t)n*ldd + k;
            dst[base] = hi; dst[base + Kpad] = hi; dst[base + 2*Kpad] = lo;
        }
    }
}

// -------------------- warp-mma GEMM (round-6 engine, z-batched epilogues) ----
// D = A @ B^T ; 128x128x32 block tile, 8 warps, 64x32 warp tile, occ 2,
// batched ldmatrix, 3-stage cp.async ring.
#define LDR 40   // smem row stride in bf16 (80 bytes) -> conflict-free
#define STAGES 3
#define STG_ELEMS (128*LDR)               // per-stage elems per matrix
#define SMEM_BYTES (STAGES*2*STG_ELEMS*2) // 61440

__device__ __forceinline__ void store_pair_split(
    __nv_bfloat16* p, int n, float v0, float v1,
    int blk1, int blk2, int b1lo, const float* bias, int relu)
{
    if (bias) { v0 += bias[n]; v1 += bias[n + 1]; }
    if (relu) { v0 = fmaxf(v0, 0.f); v1 = fmaxf(v1, 0.f); }
    __nv_bfloat16 h0, l0, h1, l1;
    split2(v0, h0, l0); split2(v1, h1, l1);
    uint32_t H = (uint32_t)b16bits(h0) | ((uint32_t)b16bits(h1) << 16);
    uint32_t L = (uint32_t)b16bits(l0) | ((uint32_t)b16bits(l1) << 16);
    *reinterpret_cast<uint32_t*>(p + n) = H;
    *reinterpret_cast<uint32_t*>(p + blk1 + n) = b1lo ? L : H;
    *reinterpret_cast<uint32_t*>(p + blk2 + n) = b1lo ? H : L;
}

__global__ __launch_bounds__(256, 2)
void mma_gemm(const __nv_bfloat16* __restrict__ A, int lda, long long aZb, long long aZc,
              const __nv_bfloat16* __restrict__ B, int ldb, long long bZb, long long bZc,
              int nch, int zdiv, int mode,
              __nv_bfloat16* outS, int ldo, int blk1, int blk2, int b1loMode,
              const float* bias, const float* bias2, int relu,
              float* outF, int ldcM, long long cZb, long long cZc,
              const float* uArr, const float* vArr)
{
    extern __shared__ __nv_bfloat16 smem_dyn[];
    const int LDR2 = LDR*2;

    int tid = threadIdx.x;
    int z = blockIdx.z, zb = z / zdiv, zc = z - zb * zdiv;
    const __nv_bfloat16* Ab = A + (size_t)zb*aZb + (size_t)zc*aZc + (size_t)(blockIdx.y*128)*lda;
    const __nv_bfloat16* Bb = B + (size_t)zb*bZb + (size_t)zc*bZc + (size_t)(blockIdx.x*128)*ldb;
    int m0 = blockIdx.y * 128, n0 = blockIdx.x * 128;

    int lane = tid & 31, wid = tid >> 5;
    int wm = (wid & 1) * 64, wn = (wid >> 1) * 32;
    int ar = lane >> 2, ac = (lane & 3) * 2;

    int lrow = tid >> 2, lseg = tid & 3;               // loader: 4 threads/row
    uint32_t sAu = smem_u32(smem_dyn);
    uint32_t sBu = sAu + STAGES*STG_ELEMS*2;
    uint32_t lso = lrow*LDR2 + lseg*16;

    uint32_t aoff = (uint32_t)(wm + (lane & 15))*LDR2 + (lane >> 4)*16;
    uint32_t boff = (uint32_t)(wn + (lane & 7))*LDR2 + (lane >> 3)*16;

    float acc[4][4][4];
    #pragma unroll
    for (int i = 0; i < 4; i++)
        #pragma unroll
        for (int j = 0; j < 4; j++)
            #pragma unroll
            for (int q = 0; q < 4; q++) acc[i][j][q] = 0.f;

    // prologue: chunks 0,1 into slots 0,1
    #pragma unroll
    for (int p = 0; p < 2; p++) {
        int k0 = p * 32;
        const __nv_bfloat16* ga = Ab + (size_t)lrow*lda + k0 + lseg*8;
        const __nv_bfloat16* gb = Bb + (size_t)lrow*ldb + k0 + lseg*8;
        uint32_t da = sAu + p*(STG_ELEMS*2), db = sBu + p*(STG_ELEMS*2);
        cp16(da + lso, ga);            cp16(db + lso, gb);
        cp16(da + lso + 64*LDR2, ga + (size_t)64*lda);
        cp16(db + lso + 64*LDR2, gb + (size_t)64*ldb);
        cp_commit();
    }

    int slot = 0, lslot = 2;
    for (int c = 0; c < nch; c++) {
        if (c >= nch - 1) cp_wait0(); else cp_wait1();
        __syncthreads();

        if (c + 2 < nch) {
            int k0 = (c + 2) * 32;
            const __nv_bfloat16* ga = Ab + (size_t)lrow*lda + k0 + lseg*8;
            const __nv_bfloat16* gb = Bb + (size_t)lrow*ldb + k0 + lseg*8;
            uint32_t da = sAu + lslot*(STG_ELEMS*2), db = sBu + lslot*(STG_ELEMS*2);
            cp16(da + lso, ga);            cp16(db + lso, gb);
            cp16(da + lso + 64*LDR2, ga + (size_t)64*lda);
            cp16(db + lso + 64*LDR2, gb + (size_t)64*ldb);
            cp_commit();
            lslot++; if (lslot == STAGES) lslot = 0;
        }

        uint32_t sa = sAu + slot*(STG_ELEMS*2);
        uint32_t sbb = sBu + slot*(STG_ELEMS*2);
        slot++; if (slot == STAGES) slot = 0;

        uint32_t bf[4][4];
        #pragma unroll
        for (int nt = 0; nt < 4; nt++) ldm4(bf[nt], sbb + boff + nt*(8*LDR2));

        #pragma unroll
        for (int ks = 0; ks < 2; ks++) {
            uint32_t af[4][4];
            #pragma unroll
            for (int mt = 0; mt < 4; mt++)
                ldm4(af[mt], sa + aoff + mt*(16*LDR2) + ks*32);
            #pragma unroll
            for (int mt = 0; mt < 4; mt++)
                #pragma unroll
                for (int nt = 0; nt < 4; nt++)
                    mma16816(acc[mt][nt], af[mt], &bf[nt][ks*2]);
        }
    }
    __syncthreads();

    // -------- epilogue --------
    if (mode == 0) {
        int b1lo = (b1loMode == 2) ? (zc == 0 ? 1 : 0) : b1loMode;
        const float* bs = (zc == 1 && bias2) ? bias2 : bias;
        __nv_bfloat16* base = outS + (size_t)zb*cZb + (size_t)zc*cZc;
        #pragma unroll
        for (int mt = 0; mt < 4; mt++) {
            int m = m0 + wm + mt*16 + ar;
            __nv_bfloat16* p0 = base + (size_t)m*ldo;
            __nv_bfloat16* p1 = p0 + (size_t)8*ldo;
            #pragma unroll
            for (int nt = 0; nt < 4; nt++) {
                int n = n0 + wn + nt*8 + ac;
                store_pair_split(p0, n, acc[mt][nt][0], acc[mt][nt][1], blk1, blk2, b1lo, bs, relu);
                store_pair_split(p1, n, acc[mt][nt][2], acc[mt][nt][3], blk1, blk2, b1lo, bs, relu);
            }
        }
    } else {
        float* base = outF + (size_t)zb*cZb + (size_t)zc*cZc;
        const float* uz = uArr + (size_t)z*512;
        const float* vz = vArr + (size_t)z*512;
        #pragma unroll
        for (int mt = 0; mt < 4; mt++) {
            int m = m0 + wm + mt*16 + ar;
            float u0 = uz[m], u1 = uz[m + 8];
            float* p0 = base + (size_t)m*ldcM;
            float* p1 = p0 + (size_t)8*ldcM;
            #pragma unroll
            for (int nt = 0; nt < 4; nt++) {
                int n = n0 + wn + nt*8 + ac;
                float vn0 = vz[n], vn1 = vz[n + 1];
                p0[(size_t)n*3]     = acc[mt][nt][0] + u0 + vn0;
                p0[(size_t)(n+1)*3] = acc[mt][nt][1] + u0 + vn1;
                p1[(size_t)n*3]     = acc[mt][nt][2] + u1 + vn0;
                p1[(size_t)(n+1)*3] = acc[mt][nt][3] + u1 + vn1;
            }
        }
    }
}

// -------------------- launcher --------------------
extern "C" void kernel_launch(void* const* d_in, const int* in_sizes, int n_in,
                              void* d_out, int out_size) {
    const float* ctx  = (const float*)d_in[0];
    const float* ques = (const float*)d_in[1];
    const float* wsim = (const float*)d_in[2];
    const float* W1s  = (const float*)d_in[3];
    const float* b1s  = (const float*)d_in[4];
    const float* W2s  = (const float*)d_in[5];
    const float* b2s  = (const float*)d_in[6];
    const float* W1e  = (const float*)d_in[7];
    const float* b1e  = (const float*)d_in[8];
    const float* W2e  = (const float*)d_in[9];
    const float* b2e  = (const float*)d_in[10];
    const float* Wb   = (const float*)d_in[11];
    float* out = (float*)d_out;

    float *q2, *rowmax, *q2c, *w01, *w10, *w11, *u, *v;
    __nv_bfloat16 *xs, *h1, *se, *Ts, *w1, *w2, *wbt;
    cudaGetSymbolAddress((void**)&q2, g_q2);
    cudaGetSymbolAddress((void**)&rowmax, g_rowmax);
    cudaGetSymbolAddress((void**)&q2c, g_q2c);
    cudaGetSymbolAddress((void**)&w01, g_w01);
    cudaGetSymbolAddress((void**)&w10, g_w10);
    cudaGetSymbolAddress((void**)&w11, g_w11);
    cudaGetSymbolAddress((void**)&u, g_u);
    cudaGetSymbolAddress((void**)&v, g_v);
    cudaGetSymbolAddress((void**)&xs, g_xs);
    cudaGetSymbolAddress((void**)&h1, g_h1);
    cudaGetSymbolAddress((void**)&se, g_se);
    cudaGetSymbolAddress((void**)&Ts, g_Ts);
    cudaGetSymbolAddress((void**)&w1, g_w1);
    cudaGetSymbolAddress((void**)&w2, g_w2);
    cudaGetSymbolAddress((void**)&wbt, g_wbt);

    cudaFuncSetAttribute(mma_gemm, cudaFuncAttributeMaxDynamicSharedMemorySize, SMEM_BYTES);

    // front-end + weight prep (3 z-batched prep launches)
    qdot_kernel<<<dim3(Bz, LQ), 32>>>(ques, wsim, q2);
    extract_w_kernel<<<4, 256>>>(Wb, w01, w10, w11);
    prep_bsplit3<<<dim3(16, 32, 2), dim3(32, 8)>>>(W1s, W1e, W1e, 512,
        w1, (size_t)512*KX, 1024, 1024, 512);
    prep_bsplit3<<<dim3(32, 16, 2), dim3(32, 8)>>>(W2s, W2e, W2e, 1024,
        w2, (size_t)1024*KH, 512, 512, 1024);
    prep_bsplit3<<<dim3(32, 32, 3), dim3(32, 8)>>>(Wb, Wb + 1025, Wb + 2050, 3075,
        wbt, (size_t)1024*KS, 1024, 1024, 1024);
    sim_softmax_c2q_kernel<<<ROWS, 256>>>(ctx, ques, wsim, q2, xs, rowmax);
    bsoftmax_q2c_kernel<<<Bz, 256>>>(ctx, rowmax, q2c);
    fillx4_kernel<<<ROWS, 256>>>(ctx, q2c, xs);

    long long zero = 0;
    // FFW1 (start+end batched over z): h1[z] = relu(x@W1[z] + b1[z]) (A-layout)
    mma_gemm<<<dim3(4, 64, 2), 256, SMEM_BYTES>>>(
        xs, KX, zero, zero,
        w1, KX, zero, (long long)512*KX,
        96, 2, 0, h1, KH, 512, 1024, 1, b1s, b1e, 1,
        nullptr, 0, zero, (long long)ROWS*KH, nullptr, nullptr);
    // FFW2 (batched): se[z] = h1[z]@W2[z] + b2[z]; z=0 A-layout (s), z=1 B-layout (e)
    mma_gemm<<<dim3(8, 64, 2), 256, SMEM_BYTES>>>(
        h1, KH, zero, (long long)ROWS*KH,
        w2, KH, zero, (long long)1024*KH,
        48, 2, 0, se, KS, 1024, 2048, 2 /* b1lo = (zc==0) */, b2s, b2e, 0,
        nullptr, 0, zero, (long long)ROWS*KS, nullptr, nullptr);

    // rank-1 terms
    uv_kernel<<<ROWS, 256>>>(se, se + (size_t)ROWS*KS, w01, w10, w11, u, v);

    // Biaffine stage 1: T[z=b*3+c] = start_b @ wbt_c^T  (A-layout out)
    mma_gemm<<<dim3(8, 4, 48), 256, SMEM_BYTES>>>(
        se, KS, (long long)LC*KS, zero,
        wbt, KS, zero, (long long)1024*KS,
        96, 3,
        0, Ts, KS, 1024, 2048, 1, nullptr, nullptr, 0,
        nullptr, 0, (long long)3*LC*KS, (long long)LC*KS, nullptr, nullptr);

    // Biaffine stage 2: out[b,:,:,c] = T[z] @ end_b^T + u[z][x] + v[z][y]
    mma_gemm<<<dim3(4, 4, 48), 256, SMEM_BYTES>>>(
        Ts, KS, (long long)3*LC*KS, (long long)LC*KS,
        se + (size_t)ROWS*KS, KS, (long long)LC*KS, zero,
        96, 3,
        1, nullptr, 0, 0, 0, 0, nullptr, nullptr, 0,
        out, LC*3, (long long)LC*LC*3, 1ll, u, v);
}

// round 10
// speedup vs baseline: 1.3899x; 1.2395x over previous
#include <cuda_runtime.h>
#include <cuda_bf16.h>
#include <cuda_fp16.h>
#include <cstdint>
#include <math.h>

// Problem constants
#define Bz   16
#define LC   512
#define LQ   64
#define Hd   256
#define ROWS (Bz*LC)     // 8192

// bf16 split-K strides (K'' = 3K) for the FFW chain
#define KX   3072        // x'' / W1''  (K=1024)
#define KH   1536        // h1'' / W2'' (K=512)
// fp16 2-term strides for the biaffine chain
#define KF   2048        // s''/T''   ([hi | lo], K=1024)
#define KB   1024        // wbt / e   (single fp16 block, K-wrapped)

// -------------------- device scratch (zero-init .bss) --------------------
__device__ float g_q2[Bz*LQ];
__device__ float g_rowmax[ROWS];
__device__ float g_q2c[Bz*Hd];
__device__ float g_w01[3*1024];
__device__ float g_w10[3*1024];
__device__ float g_w11[3];
__device__ float g_u[48*512];
__device__ float g_v[48*512];
__device__ __align__(16) __nv_bfloat16 g_xs [(size_t)ROWS*KX];
__device__ __align__(16) __nv_bfloat16 g_h1 [(size_t)2*ROWS*KH];   // [start,end]
__device__ __align__(16) __nv_bfloat16 g_w1 [(size_t)2*512*KX];    // [W1s'',W1e'']
__device__ __align__(16) __nv_bfloat16 g_w2 [(size_t)2*1024*KH];   // [W2s'',W2e'']
// ONE contiguous buffer: s fp16 [hi,lo] at offset 0 (ROWS*KF), e fp16 hi at offset ROWS*KF
__device__ __align__(16) __half        g_sef[(size_t)ROWS*KF + (size_t)ROWS*KB];
__device__ __align__(16) __half        g_Tf [(size_t)48*LC*KF];    // T fp16 [hi,lo]
__device__ __align__(16) __half        g_wbtf[(size_t)3*1024*KB];  // Wb^T fp16 hi

// -------------------- helpers --------------------
__device__ __forceinline__ uint32_t smem_u32(const void* p) {
    uint32_t a;
    asm("{ .reg .u64 t; cvta.to.shared.u64 t, %1; cvt.u32.u64 %0, t; }" : "=r"(a) : "l"(p));
    return a;
}
__device__ __forceinline__ void cp16(uint32_t saddr, const void* g) {
    asm volatile("cp.async.ca.shared.global [%0], [%1], 16;" :: "r"(saddr), "l"(g) : "memory");
}
__device__ __forceinline__ void cp_commit() { asm volatile("cp.async.commit_group;" ::: "memory"); }
__device__ __forceinline__ void cp_wait0()  { asm volatile("cp.async.wait_group 0;" ::: "memory"); }
__device__ __forceinline__ void cp_wait1()  { asm volatile("cp.async.wait_group 1;" ::: "memory"); }

__device__ __forceinline__ void split2(float v, __nv_bfloat16& hi, __nv_bfloat16& lo) {
    hi = __float2bfloat16(v);
    lo = __float2bfloat16(v - __bfloat162float(hi));
}
__device__ __forceinline__ unsigned short b16bits(__nv_bfloat16 h) {
    return *reinterpret_cast<unsigned short*>(&h);
}
__device__ __forceinline__ unsigned short h16bits(__half h) {
    return *reinterpret_cast<unsigned short*>(&h);
}
__device__ __forceinline__ void ldm4(uint32_t* r, uint32_t saddr) {
    asm volatile("ldmatrix.sync.aligned.m8n8.x4.shared.b16 {%0,%1,%2,%3}, [%4];"
                 : "=r"(r[0]), "=r"(r[1]), "=r"(r[2]), "=r"(r[3]) : "r"(saddr));
}
__device__ __forceinline__ void mma16816_bf(float* c, const uint32_t* a, const uint32_t* b) {
    asm volatile(
        "mma.sync.aligned.m16n8k16.row.col.f32.bf16.bf16.f32 "
        "{%0,%1,%2,%3}, {%4,%5,%6,%7}, {%8,%9}, {%0,%1,%2,%3};"
        : "+f"(c[0]), "+f"(c[1]), "+f"(c[2]), "+f"(c[3])
        : "r"(a[0]), "r"(a[1]), "r"(a[2]), "r"(a[3]), "r"(b[0]), "r"(b[1]));
}
__device__ __forceinline__ void mma16816_f16(float* c, const uint32_t* a, const uint32_t* b) {
    asm volatile(
        "mma.sync.aligned.m16n8k16.row.col.f32.f16.f16.f32 "
        "{%0,%1,%2,%3}, {%4,%5,%6,%7}, {%8,%9}, {%0,%1,%2,%3};"
        : "+f"(c[0]), "+f"(c[1]), "+f"(c[2]), "+f"(c[3])
        : "r"(a[0]), "r"(a[1]), "r"(a[2]), "r"(a[3]), "r"(b[0]), "r"(b[1]));
}

// -------------------- attention front-end --------------------
__device__ __forceinline__ void xsplit_store(__nv_bfloat16* xr, int col, float v) {
    __nv_bfloat16 hi, lo; split2(v, hi, lo);
    xr[col] = hi; xr[col + 1024] = lo; xr[col + 2048] = hi;   // A-layout: hi, lo, hi
}

__global__ void qdot_kernel(const float* __restrict__ ques, const float* __restrict__ wsim,
                            float* __restrict__ q2) {
    int b = blockIdx.x, j = blockIdx.y, l = threadIdx.x;
    const float* q = ques + ((size_t)(b*LQ + j))*Hd;
    float s = 0.f;
    #pragma unroll
    for (int u = 0; u < Hd/32; u++) s += q[l + u*32] * wsim[Hd + l + u*32];
    #pragma unroll
    for (int o = 16; o > 0; o >>= 1) s += __shfl_down_sync(0xffffffffu, s, o);
    if (l == 0) q2[b*LQ + j] = s;
}

__global__ void sim_softmax_c2q_kernel(const float* __restrict__ ctx,
                                       const float* __restrict__ ques,
                                       const float* __restrict__ wsim,
                                       const float* __restrict__ q2,
                                       __nv_bfloat16* __restrict__ xs,
                                       float* __restrict__ rowmax) {
    int row = blockIdx.x, b = row >> 9;
    int t = threadIdx.x, w = t >> 5, l = t & 31;
    __shared__ float ctxs[Hd], cw3[Hd], simv[LQ], sred[8];
    __shared__ float c1s;

    const float* crow = ctx + (size_t)row * Hd;
    float cv = crow[t];
    ctxs[t] = cv;
    cw3[t]  = cv * wsim[2*Hd + t];

    float v = cv * wsim[t];
    #pragma unroll
    for (int o = 16; o > 0; o >>= 1) v += __shfl_down_sync(0xffffffffu, v, o);
    if (l == 0) sred[w] = v;
    __syncthreads();
    if (t == 0) { float s = 0.f; for (int u = 0; u < 8; u++) s += sred[u]; c1s = s; }
    __syncthreads();

    const float* qb = ques + (size_t)b * LQ * Hd;
    #pragma unroll
    for (int jj = 0; jj < 8; jj++) {
        int j = w * 8 + jj;
        const float* q = qb + (size_t)j * Hd;
        float s = 0.f;
        #pragma unroll
        for (int u = 0; u < Hd/32; u++) s += cw3[l + u*32] * q[l + u*32];
        #pragma unroll
        for (int o = 16; o > 0; o >>= 1) s += __shfl_down_sync(0xffffffffu, s, o);
        if (l == 0) simv[j] = c1s + q2[b*LQ + j] + s;
    }
    __syncthreads();

    if (t < 32) {
        float s0 = simv[t], s1v = simv[t + 32];
        float m = fmaxf(s0, s1v);
        #pragma unroll
        for (int o = 16; o > 0; o >>= 1) m = fmaxf(m, __shfl_xor_sync(0xffffffffu, m, o));
        if (t == 0) rowmax[row] = m;
        float e0 = expf(s0 - m), e1v = expf(s1v - m);
        float sum = e0 + e1v;
        #pragma unroll
        for (int o = 16; o > 0; o >>= 1) sum += __shfl_xor_sync(0xffffffffu, sum, o);
        float inv = 1.f / sum;
        simv[t] = e0 * inv; simv[t + 32] = e1v * inv;
    }
    __syncthreads();

    float acc = 0.f;
    #pragma unroll 8
    for (int j = 0; j < LQ; j++) acc += simv[j] * qb[(size_t)j*Hd + t];

    __nv_bfloat16* xr = xs + (size_t)row * KX;
    xsplit_store(xr, t,        ctxs[t]);
    xsplit_store(xr, Hd + t,   acc);
    xsplit_store(xr, 2*Hd + t, ctxs[t] * acc);
}

__global__ void bsoftmax_q2c_kernel(const float* __restrict__ ctx,
                                    const float* __restrict__ rowmax,
                                    float* __restrict__ q2c) {
    int b = blockIdx.x, t = threadIdx.x;
    __shared__ float w[LC]; __shared__ float sred[8]; __shared__ float mshared, sshared;
    w[t] = rowmax[b*LC + t]; w[t + 256] = rowmax[b*LC + t + 256];
    __syncthreads();
    float m = fmaxf(w[t], w[t + 256]);
    #pragma unroll
    for (int o = 16; o > 0; o >>= 1) m = fmaxf(m, __shfl_xor_sync(0xffffffffu, m, o));
    if ((t & 31) == 0) sred[t >> 5] = m;
    __syncthreads();
    if (t == 0) { float mm = sred[0]; for (int u = 1; u < 8; u++) mm = fmaxf(mm, sred[u]); mshared = mm; }
    __syncthreads();
    m = mshared;
    float e0 = expf(w[t] - m), e1v = expf(w[t + 256] - m);
    float s = e0 + e1v;
    #pragma unroll
    for (int o = 16; o > 0; o >>= 1) s += __shfl_xor_sync(0xffffffffu, s, o);
    if ((t & 31) == 0) sred[t >> 5] = s;
    __syncthreads();
    if (t == 0) { float ss = 0.f; for (int u = 0; u < 8; u++) ss += sred[u]; sshared = ss; }
    __syncthreads();
    float inv = 1.f / sshared;
    w[t] = e0 * inv; w[t + 256] = e1v * inv;
    __syncthreads();
    float acc = 0.f;
    const float* cb = ctx + (size_t)b * LC * Hd;
    for (int i = 0; i < LC; i++) acc += w[i] * cb[(size_t)i*Hd + t];
    q2c[b*Hd + t] = acc;
}

__global__ void fillx4_kernel(const float* __restrict__ ctx,
                              const float* __restrict__ q2c,
                              __nv_bfloat16* __restrict__ xs) {
    int row = blockIdx.x, t = threadIdx.x, b = row >> 9;
    float c = ctx[(size_t)row*Hd + t];
    xsplit_store(xs + (size_t)row*KX, 3*Hd + t, c * q2c[b*Hd + t]);
}

// extract rank-1 parts of Wb: w01[c][i]=Wb[i,c,1024], w10[c][j]=Wb[1024,c,j], w11[c]
__global__ void extract_w_kernel(const float* __restrict__ Wb,
                                 float* __restrict__ w01, float* __restrict__ w10,
                                 float* __restrict__ w11) {
    int i = blockIdx.x*256 + threadIdx.x;   // 0..1023
    #pragma unroll
    for (int c = 0; c < 3; c++) {
        w01[c*1024 + i] = Wb[(size_t)i*3075 + c*1025 + 1024];
        w10[c*1024 + i] = Wb[(size_t)1024*3075 + c*1025 + i];
    }
    if (i < 3) w11[i] = Wb[(size_t)1024*3075 + (size_t)i*1025 + 1024];
}

// u[z=b*3+c][x] = start[b,x]·w01[c] + w11[c] ; v[z][y] = end[b,y]·w10[c]
__global__ void uv_kernel(const __half* __restrict__ sf,
                          const __half* __restrict__ ef,
                          const float* __restrict__ w01, const float* __restrict__ w10,
                          const float* __restrict__ w11,
                          float* __restrict__ u, float* __restrict__ v) {
    int row = blockIdx.x, t = threadIdx.x, w = t >> 5, l = t & 31;
    int b = row >> 9, x = row & 511;
    const __half* sr = sf + (size_t)row*KF;
    const __half* er = ef + (size_t)row*KB;
    float a[6] = {0,0,0,0,0,0};
    for (int i = t; i < 1024; i += 256) {
        float sv = __half2float(sr[i]) + __half2float(sr[i + 1024]);
        float ev = __half2float(er[i]);
        #pragma unroll
        for (int c = 0; c < 3; c++) {
            a[c]     += sv * w01[c*1024 + i];
            a[3 + c] += ev * w10[c*1024 + i];
        }
    }
    __shared__ float red[6][8];
    #pragma unroll
    for (int q = 0; q < 6; q++) {
        float s = a[q];
        #pragma unroll
        for (int o = 16; o > 0; o >>= 1) s += __shfl_down_sync(0xffffffffu, s, o);
        if (l == 0) red[q][w] = s;
    }
    __syncthreads();
    if (t < 6) {
        float s = 0.f;
        #pragma unroll
        for (int k = 0; k < 8; k++) s += red[t][k];
        if (t < 3) u[(b*3 + t)*512 + x] = s + w11[t];
        else       v[(b*3 + (t - 3))*512 + x] = s;
    }
}

// Transpose weights; outMode 0 = bf16 [hi,hi,lo] B-layout (ldd 3*Kpad);
//                    outMode 1 = fp16 hi single block (ldd Kpad)
__global__ void prep_bsplit3(const float* __restrict__ a0, const float* __restrict__ a1,
                             const float* __restrict__ a2, int srcLd,
                             void* __restrict__ dstv, size_t dstZ,
                             int Kreal, int Kpad, int Nrows, int outMode) {
    const float* src = (blockIdx.z == 0) ? a0 : ((blockIdx.z == 1) ? a1 : a2);
    __shared__ float tile[32][33];
    int k0 = blockIdx.y*32, n0 = blockIdx.x*32;
    int tx = threadIdx.x, ty = threadIdx.y;
    #pragma unroll
    for (int i = 0; i < 32; i += 8) {
        int k = k0 + ty + i, n = n0 + tx;
        tile[ty + i][tx] = (k < Kreal && n < Nrows) ? src[(size_t)k*srcLd + n] : 0.f;
    }
    __syncthreads();
    if (outMode == 0) {
        __nv_bfloat16* dst = (__nv_bfloat16*)dstv + blockIdx.z * dstZ;
        int ldd = 3*Kpad;
        #pragma unroll
        for (int i = 0; i < 32; i += 8) {
            int n = n0 + ty + i, k = k0 + tx;
            if (n < Nrows) {
                __nv_bfloat16 hi, lo; split2(tile[tx][ty + i], hi, lo);
                size_t base = (size_t)n*ldd + k;
                dst[base] = hi; dst[base + Kpad] = hi; dst[base + 2*Kpad] = lo;
            }
        }
    } else {
        __half* dst = (__half*)dstv + blockIdx.z * dstZ;
        #pragma unroll
        for (int i = 0; i < 32; i += 8) {
            int n = n0 + ty + i, k = k0 + tx;
            if (n < Nrows)
                dst[(size_t)n*Kpad + k] = __float2half_rn(tile[tx][ty + i]);
        }
    }
}

// -------------------- warp-mma GEMM (templated dtype) --------------------
// D = A @ B^T ; 128x128x32 tile, 8 warps, 64x32 warp tile, occ 2,
// batched ldmatrix, 3-stage cp.async ring. B column index wrapped by bKmask.
#define LDR 40   // smem row stride in bf16 (80 bytes) -> conflict-free
#define STAGES 3
#define STG_ELEMS (128*LDR)
#define SMEM_BYTES (STAGES*2*STG_ELEMS*2) // 61440

__device__ __forceinline__ void store_pair_split(
    __nv_bfloat16* p, int n, float v0, float v1,
    int blk1, int blk2, int b1lo, const float* bias, int relu)
{
    if (bias) { v0 += bias[n]; v1 += bias[n + 1]; }
    if (relu) { v0 = fmaxf(v0, 0.f); v1 = fmaxf(v1, 0.f); }
    __nv_bfloat16 h0, l0, h1, l1;
    split2(v0, h0, l0); split2(v1, h1, l1);
    uint32_t H = (uint32_t)b16bits(h0) | ((uint32_t)b16bits(h1) << 16);
    uint32_t L = (uint32_t)b16bits(l0) | ((uint32_t)b16bits(l1) << 16);
    *reinterpret_cast<uint32_t*>(p + n) = H;
    *reinterpret_cast<uint32_t*>(p + blk1 + n) = b1lo ? L : H;
    *reinterpret_cast<uint32_t*>(p + blk2 + n) = b1lo ? H : L;
}

__device__ __forceinline__ void f16_hilo_pair(__half* p, int n, float v0, float v1) {
    __half h0 = __float2half_rn(v0); __half l0 = __float2half_rn(v0 - __half2float(h0));
    __half h1 = __float2half_rn(v1); __half l1 = __float2half_rn(v1 - __half2float(h1));
    uint32_t H = (uint32_t)h16bits(h0) | ((uint32_t)h16bits(h1) << 16);
    uint32_t L = (uint32_t)h16bits(l0) | ((uint32_t)h16bits(l1) << 16);
    *reinterpret_cast<uint32_t*>(p + n) = H;
    *reinterpret_cast<uint32_t*>(p + 1024 + n) = L;
}
__device__ __forceinline__ void f16_hi_pair(__half* p, int n, float v0, float v1) {
    __half h0 = __float2half_rn(v0);
    __half h1 = __float2half_rn(v1);
    *reinterpret_cast<uint32_t*>(p + n) =
        (uint32_t)h16bits(h0) | ((uint32_t)h16bits(h1) << 16);
}

template<int F16>
__global__ __launch_bounds__(256, 2)
void mma_gemm(const __nv_bfloat16* __restrict__ A, int lda, long long aZb, long long aZc,
              const __nv_bfloat16* __restrict__ B, int ldb, long long bZb, long long bZc,
              int bKmask, int nch, int zdiv, int mode,
              void* outS, int ldo, int blk1, int blk2, int b1loMode,
              const float* bias, const float* bias2, int relu,
              float* outF, int ldcM, long long cZb, long long cZc,
              const float* uArr, const float* vArr)
{
    extern __shared__ __nv_bfloat16 smem_dyn[];
    const int LDR2 = LDR*2;

    int tid = threadIdx.x;
    int z = blockIdx.z, zb = z / zdiv, zc = z - zb * zdiv;
    const __nv_bfloat16* Ab = A + (size_t)zb*aZb + (size_t)zc*aZc + (size_t)(blockIdx.y*128)*lda;
    const __nv_bfloat16* Bb = B + (size_t)zb*bZb + (size_t)zc*bZc + (size_t)(blockIdx.x*128)*ldb;
    int m0 = blockIdx.y * 128, n0 = blockIdx.x * 128;

    int lane = tid & 31, wid = tid >> 5;
    int wm = (wid & 1) * 64, wn = (wid >> 1) * 32;
    int ar = lane >> 2, ac = (lane & 3) * 2;

    int lrow = tid >> 2, lseg = tid & 3;               // loader: 4 threads/row
    uint32_t sAu = smem_u32(smem_dyn);
    uint32_t sBu = sAu + STAGES*STG_ELEMS*2;
    uint32_t lso = lrow*LDR2 + lseg*16;

    uint32_t aoff = (uint32_t)(wm + (lane & 15))*LDR2 + (lane >> 4)*16;
    uint32_t boff = (uint32_t)(wn + (lane & 7))*LDR2 + (lane >> 3)*16;

    float acc[4][4][4];
    #pragma unroll
    for (int i = 0; i < 4; i++)
        #pragma unroll
        for (int j = 0; j < 4; j++)
            #pragma unroll
            for (int q = 0; q < 4; q++) acc[i][j][q] = 0.f;

    // prologue: chunks 0,1 into slots 0,1
    #pragma unroll
    for (int p = 0; p < 2; p++) {
        int k0 = p * 32;
        int bk0 = k0 & bKmask;
        const __nv_bfloat16* ga = Ab + (size_t)lrow*lda + k0 + lseg*8;
        const __nv_bfloat16* gb = Bb + (size_t)lrow*ldb + bk0 + lseg*8;
        uint32_t da = sAu + p*(STG_ELEMS*2), db = sBu + p*(STG_ELEMS*2);
        cp16(da + lso, ga);            cp16(db + lso, gb);
        cp16(da + lso + 64*LDR2, ga + (size_t)64*lda);
        cp16(db + lso + 64*LDR2, gb + (size_t)64*ldb);
        cp_commit();
    }

    int slot = 0, lslot = 2;
    for (int c = 0; c < nch; c++) {
        if (c >= nch - 1) cp_wait0(); else cp_wait1();
        __syncthreads();

        if (c + 2 < nch) {
            int k0 = (c + 2) * 32;
            int bk0 = k0 & bKmask;
            const __nv_bfloat16* ga = Ab + (size_t)lrow*lda + k0 + lseg*8;
            const __nv_bfloat16* gb = Bb + (size_t)lrow*ldb + bk0 + lseg*8;
            uint32_t da = sAu + lslot*(STG_ELEMS*2), db = sBu + lslot*(STG_ELEMS*2);
            cp16(da + lso, ga);            cp16(db + lso, gb);
            cp16(da + lso + 64*LDR2, ga + (size_t)64*lda);
            cp16(db + lso + 64*LDR2, gb + (size_t)64*ldb);
            cp_commit();
            lslot++; if (lslot == STAGES) lslot = 0;
        }

        uint32_t sa = sAu + slot*(STG_ELEMS*2);
        uint32_t sbb = sBu + slot*(STG_ELEMS*2);
        slot++; if (slot == STAGES) slot = 0;

        uint32_t bf[4][4];
        #pragma unroll
        for (int nt = 0; nt < 4; nt++) ldm4(bf[nt], sbb + boff + nt*(8*LDR2));

        #pragma unroll
        for (int ks = 0; ks < 2; ks++) {
            uint32_t af[4][4];
            #pragma unroll
            for (int mt = 0; mt < 4; mt++)
                ldm4(af[mt], sa + aoff + mt*(16*LDR2) + ks*32);
            #pragma unroll
            for (int mt = 0; mt < 4; mt++)
                #pragma unroll
                for (int nt = 0; nt < 4; nt++) {
                    if (F16) mma16816_f16(acc[mt][nt], af[mt], &bf[nt][ks*2]);
                    else     mma16816_bf (acc[mt][nt], af[mt], &bf[nt][ks*2]);
                }
        }
    }
    __syncthreads();

    // -------- epilogue --------
    if (mode == 0) {
        int b1lo = b1loMode;
        const float* bs = (zc == 1 && bias2) ? bias2 : bias;
        __nv_bfloat16* base = (__nv_bfloat16*)outS + (size_t)zb*cZb + (size_t)zc*cZc;
        #pragma unroll
        for (int mt = 0; mt < 4; mt++) {
            int m = m0 + wm + mt*16 + ar;
            __nv_bfloat16* p0 = base + (size_t)m*ldo;
            __nv_bfloat16* p1 = p0 + (size_t)8*ldo;
            #pragma unroll
            for (int nt = 0; nt < 4; nt++) {
                int n = n0 + wn + nt*8 + ac;
                store_pair_split(p0, n, acc[mt][nt][0], acc[mt][nt][1], blk1, blk2, b1lo, bs, relu);
                store_pair_split(p1, n, acc[mt][nt][2], acc[mt][nt][3], blk1, blk2, b1lo, bs, relu);
            }
        }
    } else if (mode == 2) {
        // FFW2: zc==0 -> s fp16 [hi,lo] ld KF at outS; zc==1 -> e fp16 hi ld KB at outS+cZc
        const float* bs = (zc == 1) ? bias2 : bias;
        #pragma unroll
        for (int mt = 0; mt < 4; mt++) {
            int m = m0 + wm + mt*16 + ar;
            __half* p0;
            int ld = (zc == 0) ? KF : KB;
            if (zc == 0) p0 = (__half*)outS + (size_t)m*KF;
            else         p0 = (__half*)outS + (size_t)cZc + (size_t)m*KB;
            __half* p1 = p0 + (size_t)8*ld;
            #pragma unroll
            for (int nt = 0; nt < 4; nt++) {
                int n = n0 + wn + nt*8 + ac;
                float v0 = acc[mt][nt][0] + bs[n], v1 = acc[mt][nt][1] + bs[n+1];
                float v2 = acc[mt][nt][2] + bs[n], v3 = acc[mt][nt][3] + bs[n+1];
                if (zc == 0) { f16_hilo_pair(p0, n, v0, v1); f16_hilo_pair(p1, n, v2, v3); }
                else         { f16_hi_pair(p0, n, v0, v1);   f16_hi_pair(p1, n, v2, v3); }
            }
        }
    } else if (mode == 3) {
        // stage1: T fp16 [hi,lo], ld KF
        __half* base = (__half*)outS + (size_t)zb*cZb + (size_t)zc*cZc;
        #pragma unroll
        for (int mt = 0; mt < 4; mt++) {
            int m = m0 + wm + mt*16 + ar;
            __half* p0 = base + (size_t)m*KF;
            __half* p1 = p0 + (size_t)8*KF;
            #pragma unroll
            for (int nt = 0; nt < 4; nt++) {
                int n = n0 + wn + nt*8 + ac;
                f16_hilo_pair(p0, n, acc[mt][nt][0], acc[mt][nt][1]);
                f16_hilo_pair(p1, n, acc[mt][nt][2], acc[mt][nt][3]);
            }
        }
    } else {
        float* base = outF + (size_t)zb*cZb + (size_t)zc*cZc;
        const float* uz = uArr + (size_t)z*512;
        const float* vz = vArr + (size_t)z*512;
        #pragma unroll
        for (int mt = 0; mt < 4; mt++) {
            int m = m0 + wm + mt*16 + ar;
            float u0 = uz[m], u1 = uz[m + 8];
            float* p0 = base + (size_t)m*ldcM;
            float* p1 = p0 + (size_t)8*ldcM;
            #pragma unroll
            for (int nt = 0; nt < 4; nt++) {
                int n = n0 + wn + nt*8 + ac;
                float vn0 = vz[n], vn1 = vz[n + 1];
                p0[(size_t)n*3]     = acc[mt][nt][0] + u0 + vn0;
                p0[(size_t)(n+1)*3] = acc[mt][nt][1] + u0 + vn1;
                p1[(size_t)n*3]     = acc[mt][nt][2] + u1 + vn0;
                p1[(size_t)(n+1)*3] = acc[mt][nt][3] + u1 + vn1;
            }
        }
    }
}

// -------------------- launcher --------------------
extern "C" void kernel_launch(void* const* d_in, const int* in_sizes, int n_in,
                              void* d_out, int out_size) {
    const float* ctx  = (const float*)d_in[0];
    const float* ques = (const float*)d_in[1];
    const float* wsim = (const float*)d_in[2];
    const float* W1s  = (const float*)d_in[3];
    const float* b1s  = (const float*)d_in[4];
    const float* W2s  = (const float*)d_in[5];
    const float* b2s  = (const float*)d_in[6];
    const float* W1e  = (const float*)d_in[7];
    const float* b1e  = (const float*)d_in[8];
    const float* W2e  = (const float*)d_in[9];
    const float* b2e  = (const float*)d_in[10];
    const float* Wb   = (const float*)d_in[11];
    float* out = (float*)d_out;

    float *q2, *rowmax, *q2c, *w01, *w10, *w11, *u, *v;
    __nv_bfloat16 *xs, *h1, *w1, *w2;
    __half *sef, *Tf, *wbtf;
    cudaGetSymbolAddress((void**)&q2, g_q2);
    cudaGetSymbolAddress((void**)&rowmax, g_rowmax);
    cudaGetSymbolAddress((void**)&q2c, g_q2c);
    cudaGetSymbolAddress((void**)&w01, g_w01);
    cudaGetSymbolAddress((void**)&w10, g_w10);
    cudaGetSymbolAddress((void**)&w11, g_w11);
    cudaGetSymbolAddress((void**)&u, g_u);
    cudaGetSymbolAddress((void**)&v, g_v);
    cudaGetSymbolAddress((void**)&xs, g_xs);
    cudaGetSymbolAddress((void**)&h1, g_h1);
    cudaGetSymbolAddress((void**)&w1, g_w1);
    cudaGetSymbolAddress((void**)&w2, g_w2);
    cudaGetSymbolAddress((void**)&sef, g_sef);
    cudaGetSymbolAddress((void**)&Tf, g_Tf);
    cudaGetSymbolAddress((void**)&wbtf, g_wbtf);

    __half* sf = sef;                               // s fp16 [hi,lo], ld KF
    __half* ef = sef + (size_t)ROWS*KF;             // e fp16 hi, ld KB

    cudaFuncSetAttribute(mma_gemm<0>, cudaFuncAttributeMaxDynamicSharedMemorySize, SMEM_BYTES);
    cudaFuncSetAttribute(mma_gemm<1>, cudaFuncAttributeMaxDynamicSharedMemorySize, SMEM_BYTES);

    // front-end + weight prep
    qdot_kernel<<<dim3(Bz, LQ), 32>>>(ques, wsim, q2);
    extract_w_kernel<<<4, 256>>>(Wb, w01, w10, w11);
    prep_bsplit3<<<dim3(16, 32, 2), dim3(32, 8)>>>(W1s, W1e, W1e, 512,
        w1, (size_t)512*KX, 1024, 1024, 512, 0);
    prep_bsplit3<<<dim3(32, 16, 2), dim3(32, 8)>>>(W2s, W2e, W2e, 1024,
        w2, (size_t)1024*KH, 512, 512, 1024, 0);
    prep_bsplit3<<<dim3(32, 32, 3), dim3(32, 8)>>>(Wb, Wb + 1025, Wb + 2050, 3075,
        wbtf, (size_t)1024*KB, 1024, 1024, 1024, 1);
    sim_softmax_c2q_kernel<<<ROWS, 256>>>(ctx, ques, wsim, q2, xs, rowmax);
    bsoftmax_q2c_kernel<<<Bz, 256>>>(ctx, rowmax, q2c);
    fillx4_kernel<<<ROWS, 256>>>(ctx, q2c, xs);

    long long zero = 0;
    const int NOMASK = 0x7fffffff;
    // FFW1 (bf16 3-term, start+end batched): h1[z] = relu(x@W1[z]+b1[z]), A-layout
    mma_gemm<0><<<dim3(4, 64, 2), 256, SMEM_BYTES>>>(
        xs, KX, zero, zero,
        w1, KX, zero, (long long)512*KX, NOMASK,
        96, 2, 0, h1, KH, 512, 1024, 1, b1s, b1e, 1,
        nullptr, 0, zero, (long long)ROWS*KH, nullptr, nullptr);
    // FFW2 (bf16, batched): z=0 -> s fp16 [hi,lo] at sef; z=1 -> e fp16 hi at sef+ROWS*KF
    mma_gemm<0><<<dim3(8, 64, 2), 256, SMEM_BYTES>>>(
        h1, KH, zero, (long long)ROWS*KH,
        w2, KH, zero, (long long)1024*KH, NOMASK,
        48, 2, 2, sef, 0, 0, 0, 0, b2s, b2e, 0,
        nullptr, 0, zero, (long long)ROWS*KF /* e offset in half elems */,
        nullptr, nullptr);

    // rank-1 terms (reads s and e from the SAME contiguous buffer)
    uv_kernel<<<ROWS, 256>>>(sf, ef, w01, w10, w11, u, v);

    // Biaffine stage 1 (fp16 2-term): T[z=b*3+c] = s_b @ wbt_c^T, out fp16 [hi,lo]
    mma_gemm<1><<<dim3(8, 4, 48), 256, SMEM_BYTES>>>(
        (const __nv_bfloat16*)sf, KF, (long long)LC*KF, zero,
        (const __nv_bfloat16*)wbtf, KB, zero, (long long)1024*KB, 1023,
        64, 3, 3, Tf, 0, 0, 0, 0, nullptr, nullptr, 0,
        nullptr, 0, (long long)3*LC*KF, (long long)LC*KF, nullptr, nullptr);

    // Biaffine stage 2 (fp16 2-term): out[b,:,:,c] = T[z] @ e_b^T + u + v
    mma_gemm<1><<<dim3(4, 4, 48), 256, SMEM_BYTES>>>(
        (const __nv_bfloat16*)Tf, KF, (long long)3*LC*KF, (long long)LC*KF,
        (const __nv_bfloat16*)ef, KB, (long long)LC*KB, zero, 1023,
        64, 3, 1, nullptr, 0, 0, 0, 0, nullptr, nullptr, 0,
        out, LC*3, (long long)LC*LC*3, 1ll, u, v);
}

// round 11
// speedup vs baseline: 1.5486x; 1.1142x over previous
#include <cuda_runtime.h>
#include <cuda_bf16.h>
#include <cuda_fp16.h>
#include <cstdint>
#include <math.h>

// Problem constants
#define Bz   16
#define LC   512
#define LQ   64
#define Hd   256
#define ROWS (Bz*LC)     // 8192

// fp16 2-term strides (elements)
#define KXF  2048        // x   [hi|lo], K=1024
#define KW1  1024        // W1^T fp16 hi, K-wrapped
#define KHF  1024        // h1  [hi|lo], K=512
#define KW2  512         // W2^T fp16 hi, K-wrapped
#define KF   2048        // s/T [hi|lo], K=1024
#define KB   1024        // wbt/e fp16 hi, K-wrapped

// -------------------- device scratch (zero-init .bss) --------------------
__device__ float g_q2[Bz*LQ];
__device__ float g_rowmax[ROWS];
__device__ float g_q2c[Bz*Hd];
__device__ float g_w01[3*1024];
__device__ float g_w10[3*1024];
__device__ float g_w11[3];
__device__ float g_u[48*512];
__device__ float g_v[48*512];
__device__ __align__(16) __half g_xs [(size_t)ROWS*KXF];
__device__ __align__(16) __half g_h1 [(size_t)2*ROWS*KHF];            // [start,end]
__device__ __align__(16) __half g_w1 [(size_t)2*512*KW1];             // [W1s,W1e]^T
__device__ __align__(16) __half g_w2 [(size_t)2*1024*KW2];            // [W2s,W2e]^T
__device__ __align__(16) __half g_sef[(size_t)ROWS*KF + (size_t)ROWS*KB]; // s then e
__device__ __align__(16) __half g_Tf [(size_t)48*LC*KF];              // T [hi|lo]
__device__ __align__(16) __half g_wbtf[(size_t)3*1024*KB];            // Wb^T fp16 hi

// -------------------- helpers --------------------
__device__ __forceinline__ uint32_t smem_u32(const void* p) {
    uint32_t a;
    asm("{ .reg .u64 t; cvta.to.shared.u64 t, %1; cvt.u32.u64 %0, t; }" : "=r"(a) : "l"(p));
    return a;
}
__device__ __forceinline__ void cp16(uint32_t saddr, const void* g) {
    asm volatile("cp.async.ca.shared.global [%0], [%1], 16;" :: "r"(saddr), "l"(g) : "memory");
}
__device__ __forceinline__ void cp_commit() { asm volatile("cp.async.commit_group;" ::: "memory"); }
__device__ __forceinline__ void cp_wait0()  { asm volatile("cp.async.wait_group 0;" ::: "memory"); }
__device__ __forceinline__ void cp_wait1()  { asm volatile("cp.async.wait_group 1;" ::: "memory"); }

__device__ __forceinline__ unsigned short h16bits(__half h) {
    return *reinterpret_cast<unsigned short*>(&h);
}
__device__ __forceinline__ void ldm4(uint32_t* r, uint32_t saddr) {
    asm volatile("ldmatrix.sync.aligned.m8n8.x4.shared.b16 {%0,%1,%2,%3}, [%4];"
                 : "=r"(r[0]), "=r"(r[1]), "=r"(r[2]), "=r"(r[3]) : "r"(saddr));
}
__device__ __forceinline__ void mma16816_f16(float* c, const uint32_t* a, const uint32_t* b) {
    asm volatile(
        "mma.sync.aligned.m16n8k16.row.col.f32.f16.f16.f32 "
        "{%0,%1,%2,%3}, {%4,%5,%6,%7}, {%8,%9}, {%0,%1,%2,%3};"
        : "+f"(c[0]), "+f"(c[1]), "+f"(c[2]), "+f"(c[3])
        : "r"(a[0]), "r"(a[1]), "r"(a[2]), "r"(a[3]), "r"(b[0]), "r"(b[1]));
}

// -------------------- attention front-end --------------------
// x fp16 hi/lo: hi at col, lo at col+1024 (ld KXF)
__device__ __forceinline__ void xsplit_store(__half* xr, int col, float v) {
    __half hi = __float2half_rn(v);
    __half lo = __float2half_rn(v - __half2float(hi));
    xr[col] = hi; xr[col + 1024] = lo;
}

__global__ void qdot_kernel(const float* __restrict__ ques, const float* __restrict__ wsim,
                            float* __restrict__ q2) {
    int b = blockIdx.x, j = blockIdx.y, l = threadIdx.x;
    const float* q = ques + ((size_t)(b*LQ + j))*Hd;
    float s = 0.f;
    #pragma unroll
    for (int u = 0; u < Hd/32; u++) s += q[l + u*32] * wsim[Hd + l + u*32];
    #pragma unroll
    for (int o = 16; o > 0; o >>= 1) s += __shfl_down_sync(0xffffffffu, s, o);
    if (l == 0) q2[b*LQ + j] = s;
}

__global__ void sim_softmax_c2q_kernel(const float* __restrict__ ctx,
                                       const float* __restrict__ ques,
                                       const float* __restrict__ wsim,
                                       const float* __restrict__ q2,
                                       __half* __restrict__ xs,
                                       float* __restrict__ rowmax) {
    int row = blockIdx.x, b = row >> 9;
    int t = threadIdx.x, w = t >> 5, l = t & 31;
    __shared__ float ctxs[Hd], cw3[Hd], simv[LQ], sred[8];
    __shared__ float c1s;

    const float* crow = ctx + (size_t)row * Hd;
    float cv = crow[t];
    ctxs[t] = cv;
    cw3[t]  = cv * wsim[2*Hd + t];

    float v = cv * wsim[t];
    #pragma unroll
    for (int o = 16; o > 0; o >>= 1) v += __shfl_down_sync(0xffffffffu, v, o);
    if (l == 0) sred[w] = v;
    __syncthreads();
    if (t == 0) { float s = 0.f; for (int u = 0; u < 8; u++) s += sred[u]; c1s = s; }
    __syncthreads();

    const float* qb = ques + (size_t)b * LQ * Hd;
    #pragma unroll
    for (int jj = 0; jj < 8; jj++) {
        int j = w * 8 + jj;
        const float* q = qb + (size_t)j * Hd;
        float s = 0.f;
        #pragma unroll
        for (int u = 0; u < Hd/32; u++) s += cw3[l + u*32] * q[l + u*32];
        #pragma unroll
        for (int o = 16; o > 0; o >>= 1) s += __shfl_down_sync(0xffffffffu, s, o);
        if (l == 0) simv[j] = c1s + q2[b*LQ + j] + s;
    }
    __syncthreads();

    if (t < 32) {
        float s0 = simv[t], s1v = simv[t + 32];
        float m = fmaxf(s0, s1v);
        #pragma unroll
        for (int o = 16; o > 0; o >>= 1) m = fmaxf(m, __shfl_xor_sync(0xffffffffu, m, o));
        if (t == 0) rowmax[row] = m;
        float e0 = expf(s0 - m), e1v = expf(s1v - m);
        float sum = e0 + e1v;
        #pragma unroll
        for (int o = 16; o > 0; o >>= 1) sum += __shfl_xor_sync(0xffffffffu, sum, o);
        float inv = 1.f / sum;
        simv[t] = e0 * inv; simv[t + 32] = e1v * inv;
    }
    __syncthreads();

    float acc = 0.f;
    #pragma unroll 8
    for (int j = 0; j < LQ; j++) acc += simv[j] * qb[(size_t)j*Hd + t];

    __half* xr = xs + (size_t)row * KXF;
    xsplit_store(xr, t,        ctxs[t]);
    xsplit_store(xr, Hd + t,   acc);
    xsplit_store(xr, 2*Hd + t, ctxs[t] * acc);
}

__global__ void bsoftmax_q2c_kernel(const float* __restrict__ ctx,
                                    const float* __restrict__ rowmax,
                                    float* __restrict__ q2c) {
    int b = blockIdx.x, t = threadIdx.x;
    __shared__ float w[LC]; __shared__ float sred[8]; __shared__ float mshared, sshared;
    w[t] = rowmax[b*LC + t]; w[t + 256] = rowmax[b*LC + t + 256];
    __syncthreads();
    float m = fmaxf(w[t], w[t + 256]);
    #pragma unroll
    for (int o = 16; o > 0; o >>= 1) m = fmaxf(m, __shfl_xor_sync(0xffffffffu, m, o));
    if ((t & 31) == 0) sred[t >> 5] = m;
    __syncthreads();
    if (t == 0) { float mm = sred[0]; for (int u = 1; u < 8; u++) mm = fmaxf(mm, sred[u]); mshared = mm; }
    __syncthreads();
    m = mshared;
    float e0 = expf(w[t] - m), e1v = expf(w[t + 256] - m);
    float s = e0 + e1v;
    #pragma unroll
    for (int o = 16; o > 0; o >>= 1) s += __shfl_xor_sync(0xffffffffu, s, o);
    if ((t & 31) == 0) sred[t >> 5] = s;
    __syncthreads();
    if (t == 0) { float ss = 0.f; for (int u = 0; u < 8; u++) ss += sred[u]; sshared = ss; }
    __syncthreads();
    float inv = 1.f / sshared;
    w[t] = e0 * inv; w[t + 256] = e1v * inv;
    __syncthreads();
    float acc = 0.f;
    const float* cb = ctx + (size_t)b * LC * Hd;
    for (int i = 0; i < LC; i++) acc += w[i] * cb[(size_t)i*Hd + t];
    q2c[b*Hd + t] = acc;
}

__global__ void fillx4_kernel(const float* __restrict__ ctx,
                              const float* __restrict__ q2c,
                              __half* __restrict__ xs) {
    int row = blockIdx.x, t = threadIdx.x, b = row >> 9;
    float c = ctx[(size_t)row*Hd + t];
    xsplit_store(xs + (size_t)row*KXF, 3*Hd + t, c * q2c[b*Hd + t]);
}

// extract rank-1 parts of Wb
__global__ void extract_w_kernel(const float* __restrict__ Wb,
                                 float* __restrict__ w01, float* __restrict__ w10,
                                 float* __restrict__ w11) {
    int i = blockIdx.x*256 + threadIdx.x;   // 0..1023
    #pragma unroll
    for (int c = 0; c < 3; c++) {
        w01[c*1024 + i] = Wb[(size_t)i*3075 + c*1025 + 1024];
        w10[c*1024 + i] = Wb[(size_t)1024*3075 + c*1025 + i];
    }
    if (i < 3) w11[i] = Wb[(size_t)1024*3075 + (size_t)i*1025 + 1024];
}

// u[z=b*3+c][x] = start[b,x]·w01[c] + w11[c] ; v[z][y] = end[b,y]·w10[c]
__global__ void uv_kernel(const __half* __restrict__ sf,
                          const __half* __restrict__ ef,
                          const float* __restrict__ w01, const float* __restrict__ w10,
                          const float* __restrict__ w11,
                          float* __restrict__ u, float* __restrict__ v) {
    int row = blockIdx.x, t = threadIdx.x, w = t >> 5, l = t & 31;
    int b = row >> 9, x = row & 511;
    const __half* sr = sf + (size_t)row*KF;
    const __half* er = ef + (size_t)row*KB;
    float a[6] = {0,0,0,0,0,0};
    for (int i = t; i < 1024; i += 256) {
        float sv = __half2float(sr[i]) + __half2float(sr[i + 1024]);
        float ev = __half2float(er[i]);
        #pragma unroll
        for (int c = 0; c < 3; c++) {
            a[c]     += sv * w01[c*1024 + i];
            a[3 + c] += ev * w10[c*1024 + i];
        }
    }
    __shared__ float red[6][8];
    #pragma unroll
    for (int q = 0; q < 6; q++) {
        float s = a[q];
        #pragma unroll
        for (int o = 16; o > 0; o >>= 1) s += __shfl_down_sync(0xffffffffu, s, o);
        if (l == 0) red[q][w] = s;
    }
    __syncthreads();
    if (t < 6) {
        float s = 0.f;
        #pragma unroll
        for (int k = 0; k < 8; k++) s += red[t][k];
        if (t < 3) u[(b*3 + t)*512 + x] = s + w11[t];
        else       v[(b*3 + (t - 3))*512 + x] = s;
    }
}

// Transpose weights -> fp16 hi single block [Nrows x Kpad]
__global__ void prep_wT(const float* __restrict__ a0, const float* __restrict__ a1,
                        const float* __restrict__ a2, int srcLd,
                        __half* __restrict__ dst, size_t dstZ,
                        int Kreal, int Kpad, int Nrows) {
    const float* src = (blockIdx.z == 0) ? a0 : ((blockIdx.z == 1) ? a1 : a2);
    __half* d = dst + blockIdx.z * dstZ;
    __shared__ float tile[32][33];
    int k0 = blockIdx.y*32, n0 = blockIdx.x*32;
    int tx = threadIdx.x, ty = threadIdx.y;
    #pragma unroll
    for (int i = 0; i < 32; i += 8) {
        int k = k0 + ty + i, n = n0 + tx;
        tile[ty + i][tx] = (k < Kreal && n < Nrows) ? src[(size_t)k*srcLd + n] : 0.f;
    }
    __syncthreads();
    #pragma unroll
    for (int i = 0; i < 32; i += 8) {
        int n = n0 + ty + i, k = k0 + tx;
        if (n < Nrows)
            d[(size_t)n*Kpad + k] = __float2half_rn(tile[tx][ty + i]);
    }
}

// -------------------- fp16 warp-mma GEMM --------------------
// D = A @ B^T ; 128x128x32 tile, 8 warps, 64x32 warp tile, occ 2,
// batched ldmatrix, 3-stage cp.async ring. B K-index wrapped by bKmask.
#define LDR 40
#define STAGES 3
#define STG_ELEMS (128*LDR)
#define SMEM_BYTES (STAGES*2*STG_ELEMS*2) // 61440

__device__ __forceinline__ void f16_hilo_pair(__half* p, int n, int loOff, float v0, float v1) {
    __half h0 = __float2half_rn(v0); __half l0 = __float2half_rn(v0 - __half2float(h0));
    __half h1 = __float2half_rn(v1); __half l1 = __float2half_rn(v1 - __half2float(h1));
    uint32_t H = (uint32_t)h16bits(h0) | ((uint32_t)h16bits(h1) << 16);
    uint32_t L = (uint32_t)h16bits(l0) | ((uint32_t)h16bits(l1) << 16);
    *reinterpret_cast<uint32_t*>(p + n) = H;
    *reinterpret_cast<uint32_t*>(p + loOff + n) = L;
}
__device__ __forceinline__ void f16_hi_pair(__half* p, int n, float v0, float v1) {
    __half h0 = __float2half_rn(v0);
    __half h1 = __float2half_rn(v1);
    *reinterpret_cast<uint32_t*>(p + n) =
        (uint32_t)h16bits(h0) | ((uint32_t)h16bits(h1) << 16);
}

__global__ __launch_bounds__(256, 2)
void mma_gemm(const __half* __restrict__ A, int lda, long long aZb, long long aZc,
              const __half* __restrict__ B, int ldb, long long bZb, long long bZc,
              int bKmask, int nch, int zdiv, int mode,
              __half* outS, int ldo, int loOff,
              const float* bias, const float* bias2, int relu,
              float* outF, int ldcM, long long cZb, long long cZc,
              const float* uArr, const float* vArr)
{
    extern __shared__ __half smem_dyn[];
    const int LDR2 = LDR*2;

    int tid = threadIdx.x;
    int z = blockIdx.z, zb = z / zdiv, zc = z - zb * zdiv;
    const __half* Ab = A + (size_t)zb*aZb + (size_t)zc*aZc + (size_t)(blockIdx.y*128)*lda;
    const __half* Bb = B + (size_t)zb*bZb + (size_t)zc*bZc + (size_t)(blockIdx.x*128)*ldb;
    int m0 = blockIdx.y * 128, n0 = blockIdx.x * 128;

    int lane = tid & 31, wid = tid >> 5;
    int wm = (wid & 1) * 64, wn = (wid >> 1) * 32;
    int ar = lane >> 2, ac = (lane & 3) * 2;

    int lrow = tid >> 2, lseg = tid & 3;
    uint32_t sAu = smem_u32(smem_dyn);
    uint32_t sBu = sAu + STAGES*STG_ELEMS*2;
    uint32_t lso = lrow*LDR2 + lseg*16;

    uint32_t aoff = (uint32_t)(wm + (lane & 15))*LDR2 + (lane >> 4)*16;
    uint32_t boff = (uint32_t)(wn + (lane & 7))*LDR2 + (lane >> 3)*16;

    float acc[4][4][4];
    #pragma unroll
    for (int i = 0; i < 4; i++)
        #pragma unroll
        for (int j = 0; j < 4; j++)
            #pragma unroll
            for (int q = 0; q < 4; q++) acc[i][j][q] = 0.f;

    #pragma unroll
    for (int p = 0; p < 2; p++) {
        int k0 = p * 32;
        int bk0 = k0 & bKmask;
        const __half* ga = Ab + (size_t)lrow*lda + k0 + lseg*8;
        const __half* gb = Bb + (size_t)lrow*ldb + bk0 + lseg*8;
        uint32_t da = sAu + p*(STG_ELEMS*2), db = sBu + p*(STG_ELEMS*2);
        cp16(da + lso, ga);            cp16(db + lso, gb);
        cp16(da + lso + 64*LDR2, ga + (size_t)64*lda);
        cp16(db + lso + 64*LDR2, gb + (size_t)64*ldb);
        cp_commit();
    }

    int slot = 0, lslot = 2;
    for (int c = 0; c < nch; c++) {
        if (c >= nch - 1) cp_wait0(); else cp_wait1();
        __syncthreads();

        if (c + 2 < nch) {
            int k0 = (c + 2) * 32;
            int bk0 = k0 & bKmask;
            const __half* ga = Ab + (size_t)lrow*lda + k0 + lseg*8;
            const __half* gb = Bb + (size_t)lrow*ldb + bk0 + lseg*8;
            uint32_t da = sAu + lslot*(STG_ELEMS*2), db = sBu + lslot*(STG_ELEMS*2);
            cp16(da + lso, ga);            cp16(db + lso, gb);
            cp16(da + lso + 64*LDR2, ga + (size_t)64*lda);
            cp16(db + lso + 64*LDR2, gb + (size_t)64*ldb);
            cp_commit();
            lslot++; if (lslot == STAGES) lslot = 0;
        }

        uint32_t sa = sAu + slot*(STG_ELEMS*2);
        uint32_t sbb = sBu + slot*(STG_ELEMS*2);
        slot++; if (slot == STAGES) slot = 0;

        uint32_t bf[4][4];
        #pragma unroll
        for (int nt = 0; nt < 4; nt++) ldm4(bf[nt], sbb + boff + nt*(8*LDR2));

        #pragma unroll
        for (int ks = 0; ks < 2; ks++) {
            uint32_t af[4][4];
            #pragma unroll
            for (int mt = 0; mt < 4; mt++)
                ldm4(af[mt], sa + aoff + mt*(16*LDR2) + ks*32);
            #pragma unroll
            for (int mt = 0; mt < 4; mt++)
                #pragma unroll
                for (int nt = 0; nt < 4; nt++)
                    mma16816_f16(acc[mt][nt], af[mt], &bf[nt][ks*2]);
        }
    }
    __syncthreads();

    // -------- epilogue --------
    if (mode == 1) {
        // fp16 [hi|lo] pair output; bias per zc, optional relu
        const float* bs = (zc == 1 && bias2) ? bias2 : bias;
        __half* base = outS + (size_t)zb*cZb + (size_t)zc*cZc;
        #pragma unroll
        for (int mt = 0; mt < 4; mt++) {
            int m = m0 + wm + mt*16 + ar;
            __half* p0 = base + (size_t)m*ldo;
            __half* p1 = p0 + (size_t)8*ldo;
            #pragma unroll
            for (int nt = 0; nt < 4; nt++) {
                int n = n0 + wn + nt*8 + ac;
                float v0 = acc[mt][nt][0], v1 = acc[mt][nt][1];
                float v2 = acc[mt][nt][2], v3 = acc[mt][nt][3];
                if (bs) { v0 += bs[n]; v1 += bs[n+1]; v2 += bs[n]; v3 += bs[n+1]; }
                if (relu) { v0 = fmaxf(v0,0.f); v1 = fmaxf(v1,0.f); v2 = fmaxf(v2,0.f); v3 = fmaxf(v3,0.f); }
                f16_hilo_pair(p0, n, loOff, v0, v1);
                f16_hilo_pair(p1, n, loOff, v2, v3);
            }
        }
    } else if (mode == 2) {
        // FFW2: zc==0 -> s fp16 [hi|lo] ld KF at outS; zc==1 -> e fp16 hi ld KB at outS+cZc
        const float* bs = (zc == 1) ? bias2 : bias;
        #pragma unroll
        for (int mt = 0; mt < 4; mt++) {
            int m = m0 + wm + mt*16 + ar;
            __half* p0;
            int ld = (zc == 0) ? KF : KB;
            if (zc == 0) p0 = outS + (size_t)m*KF;
            else         p0 = outS + (size_t)cZc + (size_t)m*KB;
            __half* p1 = p0 + (size_t)8*ld;
            #pragma unroll
            for (int nt = 0; nt < 4; nt++) {
                int n = n0 + wn + nt*8 + ac;
                float v0 = acc[mt][nt][0] + bs[n], v1 = acc[mt][nt][1] + bs[n+1];
                float v2 = acc[mt][nt][2] + bs[n], v3 = acc[mt][nt][3] + bs[n+1];
                if (zc == 0) { f16_hilo_pair(p0, n, 1024, v0, v1); f16_hilo_pair(p1, n, 1024, v2, v3); }
                else         { f16_hi_pair(p0, n, v0, v1);         f16_hi_pair(p1, n, v2, v3); }
            }
        }
    } else {
        // float strided output + rank-1 terms
        float* base = outF + (size_t)zb*cZb + (size_t)zc*cZc;
        const float* uz = uArr + (size_t)z*512;
        const float* vz = vArr + (size_t)z*512;
        #pragma unroll
        for (int mt = 0; mt < 4; mt++) {
            int m = m0 + wm + mt*16 + ar;
            float u0 = uz[m], u1 = uz[m + 8];
            float* p0 = base + (size_t)m*ldcM;
            float* p1 = p0 + (size_t)8*ldcM;
            #pragma unroll
            for (int nt = 0; nt < 4; nt++) {
                int n = n0 + wn + nt*8 + ac;
                float vn0 = vz[n], vn1 = vz[n + 1];
                p0[(size_t)n*3]     = acc[mt][nt][0] + u0 + vn0;
                p0[(size_t)(n+1)*3] = acc[mt][nt][1] + u0 + vn1;
                p1[(size_t)n*3]     = acc[mt][nt][2] + u1 + vn0;
                p1[(size_t)(n+1)*3] = acc[mt][nt][3] + u1 + vn1;
            }
        }
    }
}

// -------------------- launcher --------------------
extern "C" void kernel_launch(void* const* d_in, const int* in_sizes, int n_in,
                              void* d_out, int out_size) {
    const float* ctx  = (const float*)d_in[0];
    const float* ques = (const float*)d_in[1];
    const float* wsim = (const float*)d_in[2];
    const float* W1s  = (const float*)d_in[3];
    const float* b1s  = (const float*)d_in[4];
    const float* W2s  = (const float*)d_in[5];
    const float* b2s  = (const float*)d_in[6];
    const float* W1e  = (const float*)d_in[7];
    const float* b1e  = (const float*)d_in[8];
    const float* W2e  = (const float*)d_in[9];
    const float* b2e  = (const float*)d_in[10];
    const float* Wb   = (const float*)d_in[11];
    float* out = (float*)d_out;

    float *q2, *rowmax, *q2c, *w01, *w10, *w11, *u, *v;
    __half *xs, *h1, *w1, *w2, *sef, *Tf, *wbtf;
    cudaGetSymbolAddress((void**)&q2, g_q2);
    cudaGetSymbolAddress((void**)&rowmax, g_rowmax);
    cudaGetSymbolAddress((void**)&q2c, g_q2c);
    cudaGetSymbolAddress((void**)&w01, g_w01);
    cudaGetSymbolAddress((void**)&w10, g_w10);
    cudaGetSymbolAddress((void**)&w11, g_w11);
    cudaGetSymbolAddress((void**)&u, g_u);
    cudaGetSymbolAddress((void**)&v, g_v);
    cudaGetSymbolAddress((void**)&xs, g_xs);
    cudaGetSymbolAddress((void**)&h1, g_h1);
    cudaGetSymbolAddress((void**)&w1, g_w1);
    cudaGetSymbolAddress((void**)&w2, g_w2);
    cudaGetSymbolAddress((void**)&sef, g_sef);
    cudaGetSymbolAddress((void**)&Tf, g_Tf);
    cudaGetSymbolAddress((void**)&wbtf, g_wbtf);

    __half* sf = sef;                               // s fp16 [hi|lo], ld KF
    __half* ef = sef + (size_t)ROWS*KF;             // e fp16 hi, ld KB

    cudaFuncSetAttribute(mma_gemm, cudaFuncAttributeMaxDynamicSharedMemorySize, SMEM_BYTES);

    // front-end + weight prep
    qdot_kernel<<<dim3(Bz, LQ), 32>>>(ques, wsim, q2);
    extract_w_kernel<<<4, 256>>>(Wb, w01, w10, w11);
    prep_wT<<<dim3(16, 32, 2), dim3(32, 8)>>>(W1s, W1e, W1e, 512,
        w1, (size_t)512*KW1, 1024, KW1, 512);
    prep_wT<<<dim3(32, 16, 2), dim3(32, 8)>>>(W2s, W2e, W2e, 1024,
        w2, (size_t)1024*KW2, 512, KW2, 1024);
    prep_wT<<<dim3(32, 32, 3), dim3(32, 8)>>>(Wb, Wb + 1025, Wb + 2050, 3075,
        wbtf, (size_t)1024*KB, 1024, KB, 1024);
    sim_softmax_c2q_kernel<<<ROWS, 256>>>(ctx, ques, wsim, q2, xs, rowmax);
    bsoftmax_q2c_kernel<<<Bz, 256>>>(ctx, rowmax, q2c);
    fillx4_kernel<<<ROWS, 256>>>(ctx, q2c, xs);

    long long zero = 0;
    // FFW1 (fp16 2-term): h1[z] = relu(x@W1[z]+b1[z]) as fp16 [hi|lo] ld KHF
    mma_gemm<<<dim3(4, 64, 2), 256, SMEM_BYTES>>>(
        xs, KXF, zero, zero,
        w1, KW1, zero, (long long)512*KW1, 1023,
        64, 2, 1, h1, KHF, 512, b1s, b1e, 1,
        nullptr, 0, zero, (long long)ROWS*KHF, nullptr, nullptr);
    // FFW2 (fp16 2-term): z=0 -> s fp16 [hi|lo] at sef; z=1 -> e fp16 hi at sef+ROWS*KF
    mma_gemm<<<dim3(8, 64, 2), 256, SMEM_BYTES>>>(
        h1, KHF, zero, (long long)ROWS*KHF,
        w2, KW2, zero, (long long)1024*KW2, 511,
        32, 2, 2, sef, 0, 0, b2s, b2e, 0,
        nullptr, 0, zero, (long long)ROWS*KF, nullptr, nullptr);

    // rank-1 terms
    uv_kernel<<<ROWS, 256>>>(sf, ef, w01, w10, w11, u, v);

    // Biaffine stage 1 (fp16 2-term): T[z=b*3+c] = s_b @ wbt_c^T, out fp16 [hi|lo]
    mma_gemm<<<dim3(8, 4, 48), 256, SMEM_BYTES>>>(
        sf, KF, (long long)LC*KF, zero,
        wbtf, KB, zero, (long long)1024*KB, 1023,
        64, 3, 1, Tf, KF, 1024, nullptr, nullptr, 0,
        nullptr, 0, (long long)3*LC*KF, (long long)LC*KF, nullptr, nullptr);

    // Biaffine stage 2 (fp16 2-term): out[b,:,:,c] = T[z] @ e_b^T + u + v
    mma_gemm<<<dim3(4, 4, 48), 256, SMEM_BYTES>>>(
        Tf, KF, (long long)3*LC*KF, (long long)LC*KF,
        ef, KB, (long long)LC*KB, zero, 1023,
        64, 3, 4, nullptr, 0, 0, nullptr, nullptr, 0,
        out, LC*3, (long long)LC*LC*3, 1ll, u, v);
}

// round 12
// speedup vs baseline: 2.1581x; 1.3936x over previous
#include <cuda_runtime.h>
#include <cuda_fp16.h>
#include <cstdint>
#include <math.h>

// Problem constants
#define Bz   16
#define LC   512
#define LQ   64
#define Hd   256
#define ROWS (Bz*LC)     // 8192

// fp16 strides (elements)
#define KXF  2048        // x   [hi|lo], K=1024
#define KW1  1024        // W1^T fp16 hi, K-wrapped
#define KHF  1024        // h1  [hi|lo], K=512
#define KW2  512         // W2^T fp16 hi, K-wrapped
#define KB   1024        // s/e/T/wbt fp16 hi, K=1024

// -------------------- device scratch (zero-init .bss) --------------------
__device__ float g_q2[Bz*LQ];
__device__ float g_rowmax[ROWS];
__device__ float g_q2c[Bz*Hd];
__device__ float g_w01[3*1024];
__device__ float g_w10[3*1024];
__device__ float g_w11[3];
__device__ float g_u[48*512];
__device__ float g_v[48*512];
__device__ __align__(16) __half g_xs [(size_t)ROWS*KXF];
__device__ __align__(16) __half g_h1 [(size_t)2*ROWS*KHF];   // [start,end] hi|lo
__device__ __align__(16) __half g_w1 [(size_t)2*512*KW1];    // [W1s,W1e]^T hi
__device__ __align__(16) __half g_w2 [(size_t)2*1024*KW2];   // [W2s,W2e]^T hi
__device__ __align__(16) __half g_sef[(size_t)2*ROWS*KB];    // s hi, then e hi
__device__ __align__(16) __half g_Tf [(size_t)48*LC*KB];     // T hi
__device__ __align__(16) __half g_wbtf[(size_t)3*1024*KB];   // Wb^T hi

// -------------------- helpers --------------------
__device__ __forceinline__ uint32_t smem_u32(const void* p) {
    uint32_t a;
    asm("{ .reg .u64 t; cvta.to.shared.u64 t, %1; cvt.u32.u64 %0, t; }" : "=r"(a) : "l"(p));
    return a;
}
__device__ __forceinline__ void cp16(uint32_t saddr, const void* g) {
    asm volatile("cp.async.ca.shared.global [%0], [%1], 16;" :: "r"(saddr), "l"(g) : "memory");
}
__device__ __forceinline__ void cp_commit() { asm volatile("cp.async.commit_group;" ::: "memory"); }
__device__ __forceinline__ void cp_wait0()  { asm volatile("cp.async.wait_group 0;" ::: "memory"); }
__device__ __forceinline__ void cp_wait1()  { asm volatile("cp.async.wait_group 1;" ::: "memory"); }

__device__ __forceinline__ unsigned short h16bits(__half h) {
    return *reinterpret_cast<unsigned short*>(&h);
}
__device__ __forceinline__ void ldm4(uint32_t* r, uint32_t saddr) {
    asm volatile("ldmatrix.sync.aligned.m8n8.x4.shared.b16 {%0,%1,%2,%3}, [%4];"
                 : "=r"(r[0]), "=r"(r[1]), "=r"(r[2]), "=r"(r[3]) : "r"(saddr));
}
__device__ __forceinline__ void mma16816_f16(float* c, const uint32_t* a, const uint32_t* b) {
    asm volatile(
        "mma.sync.aligned.m16n8k16.row.col.f32.f16.f16.f32 "
        "{%0,%1,%2,%3}, {%4,%5,%6,%7}, {%8,%9}, {%0,%1,%2,%3};"
        : "+f"(c[0]), "+f"(c[1]), "+f"(c[2]), "+f"(c[3])
        : "r"(a[0]), "r"(a[1]), "r"(a[2]), "r"(a[3]), "r"(b[0]), "r"(b[1]));
}

// -------------------- attention front-end --------------------
__device__ __forceinline__ void xsplit_store(__half* xr, int col, float v) {
    __half hi = __float2half_rn(v);
    __half lo = __float2half_rn(v - __half2float(hi));
    xr[col] = hi; xr[col + 1024] = lo;
}

__global__ void qdot_kernel(const float* __restrict__ ques, const float* __restrict__ wsim,
                            float* __restrict__ q2) {
    int b = blockIdx.x, j = blockIdx.y, l = threadIdx.x;
    const float* q = ques + ((size_t)(b*LQ + j))*Hd;
    float s = 0.f;
    #pragma unroll
    for (int u = 0; u < Hd/32; u++) s += q[l + u*32] * wsim[Hd + l + u*32];
    #pragma unroll
    for (int o = 16; o > 0; o >>= 1) s += __shfl_down_sync(0xffffffffu, s, o);
    if (l == 0) q2[b*LQ + j] = s;
}

__global__ void sim_softmax_c2q_kernel(const float* __restrict__ ctx,
                                       const float* __restrict__ ques,
                                       const float* __restrict__ wsim,
                                       const float* __restrict__ q2,
                                       __half* __restrict__ xs,
                                       float* __restrict__ rowmax) {
    int row = blockIdx.x, b = row >> 9;
    int t = threadIdx.x, w = t >> 5, l = t & 31;
    __shared__ float ctxs[Hd], cw3[Hd], simv[LQ], sred[8];
    __shared__ float c1s;

    const float* crow = ctx + (size_t)row * Hd;
    float cv = crow[t];
    ctxs[t] = cv;
    cw3[t]  = cv * wsim[2*Hd + t];

    float v = cv * wsim[t];
    #pragma unroll
    for (int o = 16; o > 0; o >>= 1) v += __shfl_down_sync(0xffffffffu, v, o);
    if (l == 0) sred[w] = v;
    __syncthreads();
    if (t == 0) { float s = 0.f; for (int u = 0; u < 8; u++) s += sred[u]; c1s = s; }
    __syncthreads();

    const float* qb = ques + (size_t)b * LQ * Hd;
    #pragma unroll
    for (int jj = 0; jj < 8; jj++) {
        int j = w * 8 + jj;
        const float* q = qb + (size_t)j * Hd;
        float s = 0.f;
        #pragma unroll
        for (int u = 0; u < Hd/32; u++) s += cw3[l + u*32] * q[l + u*32];
        #pragma unroll
        for (int o = 16; o > 0; o >>= 1) s += __shfl_down_sync(0xffffffffu, s, o);
        if (l == 0) simv[j] = c1s + q2[b*LQ + j] + s;
    }
    __syncthreads();

    if (t < 32) {
        float s0 = simv[t], s1v = simv[t + 32];
        float m = fmaxf(s0, s1v);
        #pragma unroll
        for (int o = 16; o > 0; o >>= 1) m = fmaxf(m, __shfl_xor_sync(0xffffffffu, m, o));
        if (t == 0) rowmax[row] = m;
        float e0 = expf(s0 - m), e1v = expf(s1v - m);
        float sum = e0 + e1v;
        #pragma unroll
        for (int o = 16; o > 0; o >>= 1) sum += __shfl_xor_sync(0xffffffffu, sum, o);
        float inv = 1.f / sum;
        simv[t] = e0 * inv; simv[t + 32] = e1v * inv;
    }
    __syncthreads();

    float acc = 0.f;
    #pragma unroll 8
    for (int j = 0; j < LQ; j++) acc += simv[j] * qb[(size_t)j*Hd + t];

    __half* xr = xs + (size_t)row * KXF;
    xsplit_store(xr, t,        ctxs[t]);
    xsplit_store(xr, Hd + t,   acc);
    xsplit_store(xr, 2*Hd + t, ctxs[t] * acc);
}

__global__ void bsoftmax_q2c_kernel(const float* __restrict__ ctx,
                                    const float* __restrict__ rowmax,
                                    float* __restrict__ q2c) {
    int b = blockIdx.x, t = threadIdx.x;
    __shared__ float w[LC]; __shared__ float sred[8]; __shared__ float mshared, sshared;
    w[t] = rowmax[b*LC + t]; w[t + 256] = rowmax[b*LC + t + 256];
    __syncthreads();
    float m = fmaxf(w[t], w[t + 256]);
    #pragma unroll
    for (int o = 16; o > 0; o >>= 1) m = fmaxf(m, __shfl_xor_sync(0xffffffffu, m, o));
    if ((t & 31) == 0) sred[t >> 5] = m;
    __syncthreads();
    if (t == 0) { float mm = sred[0]; for (int u = 1; u < 8; u++) mm = fmaxf(mm, sred[u]); mshared = mm; }
    __syncthreads();
    m = mshared;
    float e0 = expf(w[t] - m), e1v = expf(w[t + 256] - m);
    float s = e0 + e1v;
    #pragma unroll
    for (int o = 16; o > 0; o >>= 1) s += __shfl_xor_sync(0xffffffffu, s, o);
    if ((t & 31) == 0) sred[t >> 5] = s;
    __syncthreads();
    if (t == 0) { float ss = 0.f; for (int u = 0; u < 8; u++) ss += sred[u]; sshared = ss; }
    __syncthreads();
    float inv = 1.f / sshared;
    w[t] = e0 * inv; w[t + 256] = e1v * inv;
    __syncthreads();
    float acc = 0.f;
    const float* cb = ctx + (size_t)b * LC * Hd;
    for (int i = 0; i < LC; i++) acc += w[i] * cb[(size_t)i*Hd + t];
    q2c[b*Hd + t] = acc;
}

__global__ void fillx4_kernel(const float* __restrict__ ctx,
                              const float* __restrict__ q2c,
                              __half* __restrict__ xs) {
    int row = blockIdx.x, t = threadIdx.x, b = row >> 9;
    float c = ctx[(size_t)row*Hd + t];
    xsplit_store(xs + (size_t)row*KXF, 3*Hd + t, c * q2c[b*Hd + t]);
}

// extract rank-1 parts of Wb
__global__ void extract_w_kernel(const float* __restrict__ Wb,
                                 float* __restrict__ w01, float* __restrict__ w10,
                                 float* __restrict__ w11) {
    int i = blockIdx.x*256 + threadIdx.x;   // 0..1023
    #pragma unroll
    for (int c = 0; c < 3; c++) {
        w01[c*1024 + i] = Wb[(size_t)i*3075 + c*1025 + 1024];
        w10[c*1024 + i] = Wb[(size_t)1024*3075 + c*1025 + i];
    }
    if (i < 3) w11[i] = Wb[(size_t)1024*3075 + (size_t)i*1025 + 1024];
}

// u[z=b*3+c][x] = s[b,x]·w01[c] + w11[c] ; v[z][y] = e[b,y]·w10[c]   (hi-only s/e)
__global__ void uv_kernel(const __half* __restrict__ sf,
                          const __half* __restrict__ ef,
                          const float* __restrict__ w01, const float* __restrict__ w10,
                          const float* __restrict__ w11,
                          float* __restrict__ u, float* __restrict__ v) {
    int row = blockIdx.x, t = threadIdx.x, w = t >> 5, l = t & 31;
    int b = row >> 9, x = row & 511;
    const __half* sr = sf + (size_t)row*KB;
    const __half* er = ef + (size_t)row*KB;
    float a[6] = {0,0,0,0,0,0};
    for (int i = t; i < 1024; i += 256) {
        float sv = __half2float(sr[i]);
        float ev = __half2float(er[i]);
        #pragma unroll
        for (int c = 0; c < 3; c++) {
            a[c]     += sv * w01[c*1024 + i];
            a[3 + c] += ev * w10[c*1024 + i];
        }
    }
    __shared__ float red[6][8];
    #pragma unroll
    for (int q = 0; q < 6; q++) {
        float s = a[q];
        #pragma unroll
        for (int o = 16; o > 0; o >>= 1) s += __shfl_down_sync(0xffffffffu, s, o);
        if (l == 0) red[q][w] = s;
    }
    __syncthreads();
    if (t < 6) {
        float s = 0.f;
        #pragma unroll
        for (int k = 0; k < 8; k++) s += red[t][k];
        if (t < 3) u[(b*3 + t)*512 + x] = s + w11[t];
        else       v[(b*3 + (t - 3))*512 + x] = s;
    }
}

// Transpose weights -> fp16 hi single block [Nrows x Kpad]
__global__ void prep_wT(const float* __restrict__ a0, const float* __restrict__ a1,
                        const float* __restrict__ a2, int srcLd,
                        __half* __restrict__ dst, size_t dstZ,
                        int Kreal, int Kpad, int Nrows) {
    const float* src = (blockIdx.z == 0) ? a0 : ((blockIdx.z == 1) ? a1 : a2);
    __half* d = dst + blockIdx.z * dstZ;
    __shared__ float tile[32][33];
    int k0 = blockIdx.y*32, n0 = blockIdx.x*32;
    int tx = threadIdx.x, ty = threadIdx.y;
    #pragma unroll
    for (int i = 0; i < 32; i += 8) {
        int k = k0 + ty + i, n = n0 + tx;
        tile[ty + i][tx] = (k < Kreal && n < Nrows) ? src[(size_t)k*srcLd + n] : 0.f;
    }
    __syncthreads();
    #pragma unroll
    for (int i = 0; i < 32; i += 8) {
        int n = n0 + ty + i, k = k0 + tx;
        if (n < Nrows)
            d[(size_t)n*Kpad + k] = __float2half_rn(tile[tx][ty + i]);
    }
}

// -------------------- fp16 warp-mma GEMM --------------------
// D = A @ B^T ; 128x128x32 tile, 8 warps, 64x32 warp tile, occ 2,
// batched ldmatrix, 3-stage cp.async ring. B K-index wrapped by bKmask.
#define LDR 40
#define STAGES 3
#define STG_ELEMS (128*LDR)
#define SMEM_BYTES (STAGES*2*STG_ELEMS*2) // 61440

__device__ __forceinline__ void f16_hilo_pair(__half* p, int n, int loOff, float v0, float v1) {
    __half h0 = __float2half_rn(v0); __half l0 = __float2half_rn(v0 - __half2float(h0));
    __half h1 = __float2half_rn(v1); __half l1 = __float2half_rn(v1 - __half2float(h1));
    uint32_t H = (uint32_t)h16bits(h0) | ((uint32_t)h16bits(h1) << 16);
    uint32_t L = (uint32_t)h16bits(l0) | ((uint32_t)h16bits(l1) << 16);
    *reinterpret_cast<uint32_t*>(p + n) = H;
    *reinterpret_cast<uint32_t*>(p + loOff + n) = L;
}
__device__ __forceinline__ void f16_hi_pair(__half* p, int n, float v0, float v1) {
    __half h0 = __float2half_rn(v0);
    __half h1 = __float2half_rn(v1);
    *reinterpret_cast<uint32_t*>(p + n) =
        (uint32_t)h16bits(h0) | ((uint32_t)h16bits(h1) << 16);
}

__global__ __launch_bounds__(256, 2)
void mma_gemm(const __half* __restrict__ A, int lda, long long aZb, long long aZc,
              const __half* __restrict__ B, int ldb, long long bZb, long long bZc,
              int bKmask, int nch, int zdiv, int mode,
              __half* outS, int ldo, int loOff,
              const float* bias, const float* bias2, int relu,
              float* outF, int ldcM, long long cZb, long long cZc,
              const float* uArr, const float* vArr)
{
    extern __shared__ __half smem_dyn[];
    const int LDR2 = LDR*2;

    int tid = threadIdx.x;
    int z = blockIdx.z, zb = z / zdiv, zc = z - zb * zdiv;
    const __half* Ab = A + (size_t)zb*aZb + (size_t)zc*aZc + (size_t)(blockIdx.y*128)*lda;
    const __half* Bb = B + (size_t)zb*bZb + (size_t)zc*bZc + (size_t)(blockIdx.x*128)*ldb;
    int m0 = blockIdx.y * 128, n0 = blockIdx.x * 128;

    int lane = tid & 31, wid = tid >> 5;
    int wm = (wid & 1) * 64, wn = (wid >> 1) * 32;
    int ar = lane >> 2, ac = (lane & 3) * 2;

    int lrow = tid >> 2, lseg = tid & 3;
    uint32_t sAu = smem_u32(smem_dyn);
    uint32_t sBu = sAu + STAGES*STG_ELEMS*2;
    uint32_t lso = lrow*LDR2 + lseg*16;

    uint32_t aoff = (uint32_t)(wm + (lane & 15))*LDR2 + (lane >> 4)*16;
    uint32_t boff = (uint32_t)(wn + (lane & 7))*LDR2 + (lane >> 3)*16;

    float acc[4][4][4];
    #pragma unroll
    for (int i = 0; i < 4; i++)
        #pragma unroll
        for (int j = 0; j < 4; j++)
            #pragma unroll
            for (int q = 0; q < 4; q++) acc[i][j][q] = 0.f;

    #pragma unroll
    for (int p = 0; p < 2; p++) {
        int k0 = p * 32;
        int bk0 = k0 & bKmask;
        const __half* ga = Ab + (size_t)lrow*lda + k0 + lseg*8;
        const __half* gb = Bb + (size_t)lrow*ldb + bk0 + lseg*8;
        uint32_t da = sAu + p*(STG_ELEMS*2), db = sBu + p*(STG_ELEMS*2);
        cp16(da + lso, ga);            cp16(db + lso, gb);
        cp16(da + lso + 64*LDR2, ga + (size_t)64*lda);
        cp16(db + lso + 64*LDR2, gb + (size_t)64*ldb);
        cp_commit();
    }

    int slot = 0, lslot = 2;
    for (int c = 0; c < nch; c++) {
        if (c >= nch - 1) cp_wait0(); else cp_wait1();
        __syncthreads();

        if (c + 2 < nch) {
            int k0 = (c + 2) * 32;
            int bk0 = k0 & bKmask;
            const __half* ga = Ab + (size_t)lrow*lda + k0 + lseg*8;
            const __half* gb = Bb + (size_t)lrow*ldb + bk0 + lseg*8;
            uint32_t da = sAu + lslot*(STG_ELEMS*2), db = sBu + lslot*(STG_ELEMS*2);
            cp16(da + lso, ga);            cp16(db + lso, gb);
            cp16(da + lso + 64*LDR2, ga + (size_t)64*lda);
            cp16(db + lso + 64*LDR2, gb + (size_t)64*ldb);
            cp_commit();
            lslot++; if (lslot == STAGES) lslot = 0;
        }

        uint32_t sa = sAu + slot*(STG_ELEMS*2);
        uint32_t sbb = sBu + slot*(STG_ELEMS*2);
        slot++; if (slot == STAGES) slot = 0;

        uint32_t bf[4][4];
        #pragma unroll
        for (int nt = 0; nt < 4; nt++) ldm4(bf[nt], sbb + boff + nt*(8*LDR2));

        #pragma unroll
        for (int ks = 0; ks < 2; ks++) {
            uint32_t af[4][4];
            #pragma unroll
            for (int mt = 0; mt < 4; mt++)
                ldm4(af[mt], sa + aoff + mt*(16*LDR2) + ks*32);
            #pragma unroll
            for (int mt = 0; mt < 4; mt++)
                #pragma unroll
                for (int nt = 0; nt < 4; nt++)
                    mma16816_f16(acc[mt][nt], af[mt], &bf[nt][ks*2]);
        }
    }
    __syncthreads();

    // -------- epilogue --------
    if (mode == 1) {
        // fp16 [hi|lo] pair output (FFW1); bias per zc, relu
        const float* bs = (zc == 1 && bias2) ? bias2 : bias;
        __half* base = outS + (size_t)zb*cZb + (size_t)zc*cZc;
        #pragma unroll
        for (int mt = 0; mt < 4; mt++) {
            int m = m0 + wm + mt*16 + ar;
            __half* p0 = base + (size_t)m*ldo;
            __half* p1 = p0 + (size_t)8*ldo;
            #pragma unroll
            for (int nt = 0; nt < 4; nt++) {
                int n = n0 + wn + nt*8 + ac;
                float v0 = acc[mt][nt][0], v1 = acc[mt][nt][1];
                float v2 = acc[mt][nt][2], v3 = acc[mt][nt][3];
                if (bs) { v0 += bs[n]; v1 += bs[n+1]; v2 += bs[n]; v3 += bs[n+1]; }
                if (relu) { v0 = fmaxf(v0,0.f); v1 = fmaxf(v1,0.f); v2 = fmaxf(v2,0.f); v3 = fmaxf(v3,0.f); }
                f16_hilo_pair(p0, n, loOff, v0, v1);
                f16_hilo_pair(p1, n, loOff, v2, v3);
            }
        }
    } else if (mode == 2) {
        // fp16 hi-only output (FFW2 + stage1); optional bias per zc
        const float* bs = (zc == 1 && bias2) ? bias2 : bias;
        __half* base = outS + (size_t)zb*cZb + (size_t)zc*cZc;
        #pragma unroll
        for (int mt = 0; mt < 4; mt++) {
            int m = m0 + wm + mt*16 + ar;
            __half* p0 = base + (size_t)m*ldo;
            __half* p1 = p0 + (size_t)8*ldo;
            #pragma unroll
            for (int nt = 0; nt < 4; nt++) {
                int n = n0 + wn + nt*8 + ac;
                float v0 = acc[mt][nt][0], v1 = acc[mt][nt][1];
                float v2 = acc[mt][nt][2], v3 = acc[mt][nt][3];
                if (bs) { v0 += bs[n]; v1 += bs[n+1]; v2 += bs[n]; v3 += bs[n+1]; }
                f16_hi_pair(p0, n, v0, v1);
                f16_hi_pair(p1, n, v2, v3);
            }
        }
    } else {
        // float strided output + rank-1 terms (stage2)
        float* base = outF + (size_t)zb*cZb + (size_t)zc*cZc;
        const float* uz = uArr + (size_t)z*512;
        const float* vz = vArr + (size_t)z*512;
        #pragma unroll
        for (int mt = 0; mt < 4; mt++) {
            int m = m0 + wm + mt*16 + ar;
            float u0 = uz[m], u1 = uz[m + 8];
            float* p0 = base + (size_t)m*ldcM;
            float* p1 = p0 + (size_t)8*ldcM;
            #pragma unroll
            for (int nt = 0; nt < 4; nt++) {
                int n = n0 + wn + nt*8 + ac;
                float vn0 = vz[n], vn1 = vz[n + 1];
                p0[(size_t)n*3]     = acc[mt][nt][0] + u0 + vn0;
                p0[(size_t)(n+1)*3] = acc[mt][nt][1] + u0 + vn1;
                p1[(size_t)n*3]     = acc[mt][nt][2] + u1 + vn0;
                p1[(size_t)(n+1)*3] = acc[mt][nt][3] + u1 + vn1;
            }
        }
    }
}

// -------------------- launcher --------------------
extern "C" void kernel_launch(void* const* d_in, const int* in_sizes, int n_in,
                              void* d_out, int out_size) {
    const float* ctx  = (const float*)d_in[0];
    const float* ques = (const float*)d_in[1];
    const float* wsim = (const float*)d_in[2];
    const float* W1s  = (const float*)d_in[3];
    const float* b1s  = (const float*)d_in[4];
    const float* W2s  = (const float*)d_in[5];
    const float* b2s  = (const float*)d_in[6];
    const float* W1e  = (const float*)d_in[7];
    const float* b1e  = (const float*)d_in[8];
    const float* W2e  = (const float*)d_in[9];
    const float* b2e  = (const float*)d_in[10];
    const float* Wb   = (const float*)d_in[11];
    float* out = (float*)d_out;

    float *q2, *rowmax, *q2c, *w01, *w10, *w11, *u, *v;
    __half *xs, *h1, *w1, *w2, *sef, *Tf, *wbtf;
    cudaGetSymbolAddress((void**)&q2, g_q2);
    cudaGetSymbolAddress((void**)&rowmax, g_rowmax);
    cudaGetSymbolAddress((void**)&q2c, g_q2c);
    cudaGetSymbolAddress((void**)&w01, g_w01);
    cudaGetSymbolAddress((void**)&w10, g_w10);
    cudaGetSymbolAddress((void**)&w11, g_w11);
    cudaGetSymbolAddress((void**)&u, g_u);
    cudaGetSymbolAddress((void**)&v, g_v);
    cudaGetSymbolAddress((void**)&xs, g_xs);
    cudaGetSymbolAddress((void**)&h1, g_h1);
    cudaGetSymbolAddress((void**)&w1, g_w1);
    cudaGetSymbolAddress((void**)&w2, g_w2);
    cudaGetSymbolAddress((void**)&sef, g_sef);
    cudaGetSymbolAddress((void**)&Tf, g_Tf);
    cudaGetSymbolAddress((void**)&wbtf, g_wbtf);

    __half* sf = sef;                               // s fp16 hi, ld KB
    __half* ef = sef + (size_t)ROWS*KB;             // e fp16 hi, ld KB

    cudaFuncSetAttribute(mma_gemm, cudaFuncAttributeMaxDynamicSharedMemorySize, SMEM_BYTES);

    // front-end + weight prep
    qdot_kernel<<<dim3(Bz, LQ), 32>>>(ques, wsim, q2);
    extract_w_kernel<<<4, 256>>>(Wb, w01, w10, w11);
    prep_wT<<<dim3(16, 32, 2), dim3(32, 8)>>>(W1s, W1e, W1e, 512,
        w1, (size_t)512*KW1, 1024, KW1, 512);
    prep_wT<<<dim3(32, 16, 2), dim3(32, 8)>>>(W2s, W2e, W2e, 1024,
        w2, (size_t)1024*KW2, 512, KW2, 1024);
    prep_wT<<<dim3(32, 32, 3), dim3(32, 8)>>>(Wb, Wb + 1025, Wb + 2050, 3075,
        wbtf, (size_t)1024*KB, 1024, KB, 1024);
    sim_softmax_c2q_kernel<<<ROWS, 256>>>(ctx, ques, wsim, q2, xs, rowmax);
    bsoftmax_q2c_kernel<<<Bz, 256>>>(ctx, rowmax, q2c);
    fillx4_kernel<<<ROWS, 256>>>(ctx, q2c, xs);

    long long zero = 0;
    // FFW1 (x [hi|lo] @ W1hi): h1[z] = relu(...) as fp16 [hi|lo], ld KHF
    mma_gemm<<<dim3(4, 64, 2), 256, SMEM_BYTES>>>(
        xs, KXF, zero, zero,
        w1, KW1, zero, (long long)512*KW1, 1023,
        64, 2, 1, h1, KHF, 512, b1s, b1e, 1,
        nullptr, 0, zero, (long long)ROWS*KHF, nullptr, nullptr);
    // FFW2 (h1 [hi|lo] @ W2hi): s,e fp16 hi-only, ld KB
    mma_gemm<<<dim3(8, 64, 2), 256, SMEM_BYTES>>>(
        h1, KHF, zero, (long long)ROWS*KHF,
        w2, KW2, zero, (long long)1024*KW2, 511,
        32, 2, 2, sef, KB, 0, b2s, b2e, 0,
        nullptr, 0, zero, (long long)ROWS*KB, nullptr, nullptr);

    // rank-1 terms
    uv_kernel<<<ROWS, 256>>>(sf, ef, w01, w10, w11, u, v);

    // Biaffine stage 1 (s hi @ wbt hi): T fp16 hi-only, ld KB
    mma_gemm<<<dim3(8, 4, 48), 256, SMEM_BYTES>>>(
        sf, KB, (long long)LC*KB, zero,
        wbtf, KB, zero, (long long)1024*KB, 1023,
        32, 3, 2, Tf, KB, 0, nullptr, nullptr, 0,
        nullptr, 0, (long long)3*LC*KB, (long long)LC*KB, nullptr, nullptr);

    // Biaffine stage 2 (T hi @ e hi): out float strided + u + v
    mma_gemm<<<dim3(4, 4, 48), 256, SMEM_BYTES>>>(
        Tf, KB, (long long)3*LC*KB, (long long)LC*KB,
        ef, KB, (long long)LC*KB, zero, 1023,
        32, 3, 4, nullptr, 0, 0, nullptr, nullptr, 0,
        out, LC*3, (long long)LC*LC*3, 1ll, u, v);
}

// round 13
// speedup vs baseline: 2.6275x; 1.2175x over previous
#include <cuda_runtime.h>
#include <cuda_fp16.h>
#include <cstdint>
#include <math.h>

// Problem constants
#define Bz   16
#define LC   512
#define LQ   64
#define Hd   256
#define ROWS (Bz*LC)     // 8192

// fp16 hi-only strides (elements)
#define KXF  1024        // x  hi, K=1024
#define KW1  1024        // W1^T hi
#define KHF  512         // h1 hi, K=512
#define KW2  512         // W2^T hi
#define KB   1024        // s/e/T/wbt hi, K=1024

// -------------------- device scratch (zero-init .bss) --------------------
__device__ float g_q2[Bz*LQ];
__device__ float g_rowmax[ROWS];
__device__ float g_q2c[Bz*Hd];
__device__ float g_w01[3*1024];
__device__ float g_w10[3*1024];
__device__ float g_w11[3];
__device__ float g_u[48*512];
__device__ float g_v[48*512];
__device__ __align__(16) __half g_xs [(size_t)ROWS*KXF];
__device__ __align__(16) __half g_h1 [(size_t)2*ROWS*KHF];   // [start,end] hi
__device__ __align__(16) __half g_w1 [(size_t)2*512*KW1];    // [W1s,W1e]^T hi
__device__ __align__(16) __half g_w2 [(size_t)2*1024*KW2];   // [W2s,W2e]^T hi
__device__ __align__(16) __half g_sef[(size_t)2*ROWS*KB];    // s hi, then e hi
__device__ __align__(16) __half g_Tf [(size_t)48*LC*KB];     // T hi
__device__ __align__(16) __half g_wbtf[(size_t)3*1024*KB];   // Wb^T hi

// -------------------- helpers --------------------
__device__ __forceinline__ uint32_t smem_u32(const void* p) {
    uint32_t a;
    asm("{ .reg .u64 t; cvta.to.shared.u64 t, %1; cvt.u32.u64 %0, t; }" : "=r"(a) : "l"(p));
    return a;
}
__device__ __forceinline__ void cp16(uint32_t saddr, const void* g) {
    asm volatile("cp.async.ca.shared.global [%0], [%1], 16;" :: "r"(saddr), "l"(g) : "memory");
}
__device__ __forceinline__ void cp_commit() { asm volatile("cp.async.commit_group;" ::: "memory"); }
__device__ __forceinline__ void cp_wait0()  { asm volatile("cp.async.wait_group 0;" ::: "memory"); }
__device__ __forceinline__ void cp_wait1()  { asm volatile("cp.async.wait_group 1;" ::: "memory"); }

__device__ __forceinline__ unsigned short h16bits(__half h) {
    return *reinterpret_cast<unsigned short*>(&h);
}
__device__ __forceinline__ void ldm4(uint32_t* r, uint32_t saddr) {
    asm volatile("ldmatrix.sync.aligned.m8n8.x4.shared.b16 {%0,%1,%2,%3}, [%4];"
                 : "=r"(r[0]), "=r"(r[1]), "=r"(r[2]), "=r"(r[3]) : "r"(saddr));
}
__device__ __forceinline__ void mma16816_f16(float* c, const uint32_t* a, const uint32_t* b) {
    asm volatile(
        "mma.sync.aligned.m16n8k16.row.col.f32.f16.f16.f32 "
        "{%0,%1,%2,%3}, {%4,%5,%6,%7}, {%8,%9}, {%0,%1,%2,%3};"
        : "+f"(c[0]), "+f"(c[1]), "+f"(c[2]), "+f"(c[3])
        : "r"(a[0]), "r"(a[1]), "r"(a[2]), "r"(a[3]), "r"(b[0]), "r"(b[1]));
}

// -------------------- attention front-end --------------------
__global__ void qdot_kernel(const float* __restrict__ ques, const float* __restrict__ wsim,
                            float* __restrict__ q2) {
    int b = blockIdx.x, j = blockIdx.y, l = threadIdx.x;
    const float* q = ques + ((size_t)(b*LQ + j))*Hd;
    float s = 0.f;
    #pragma unroll
    for (int u = 0; u < Hd/32; u++) s += q[l + u*32] * wsim[Hd + l + u*32];
    #pragma unroll
    for (int o = 16; o > 0; o >>= 1) s += __shfl_down_sync(0xffffffffu, s, o);
    if (l == 0) q2[b*LQ + j] = s;
}

__global__ void sim_softmax_c2q_kernel(const float* __restrict__ ctx,
                                       const float* __restrict__ ques,
                                       const float* __restrict__ wsim,
                                       const float* __restrict__ q2,
                                       __half* __restrict__ xs,
                                       float* __restrict__ rowmax) {
    int row = blockIdx.x, b = row >> 9;
    int t = threadIdx.x, w = t >> 5, l = t & 31;
    __shared__ float ctxs[Hd], cw3[Hd], simv[LQ], sred[8];
    __shared__ float c1s;

    const float* crow = ctx + (size_t)row * Hd;
    float cv = crow[t];
    ctxs[t] = cv;
    cw3[t]  = cv * wsim[2*Hd + t];

    float v = cv * wsim[t];
    #pragma unroll
    for (int o = 16; o > 0; o >>= 1) v += __shfl_down_sync(0xffffffffu, v, o);
    if (l == 0) sred[w] = v;
    __syncthreads();
    if (t == 0) { float s = 0.f; for (int u = 0; u < 8; u++) s += sred[u]; c1s = s; }
    __syncthreads();

    const float* qb = ques + (size_t)b * LQ * Hd;
    #pragma unroll
    for (int jj = 0; jj < 8; jj++) {
        int j = w * 8 + jj;
        const float* q = qb + (size_t)j * Hd;
        float s = 0.f;
        #pragma unroll
        for (int u = 0; u < Hd/32; u++) s += cw3[l + u*32] * q[l + u*32];
        #pragma unroll
        for (int o = 16; o > 0; o >>= 1) s += __shfl_down_sync(0xffffffffu, s, o);
        if (l == 0) simv[j] = c1s + q2[b*LQ + j] + s;
    }
    __syncthreads();

    if (t < 32) {
        float s0 = simv[t], s1v = simv[t + 32];
        float m = fmaxf(s0, s1v);
        #pragma unroll
        for (int o = 16; o > 0; o >>= 1) m = fmaxf(m, __shfl_xor_sync(0xffffffffu, m, o));
        if (t == 0) rowmax[row] = m;
        float e0 = expf(s0 - m), e1v = expf(s1v - m);
        float sum = e0 + e1v;
        #pragma unroll
        for (int o = 16; o > 0; o >>= 1) sum += __shfl_xor_sync(0xffffffffu, sum, o);
        float inv = 1.f / sum;
        simv[t] = e0 * inv; simv[t + 32] = e1v * inv;
    }
    __syncthreads();

    float acc = 0.f;
    #pragma unroll 8
    for (int j = 0; j < LQ; j++) acc += simv[j] * qb[(size_t)j*Hd + t];

    __half* xr = xs + (size_t)row * KXF;
    xr[t]        = __float2half_rn(ctxs[t]);
    xr[Hd + t]   = __float2half_rn(acc);
    xr[2*Hd + t] = __float2half_rn(ctxs[t] * acc);
}

__global__ void bsoftmax_q2c_kernel(const float* __restrict__ ctx,
                                    const float* __restrict__ rowmax,
                                    float* __restrict__ q2c) {
    int b = blockIdx.x, t = threadIdx.x;
    __shared__ float w[LC]; __shared__ float sred[8]; __shared__ float mshared, sshared;
    w[t] = rowmax[b*LC + t]; w[t + 256] = rowmax[b*LC + t + 256];
    __syncthreads();
    float m = fmaxf(w[t], w[t + 256]);
    #pragma unroll
    for (int o = 16; o > 0; o >>= 1) m = fmaxf(m, __shfl_xor_sync(0xffffffffu, m, o));
    if ((t & 31) == 0) sred[t >> 5] = m;
    __syncthreads();
    if (t == 0) { float mm = sred[0]; for (int u = 1; u < 8; u++) mm = fmaxf(mm, sred[u]); mshared = mm; }
    __syncthreads();
    m = mshared;
    float e0 = expf(w[t] - m), e1v = expf(w[t + 256] - m);
    float s = e0 + e1v;
    #pragma unroll
    for (int o = 16; o > 0; o >>= 1) s += __shfl_xor_sync(0xffffffffu, s, o);
    if ((t & 31) == 0) sred[t >> 5] = s;
    __syncthreads();
    if (t == 0) { float ss = 0.f; for (int u = 0; u < 8; u++) ss += sred[u]; sshared = ss; }
    __syncthreads();
    float inv = 1.f / sshared;
    w[t] = e0 * inv; w[t + 256] = e1v * inv;
    __syncthreads();
    float acc = 0.f;
    const float* cb = ctx + (size_t)b * LC * Hd;
    for (int i = 0; i < LC; i++) acc += w[i] * cb[(size_t)i*Hd + t];
    q2c[b*Hd + t] = acc;
}

__global__ void fillx4_kernel(const float* __restrict__ ctx,
                              const float* __restrict__ q2c,
                              __half* __restrict__ xs) {
    int row = blockIdx.x, t = threadIdx.x, b = row >> 9;
    float c = ctx[(size_t)row*Hd + t];
    xs[(size_t)row*KXF + 3*Hd + t] = __float2half_rn(c * q2c[b*Hd + t]);
}

// extract rank-1 parts of Wb
__global__ void extract_w_kernel(const float* __restrict__ Wb,
                                 float* __restrict__ w01, float* __restrict__ w10,
                                 float* __restrict__ w11) {
    int i = blockIdx.x*256 + threadIdx.x;   // 0..1023
    #pragma unroll
    for (int c = 0; c < 3; c++) {
        w01[c*1024 + i] = Wb[(size_t)i*3075 + c*1025 + 1024];
        w10[c*1024 + i] = Wb[(size_t)1024*3075 + c*1025 + i];
    }
    if (i < 3) w11[i] = Wb[(size_t)1024*3075 + (size_t)i*1025 + 1024];
}

// u[z=b*3+c][x] = s[b,x]·w01[c] + w11[c] ; v[z][y] = e[b,y]·w10[c]
__global__ void uv_kernel(const __half* __restrict__ sf,
                          const __half* __restrict__ ef,
                          const float* __restrict__ w01, const float* __restrict__ w10,
                          const float* __restrict__ w11,
                          float* __restrict__ u, float* __restrict__ v) {
    int row = blockIdx.x, t = threadIdx.x, w = t >> 5, l = t & 31;
    int b = row >> 9, x = row & 511;
    const __half* sr = sf + (size_t)row*KB;
    const __half* er = ef + (size_t)row*KB;
    float a[6] = {0,0,0,0,0,0};
    for (int i = t; i < 1024; i += 256) {
        float sv = __half2float(sr[i]);
        float ev = __half2float(er[i]);
        #pragma unroll
        for (int c = 0; c < 3; c++) {
            a[c]     += sv * w01[c*1024 + i];
            a[3 + c] += ev * w10[c*1024 + i];
        }
    }
    __shared__ float red[6][8];
    #pragma unroll
    for (int q = 0; q < 6; q++) {
        float s = a[q];
        #pragma unroll
        for (int o = 16; o > 0; o >>= 1) s += __shfl_down_sync(0xffffffffu, s, o);
        if (l == 0) red[q][w] = s;
    }
    __syncthreads();
    if (t < 6) {
        float s = 0.f;
        #pragma unroll
        for (int k = 0; k < 8; k++) s += red[t][k];
        if (t < 3) u[(b*3 + t)*512 + x] = s + w11[t];
        else       v[(b*3 + (t - 3))*512 + x] = s;
    }
}

// Transpose weights -> fp16 hi single block [Nrows x Kpad]
__global__ void prep_wT(const float* __restrict__ a0, const float* __restrict__ a1,
                        const float* __restrict__ a2, int srcLd,
                        __half* __restrict__ dst, size_t dstZ,
                        int Kreal, int Kpad, int Nrows) {
    const float* src = (blockIdx.z == 0) ? a0 : ((blockIdx.z == 1) ? a1 : a2);
    __half* d = dst + blockIdx.z * dstZ;
    __shared__ float tile[32][33];
    int k0 = blockIdx.y*32, n0 = blockIdx.x*32;
    int tx = threadIdx.x, ty = threadIdx.y;
    #pragma unroll
    for (int i = 0; i < 32; i += 8) {
        int k = k0 + ty + i, n = n0 + tx;
        tile[ty + i][tx] = (k < Kreal && n < Nrows) ? src[(size_t)k*srcLd + n] : 0.f;
    }
    __syncthreads();
    #pragma unroll
    for (int i = 0; i < 32; i += 8) {
        int n = n0 + ty + i, k = k0 + tx;
        if (n < Nrows)
            d[(size_t)n*Kpad + k] = __float2half_rn(tile[tx][ty + i]);
    }
}

// -------------------- fp16 warp-mma GEMM --------------------
// D = A @ B^T ; 128x128x32 tile, 8 warps, 64x32 warp tile, occ 2,
// batched ldmatrix, 3-stage cp.async ring.
#define LDR 40
#define STAGES 3
#define STG_ELEMS (128*LDR)
#define SMEM_BYTES (STAGES*2*STG_ELEMS*2) // 61440

__device__ __forceinline__ void f16_hi_pair(__half* p, int n, float v0, float v1) {
    __half h0 = __float2half_rn(v0);
    __half h1 = __float2half_rn(v1);
    *reinterpret_cast<uint32_t*>(p + n) =
        (uint32_t)h16bits(h0) | ((uint32_t)h16bits(h1) << 16);
}

__global__ __launch_bounds__(256, 2)
void mma_gemm(const __half* __restrict__ A, int lda, long long aZb, long long aZc,
              const __half* __restrict__ B, int ldb, long long bZb, long long bZc,
              int nch, int zdiv, int mode,
              __half* outS, int ldo,
              const float* bias, const float* bias2, int relu,
              float* outF, int ldcM, long long cZb, long long cZc,
              const float* uArr, const float* vArr)
{
    extern __shared__ __half smem_dyn[];
    const int LDR2 = LDR*2;

    int tid = threadIdx.x;
    int z = blockIdx.z, zb = z / zdiv, zc = z - zb * zdiv;
    const __half* Ab = A + (size_t)zb*aZb + (size_t)zc*aZc + (size_t)(blockIdx.y*128)*lda;
    const __half* Bb = B + (size_t)zb*bZb + (size_t)zc*bZc + (size_t)(blockIdx.x*128)*ldb;
    int m0 = blockIdx.y * 128, n0 = blockIdx.x * 128;

    int lane = tid & 31, wid = tid >> 5;
    int wm = (wid & 1) * 64, wn = (wid >> 1) * 32;
    int ar = lane >> 2, ac = (lane & 3) * 2;

    int lrow = tid >> 2, lseg = tid & 3;
    uint32_t sAu = smem_u32(smem_dyn);
    uint32_t sBu = sAu + STAGES*STG_ELEMS*2;
    uint32_t lso = lrow*LDR2 + lseg*16;

    uint32_t aoff = (uint32_t)(wm + (lane & 15))*LDR2 + (lane >> 4)*16;
    uint32_t boff = (uint32_t)(wn + (lane & 7))*LDR2 + (lane >> 3)*16;

    float acc[4][4][4];
    #pragma unroll
    for (int i = 0; i < 4; i++)
        #pragma unroll
        for (int j = 0; j < 4; j++)
            #pragma unroll
            for (int q = 0; q < 4; q++) acc[i][j][q] = 0.f;

    #pragma unroll
    for (int p = 0; p < 2; p++) {
        int k0 = p * 32;
        const __half* ga = Ab + (size_t)lrow*lda + k0 + lseg*8;
        const __half* gb = Bb + (size_t)lrow*ldb + k0 + lseg*8;
        uint32_t da = sAu + p*(STG_ELEMS*2), db = sBu + p*(STG_ELEMS*2);
        cp16(da + lso, ga);            cp16(db + lso, gb);
        cp16(da + lso + 64*LDR2, ga + (size_t)64*lda);
        cp16(db + lso + 64*LDR2, gb + (size_t)64*ldb);
        cp_commit();
    }

    int slot = 0, lslot = 2;
    for (int c = 0; c < nch; c++) {
        if (c >= nch - 1) cp_wait0(); else cp_wait1();
        __syncthreads();

        if (c + 2 < nch) {
            int k0 = (c + 2) * 32;
            const __half* ga = Ab + (size_t)lrow*lda + k0 + lseg*8;
            const __half* gb = Bb + (size_t)lrow*ldb + k0 + lseg*8;
            uint32_t da = sAu + lslot*(STG_ELEMS*2), db = sBu + lslot*(STG_ELEMS*2);
            cp16(da + lso, ga);            cp16(db + lso, gb);
            cp16(da + lso + 64*LDR2, ga + (size_t)64*lda);
            cp16(db + lso + 64*LDR2, gb + (size_t)64*ldb);
            cp_commit();
            lslot++; if (lslot == STAGES) lslot = 0;
        }

        uint32_t sa = sAu + slot*(STG_ELEMS*2);
        uint32_t sbb = sBu + slot*(STG_ELEMS*2);
        slot++; if (slot == STAGES) slot = 0;

        uint32_t bf[4][4];
        #pragma unroll
        for (int nt = 0; nt < 4; nt++) ldm4(bf[nt], sbb + boff + nt*(8*LDR2));

        #pragma unroll
        for (int ks = 0; ks < 2; ks++) {
            uint32_t af[4][4];
            #pragma unroll
            for (int mt = 0; mt < 4; mt++)
                ldm4(af[mt], sa + aoff + mt*(16*LDR2) + ks*32);
            #pragma unroll
            for (int mt = 0; mt < 4; mt++)
                #pragma unroll
                for (int nt = 0; nt < 4; nt++)
                    mma16816_f16(acc[mt][nt], af[mt], &bf[nt][ks*2]);
        }
    }
    __syncthreads();

    // -------- epilogue --------
    if (mode == 2) {
        // fp16 hi-only output; optional per-z bias and relu
        const float* bs = (zc == 1 && bias2) ? bias2 : bias;
        __half* base = outS + (size_t)zb*cZb + (size_t)zc*cZc;
        #pragma unroll
        for (int mt = 0; mt < 4; mt++) {
            int m = m0 + wm + mt*16 + ar;
            __half* p0 = base + (size_t)m*ldo;
            __half* p1 = p0 + (size_t)8*ldo;
            #pragma unroll
            for (int nt = 0; nt < 4; nt++) {
                int n = n0 + wn + nt*8 + ac;
                float v0 = acc[mt][nt][0], v1 = acc[mt][nt][1];
                float v2 = acc[mt][nt][2], v3 = acc[mt][nt][3];
                if (bs) { v0 += bs[n]; v1 += bs[n+1]; v2 += bs[n]; v3 += bs[n+1]; }
                if (relu) { v0 = fmaxf(v0,0.f); v1 = fmaxf(v1,0.f); v2 = fmaxf(v2,0.f); v3 = fmaxf(v3,0.f); }
                f16_hi_pair(p0, n, v0, v1);
                f16_hi_pair(p1, n, v2, v3);
            }
        }
    } else {
        // float strided output + rank-1 terms (stage2)
        float* base = outF + (size_t)zb*cZb + (size_t)zc*cZc;
        const float* uz = uArr + (size_t)z*512;
        const float* vz = vArr + (size_t)z*512;
        #pragma unroll
        for (int mt = 0; mt < 4; mt++) {
            int m = m0 + wm + mt*16 + ar;
            float u0 = uz[m], u1 = uz[m + 8];
            float* p0 = base + (size_t)m*ldcM;
            float* p1 = p0 + (size_t)8*ldcM;
            #pragma unroll
            for (int nt = 0; nt < 4; nt++) {
                int n = n0 + wn + nt*8 + ac;
                float vn0 = vz[n], vn1 = vz[n + 1];
                p0[(size_t)n*3]     = acc[mt][nt][0] + u0 + vn0;
                p0[(size_t)(n+1)*3] = acc[mt][nt][1] + u0 + vn1;
                p1[(size_t)n*3]     = acc[mt][nt][2] + u1 + vn0;
                p1[(size_t)(n+1)*3] = acc[mt][nt][3] + u1 + vn1;
            }
        }
    }
}

// -------------------- launcher --------------------
extern "C" void kernel_launch(void* const* d_in, const int* in_sizes, int n_in,
                              void* d_out, int out_size) {
    const float* ctx  = (const float*)d_in[0];
    const float* ques = (const float*)d_in[1];
    const float* wsim = (const float*)d_in[2];
    const float* W1s  = (const float*)d_in[3];
    const float* b1s  = (const float*)d_in[4];
    const float* W2s  = (const float*)d_in[5];
    const float* b2s  = (const float*)d_in[6];
    const float* W1e  = (const float*)d_in[7];
    const float* b1e  = (const float*)d_in[8];
    const float* W2e  = (const float*)d_in[9];
    const float* b2e  = (const float*)d_in[10];
    const float* Wb   = (const float*)d_in[11];
    float* out = (float*)d_out;

    float *q2, *rowmax, *q2c, *w01, *w10, *w11, *u, *v;
    __half *xs, *h1, *w1, *w2, *sef, *Tf, *wbtf;
    cudaGetSymbolAddress((void**)&q2, g_q2);
    cudaGetSymbolAddress((void**)&rowmax, g_rowmax);
    cudaGetSymbolAddress((void**)&q2c, g_q2c);
    cudaGetSymbolAddress((void**)&w01, g_w01);
    cudaGetSymbolAddress((void**)&w10, g_w10);
    cudaGetSymbolAddress((void**)&w11, g_w11);
    cudaGetSymbolAddress((void**)&u, g_u);
    cudaGetSymbolAddress((void**)&v, g_v);
    cudaGetSymbolAddress((void**)&xs, g_xs);
    cudaGetSymbolAddress((void**)&h1, g_h1);
    cudaGetSymbolAddress((void**)&w1, g_w1);
    cudaGetSymbolAddress((void**)&w2, g_w2);
    cudaGetSymbolAddress((void**)&sef, g_sef);
    cudaGetSymbolAddress((void**)&Tf, g_Tf);
    cudaGetSymbolAddress((void**)&wbtf, g_wbtf);

    __half* sf = sef;                               // s hi, ld KB
    __half* ef = sef + (size_t)ROWS*KB;             // e hi, ld KB

    cudaFuncSetAttribute(mma_gemm, cudaFuncAttributeMaxDynamicSharedMemorySize, SMEM_BYTES);

    // front-end + weight prep
    qdot_kernel<<<dim3(Bz, LQ), 32>>>(ques, wsim, q2);
    extract_w_kernel<<<4, 256>>>(Wb, w01, w10, w11);
    prep_wT<<<dim3(16, 32, 2), dim3(32, 8)>>>(W1s, W1e, W1e, 512,
        w1, (size_t)512*KW1, 1024, KW1, 512);
    prep_wT<<<dim3(32, 16, 2), dim3(32, 8)>>>(W2s, W2e, W2e, 1024,
        w2, (size_t)1024*KW2, 512, KW2, 1024);
    prep_wT<<<dim3(32, 32, 3), dim3(32, 8)>>>(Wb, Wb + 1025, Wb + 2050, 3075,
        wbtf, (size_t)1024*KB, 1024, KB, 1024);
    sim_softmax_c2q_kernel<<<ROWS, 256>>>(ctx, ques, wsim, q2, xs, rowmax);
    bsoftmax_q2c_kernel<<<Bz, 256>>>(ctx, rowmax, q2c);
    fillx4_kernel<<<ROWS, 256>>>(ctx, q2c, xs);

    long long zero = 0;
    // FFW1 (x hi @ W1 hi): h1[z] = relu(x@W1[z]+b1[z]) hi-only, ld KHF
    mma_gemm<<<dim3(4, 64, 2), 256, SMEM_BYTES>>>(
        xs, KXF, zero, zero,
        w1, KW1, zero, (long long)512*KW1,
        32, 2, 2, h1, KHF, b1s, b1e, 1,
        nullptr, 0, zero, (long long)ROWS*KHF, nullptr, nullptr);
    // FFW2 (h1 hi @ W2 hi): s,e hi-only, ld KB
    mma_gemm<<<dim3(8, 64, 2), 256, SMEM_BYTES>>>(
        h1, KHF, zero, (long long)ROWS*KHF,
        w2, KW2, zero, (long long)1024*KW2,
        16, 2, 2, sef, KB, b2s, b2e, 0,
        nullptr, 0, zero, (long long)ROWS*KB, nullptr, nullptr);

    // rank-1 terms
    uv_kernel<<<ROWS, 256>>>(sf, ef, w01, w10, w11, u, v);

    // Biaffine stage 1 (s hi @ wbt hi): T hi-only, ld KB
    mma_gemm<<<dim3(8, 4, 48), 256, SMEM_BYTES>>>(
        sf, KB, (long long)LC*KB, zero,
        wbtf, KB, zero, (long long)1024*KB,
        32, 3, 2, Tf, KB, nullptr, nullptr, 0,
        nullptr, 0, (long long)3*LC*KB, (long long)LC*KB, nullptr, nullptr);

    // Biaffine stage 2 (T hi @ e hi): out float strided + u + v
    mma_gemm<<<dim3(4, 4, 48), 256, SMEM_BYTES>>>(
        Tf, KB, (long long)3*LC*KB, (long long)LC*KB,
        ef, KB, (long long)LC*KB, zero,
        32, 3, 4, nullptr, 0, nullptr, nullptr, 0,
        out, LC*3, (long long)LC*LC*3, 1ll, u, v);
}

// round 14
// speedup vs baseline: 3.5036x; 1.3335x over previous
#include <cuda_runtime.h>
#include <cuda_fp16.h>
#include <cstdint>
#include <math.h>

// Problem constants
#define Bz   16
#define LC   512
#define LQ   64
#define Hd   256
#define ROWS (Bz*LC)     // 8192

#define KXF  1024        // x hi, K=1024
#define KW1  1024        // W1^T hi
#define KHF  512         // h1 hi, K=512

// -------------------- device scratch (zero-init .bss) --------------------
__device__ float g_q2[Bz*LQ];
__device__ float g_rowmax[ROWS];
__device__ float g_q2c[Bz*Hd];
__device__ float g_qv[3*1024];
__device__ float g_rv[3*1024];
__device__ float g_s0[3];
__device__ float g_s1[3];
__device__ float g_uq[3*512];
__device__ float g_vq[3*512];
__device__ float g_u[48*512];
__device__ float g_v[48*512];
__device__ __align__(16) __half g_xs [(size_t)ROWS*KXF];
__device__ __align__(16) __half g_h1 [(size_t)2*ROWS*KHF];   // [start,end] hi
__device__ __align__(16) __half g_w1 [(size_t)2*512*KW1];    // [W1s,W1e]^T hi
__device__ __align__(16) __half g_w2sf[(size_t)512*2048];    // W2s [hi|lo]
__device__ __align__(16) __half g_w2ef[(size_t)512*2048];    // W2e [hi|hi]
__device__ __align__(16) __half g_wbtf[(size_t)3*1024*1024]; // Wb00^T hi
__device__ __align__(16) __half g_Pf [(size_t)3*512*2048];   // P = W2s@Wb00, [hi|lo]
__device__ __align__(16) __half g_Mtf[(size_t)3*512*512];    // Mt = M^T hi
__device__ __align__(16) __half g_Tf [(size_t)48*LC*KHF];    // T hi

// -------------------- helpers --------------------
__device__ __forceinline__ uint32_t smem_u32(const void* p) {
    uint32_t a;
    asm("{ .reg .u64 t; cvta.to.shared.u64 t, %1; cvt.u32.u64 %0, t; }" : "=r"(a) : "l"(p));
    return a;
}
__device__ __forceinline__ void cp16(uint32_t saddr, const void* g) {
    asm volatile("cp.async.ca.shared.global [%0], [%1], 16;" :: "r"(saddr), "l"(g) : "memory");
}
__device__ __forceinline__ void cp_commit() { asm volatile("cp.async.commit_group;" ::: "memory"); }
__device__ __forceinline__ void cp_wait0()  { asm volatile("cp.async.wait_group 0;" ::: "memory"); }
__device__ __forceinline__ void cp_wait1()  { asm volatile("cp.async.wait_group 1;" ::: "memory"); }

__device__ __forceinline__ unsigned short h16bits(__half h) {
    return *reinterpret_cast<unsigned short*>(&h);
}
__device__ __forceinline__ void ldm4(uint32_t* r, uint32_t saddr) {
    asm volatile("ldmatrix.sync.aligned.m8n8.x4.shared.b16 {%0,%1,%2,%3}, [%4];"
                 : "=r"(r[0]), "=r"(r[1]), "=r"(r[2]), "=r"(r[3]) : "r"(saddr));
}
__device__ __forceinline__ void mma16816_f16(float* c, const uint32_t* a, const uint32_t* b) {
    asm volatile(
        "mma.sync.aligned.m16n8k16.row.col.f32.f16.f16.f32 "
        "{%0,%1,%2,%3}, {%4,%5,%6,%7}, {%8,%9}, {%0,%1,%2,%3};"
        : "+f"(c[0]), "+f"(c[1]), "+f"(c[2]), "+f"(c[3])
        : "r"(a[0]), "r"(a[1]), "r"(a[2]), "r"(a[3]), "r"(b[0]), "r"(b[1]));
}
__device__ __forceinline__ float blk_reduce(float s, float* sm, int t, int nw) {
    int w = t >> 5, l = t & 31;
    #pragma unroll
    for (int o = 16; o > 0; o >>= 1) s += __shfl_down_sync(0xffffffffu, s, o);
    if (l == 0) sm[w] = s;
    __syncthreads();
    float r = 0.f;
    if (t == 0) for (int k = 0; k < nw; k++) r += sm[k];
    return r;
}

// -------------------- attention front-end --------------------
__global__ void qdot_kernel(const float* __restrict__ ques, const float* __restrict__ wsim,
                            float* __restrict__ q2) {
    int b = blockIdx.x, j = blockIdx.y, l = threadIdx.x;
    const float* q = ques + ((size_t)(b*LQ + j))*Hd;
    float s = 0.f;
    #pragma unroll
    for (int u = 0; u < Hd/32; u++) s += q[l + u*32] * wsim[Hd + l + u*32];
    #pragma unroll
    for (int o = 16; o > 0; o >>= 1) s += __shfl_down_sync(0xffffffffu, s, o);
    if (l == 0) q2[b*LQ + j] = s;
}

__global__ void sim_softmax_c2q_kernel(const float* __restrict__ ctx,
                                       const float* __restrict__ ques,
                                       const float* __restrict__ wsim,
                                       const float* __restrict__ q2,
                                       __half* __restrict__ xs,
                                       float* __restrict__ rowmax) {
    int row = blockIdx.x, b = row >> 9;
    int t = threadIdx.x, w = t >> 5, l = t & 31;
    __shared__ float ctxs[Hd], cw3[Hd], simv[LQ], sred[8];
    __shared__ float c1s;

    const float* crow = ctx + (size_t)row * Hd;
    float cv = crow[t];
    ctxs[t] = cv;
    cw3[t]  = cv * wsim[2*Hd + t];

    float v = cv * wsim[t];
    #pragma unroll
    for (int o = 16; o > 0; o >>= 1) v += __shfl_down_sync(0xffffffffu, v, o);
    if (l == 0) sred[w] = v;
    __syncthreads();
    if (t == 0) { float s = 0.f; for (int u = 0; u < 8; u++) s += sred[u]; c1s = s; }
    __syncthreads();

    const float* qb = ques + (size_t)b * LQ * Hd;
    #pragma unroll
    for (int jj = 0; jj < 8; jj++) {
        int j = w * 8 + jj;
        const float* q = qb + (size_t)j * Hd;
        float s = 0.f;
        #pragma unroll
        for (int u = 0; u < Hd/32; u++) s += cw3[l + u*32] * q[l + u*32];
        #pragma unroll
        for (int o = 16; o > 0; o >>= 1) s += __shfl_down_sync(0xffffffffu, s, o);
        if (l == 0) simv[j] = c1s + q2[b*LQ + j] + s;
    }
    __syncthreads();

    if (t < 32) {
        float s0 = simv[t], s1v = simv[t + 32];
        float m = fmaxf(s0, s1v);
        #pragma unroll
        for (int o = 16; o > 0; o >>= 1) m = fmaxf(m, __shfl_xor_sync(0xffffffffu, m, o));
        if (t == 0) rowmax[row] = m;
        float e0 = expf(s0 - m), e1v = expf(s1v - m);
        float sum = e0 + e1v;
        #pragma unroll
        for (int o = 16; o > 0; o >>= 1) sum += __shfl_xor_sync(0xffffffffu, sum, o);
        float inv = 1.f / sum;
        simv[t] = e0 * inv; simv[t + 32] = e1v * inv;
    }
    __syncthreads();

    float acc = 0.f;
    #pragma unroll 8
    for (int j = 0; j < LQ; j++) acc += simv[j] * qb[(size_t)j*Hd + t];

    __half* xr = xs + (size_t)row * KXF;
    xr[t]        = __float2half_rn(ctxs[t]);
    xr[Hd + t]   = __float2half_rn(acc);
    xr[2*Hd + t] = __float2half_rn(ctxs[t] * acc);
}

__global__ void bsoftmax_q2c_kernel(const float* __restrict__ ctx,
                                    const float* __restrict__ rowmax,
                                    float* __restrict__ q2c) {
    int b = blockIdx.x, t = threadIdx.x;
    __shared__ float w[LC]; __shared__ float sred[8]; __shared__ float mshared, sshared;
    w[t] = rowmax[b*LC + t]; w[t + 256] = rowmax[b*LC + t + 256];
    __syncthreads();
    float m = fmaxf(w[t], w[t + 256]);
    #pragma unroll
    for (int o = 16; o > 0; o >>= 1) m = fmaxf(m, __shfl_xor_sync(0xffffffffu, m, o));
    if ((t & 31) == 0) sred[t >> 5] = m;
    __syncthreads();
    if (t == 0) { float mm = sred[0]; for (int u = 1; u < 8; u++) mm = fmaxf(mm, sred[u]); mshared = mm; }
    __syncthreads();
    m = mshared;
    float e0 = expf(w[t] - m), e1v = expf(w[t + 256] - m);
    float s = e0 + e1v;
    #pragma unroll
    for (int o = 16; o > 0; o >>= 1) s += __shfl_xor_sync(0xffffffffu, s, o);
    if ((t & 31) == 0) sred[t >> 5] = s;
    __syncthreads();
    if (t == 0) { float ss = 0.f; for (int u = 0; u < 8; u++) ss += sred[u]; sshared = ss; }
    __syncthreads();
    float inv = 1.f / sshared;
    w[t] = e0 * inv; w[t + 256] = e1v * inv;
    __syncthreads();
    float acc = 0.f;
    const float* cb = ctx + (size_t)b * LC * Hd;
    for (int i = 0; i < LC; i++) acc += w[i] * cb[(size_t)i*Hd + t];
    q2c[b*Hd + t] = acc;
}

__global__ void fillx4_kernel(const float* __restrict__ ctx,
                              const float* __restrict__ q2c,
                              __half* __restrict__ xs) {
    int row = blockIdx.x, t = threadIdx.x, b = row >> 9;
    float c = ctx[(size_t)row*Hd + t];
    xs[(size_t)row*KXF + 3*Hd + t] = __float2half_rn(c * q2c[b*Hd + t]);
}

// -------------------- rank-1 / bias folding (all fp32, exact) --------------------
// q_c[t] = Wb00_c[t,:]·b2e + w01_c[t];  r_c[t] = b2s·Wb00_c[:,t] + w10_c[t]
__global__ void qr_kernel(const float* __restrict__ Wb, const float* __restrict__ b2s,
                          const float* __restrict__ b2e,
                          float* __restrict__ qv, float* __restrict__ rv) {
    int t = blockIdx.x, c = blockIdx.y, l = threadIdx.x;   // block 128
    __shared__ float sm[4];
    const float* rowt = Wb + (size_t)t*3075 + c*1025;
    float a0 = 0.f, a1 = 0.f;
    for (int j = l; j < 1024; j += 128) {
        a0 += rowt[j] * b2e[j];
        a1 += b2s[j] * Wb[(size_t)j*3075 + c*1025 + t];
    }
    float r0 = blk_reduce(a0, sm, l, 4);
    if (l == 0) qv[c*1024 + t] = r0 + rowt[1024];
    __syncthreads();
    float r1 = blk_reduce(a1, sm, l, 4);
    if (l == 0) rv[c*1024 + t] = r1 + Wb[(size_t)1024*3075 + c*1025 + t];
}

// s0_c = b2s·q_c + w11_c ; s1_c = b2e·w10_c
__global__ void scal_kernel(const float* __restrict__ Wb, const float* __restrict__ b2s,
                            const float* __restrict__ b2e, const float* __restrict__ qv,
                            float* __restrict__ s0, float* __restrict__ s1) {
    int c = blockIdx.x, t = threadIdx.x;   // block 256
    __shared__ float sm[8];
    float a0 = 0.f, a1 = 0.f;
    for (int k = t; k < 1024; k += 256) {
        a0 += b2s[k] * qv[c*1024 + k];
        a1 += b2e[k] * Wb[(size_t)1024*3075 + c*1025 + k];
    }
    float r0 = blk_reduce(a0, sm, t, 8);
    if (t == 0) s0[c] = r0 + Wb[(size_t)1024*3075 + c*1025 + 1024];
    __syncthreads();
    float r1 = blk_reduce(a1, sm, t, 8);
    if (t == 0) s1[c] = r1;
}

// uq_c[i] = W2s[i,:]·q_c ; vq_c[i] = W2e[i,:]·r_c
__global__ void uvq_kernel(const float* __restrict__ W2s, const float* __restrict__ W2e,
                           const float* __restrict__ qv, const float* __restrict__ rv,
                           float* __restrict__ uq, float* __restrict__ vq) {
    int i = blockIdx.x, c = blockIdx.y, l = threadIdx.x;   // block 128
    __shared__ float sm[4];
    float a0 = 0.f, a1 = 0.f;
    for (int k = l; k < 1024; k += 128) {
        a0 += W2s[(size_t)i*1024 + k] * qv[c*1024 + k];
        a1 += W2e[(size_t)i*1024 + k] * rv[c*1024 + k];
    }
    float r0 = blk_reduce(a0, sm, l, 4);
    if (l == 0) uq[c*512 + i] = r0;
    __syncthreads();
    float r1 = blk_reduce(a1, sm, l, 4);
    if (l == 0) vq[c*512 + i] = r1;
}

// U[z][x] = h1s·uq_c + s0_c ; V[z][y] = h1e·vq_c + s1_c
__global__ void uv_kernel(const __half* __restrict__ h1,
                          const float* __restrict__ uq, const float* __restrict__ vq,
                          const float* __restrict__ s0, const float* __restrict__ s1,
                          float* __restrict__ u, float* __restrict__ v) {
    int row = blockIdx.x, t = threadIdx.x, w = t >> 5, l = t & 31;
    int b = row >> 9, x = row & 511;
    const __half* hs = h1 + (size_t)row*KHF;
    const __half* he = h1 + (size_t)ROWS*KHF + (size_t)row*KHF;
    float a[6] = {0,0,0,0,0,0};
    for (int k = t; k < 512; k += 256) {
        float sv = __half2float(hs[k]);
        float ev = __half2float(he[k]);
        #pragma unroll
        for (int c = 0; c < 3; c++) {
            a[c]     += sv * uq[c*512 + k];
            a[3 + c] += ev * vq[c*512 + k];
        }
    }
    __shared__ float red[6][8];
    #pragma unroll
    for (int q = 0; q < 6; q++) {
        float s = a[q];
        #pragma unroll
        for (int o = 16; o > 0; o >>= 1) s += __shfl_down_sync(0xffffffffu, s, o);
        if (l == 0) red[q][w] = s;
    }
    __syncthreads();
    if (t < 6) {
        float s = 0.f;
        #pragma unroll
        for (int k = 0; k < 8; k++) s += red[t][k];
        if (t < 3) u[(b*3 + t)*512 + x] = s + s0[t];
        else       v[(b*3 + (t - 3))*512 + x] = s + s1[t - 3];
    }
}

// -------------------- weight preps --------------------
// Transpose -> fp16 hi single block [Nrows x Kpad]
__global__ void prep_wT(const float* __restrict__ a0, const float* __restrict__ a1,
                        const float* __restrict__ a2, int srcLd,
                        __half* __restrict__ dst, size_t dstZ,
                        int Kreal, int Kpad, int Nrows) {
    const float* src = (blockIdx.z == 0) ? a0 : ((blockIdx.z == 1) ? a1 : a2);
    __half* d = dst + blockIdx.z * dstZ;
    __shared__ float tile[32][33];
    int k0 = blockIdx.y*32, n0 = blockIdx.x*32;
    int tx = threadIdx.x, ty = threadIdx.y;
    #pragma unroll
    for (int i = 0; i < 32; i += 8) {
        int k = k0 + ty + i, n = n0 + tx;
        tile[ty + i][tx] = (k < Kreal && n < Nrows) ? src[(size_t)k*srcLd + n] : 0.f;
    }
    __syncthreads();
    #pragma unroll
    for (int i = 0; i < 32; i += 8) {
        int n = n0 + ty + i, k = k0 + tx;
        if (n < Nrows)
            d[(size_t)n*Kpad + k] = __float2half_rn(tile[tx][ty + i]);
    }
}

// W2s -> [hi|lo], W2e -> [hi|hi] (no transpose; both [512 x 2048])
__global__ void prep_w2(const float* __restrict__ W2s, const float* __restrict__ W2e,
                        __half* __restrict__ w2sf, __half* __restrict__ w2ef) {
    int i = blockIdx.x;                       // 512
    int t = blockIdx.y*256 + threadIdx.x;     // 1024
    float vs = W2s[(size_t)i*1024 + t];
    __half hs = __float2half_rn(vs);
    __half ls = __float2half_rn(vs - __half2float(hs));
    w2sf[(size_t)i*2048 + t] = hs;
    w2sf[(size_t)i*2048 + 1024 + t] = ls;
    float ve = W2e[(size_t)i*1024 + t];
    __half he = __float2half_rn(ve);
    w2ef[(size_t)i*2048 + t] = he;
    w2ef[(size_t)i*2048 + 1024 + t] = he;
}

// -------------------- fp16 warp-mma GEMM --------------------
// D = A @ B^T ; 128x128x32 tile, 8 warps, 64x32 warp tile, occ 2,
// batched ldmatrix, 3-stage cp.async ring. B K-index wrapped by bKmask.
#define LDR 40
#define STAGES 3
#define STG_ELEMS (128*LDR)
#define SMEM_BYTES (STAGES*2*STG_ELEMS*2) // 61440

__device__ __forceinline__ void f16_hilo_pair(__half* p, int n, int loOff, float v0, float v1) {
    __half h0 = __float2half_rn(v0); __half l0 = __float2half_rn(v0 - __half2float(h0));
    __half h1 = __float2half_rn(v1); __half l1 = __float2half_rn(v1 - __half2float(h1));
    uint32_t H = (uint32_t)h16bits(h0) | ((uint32_t)h16bits(h1) << 16);
    uint32_t L = (uint32_t)h16bits(l0) | ((uint32_t)h16bits(l1) << 16);
    *reinterpret_cast<uint32_t*>(p + n) = H;
    *reinterpret_cast<uint32_t*>(p + loOff + n) = L;
}
__device__ __forceinline__ void f16_hi_pair(__half* p, int n, float v0, float v1) {
    __half h0 = __float2half_rn(v0);
    __half h1 = __float2half_rn(v1);
    *reinterpret_cast<uint32_t*>(p + n) =
        (uint32_t)h16bits(h0) | ((uint32_t)h16bits(h1) << 16);
}

__global__ __launch_bounds__(256, 2)
void mma_gemm(const __half* __restrict__ A, int lda, long long aZb, long long aZc,
              const __half* __restrict__ B, int ldb, long long bZb, long long bZc,
              int bKmask, int nch, int zdiv, int mode,
              __half* outS, int ldo, int loOff,
              const float* bias, const float* bias2, int relu,
              float* outF, int ldcM, long long cZb, long long cZc,
              const float* uArr, const float* vArr)
{
    extern __shared__ __half smem_dyn[];
    const int LDR2 = LDR*2;

    int tid = threadIdx.x;
    int z = blockIdx.z, zb = z / zdiv, zc = z - zb * zdiv;
    const __half* Ab = A + (size_t)zb*aZb + (size_t)zc*aZc + (size_t)(blockIdx.y*128)*lda;
    const __half* Bb = B + (size_t)zb*bZb + (size_t)zc*bZc + (size_t)(blockIdx.x*128)*ldb;
    int m0 = blockIdx.y * 128, n0 = blockIdx.x * 128;

    int lane = tid & 31, wid = tid >> 5;
    int wm = (wid & 1) * 64, wn = (wid >> 1) * 32;
    int ar = lane >> 2, ac = (lane & 3) * 2;

    int lrow = tid >> 2, lseg = tid & 3;
    uint32_t sAu = smem_u32(smem_dyn);
    uint32_t sBu = sAu + STAGES*STG_ELEMS*2;
    uint32_t lso = lrow*LDR2 + lseg*16;

    uint32_t aoff = (uint32_t)(wm + (lane & 15))*LDR2 + (lane >> 4)*16;
    uint32_t boff = (uint32_t)(wn + (lane & 7))*LDR2 + (lane >> 3)*16;

    float acc[4][4][4];
    #pragma unroll
    for (int i = 0; i < 4; i++)
        #pragma unroll
        for (int j = 0; j < 4; j++)
            #pragma unroll
            for (int q = 0; q < 4; q++) acc[i][j][q] = 0.f;

    #pragma unroll
    for (int p = 0; p < 2; p++) {
        int k0 = p * 32;
        int bk0 = k0 & bKmask;
        const __half* ga = Ab + (size_t)lrow*lda + k0 + lseg*8;
        const __half* gb = Bb + (size_t)lrow*ldb + bk0 + lseg*8;
        uint32_t da = sAu + p*(STG_ELEMS*2), db = sBu + p*(STG_ELEMS*2);
        cp16(da + lso, ga);            cp16(db + lso, gb);
        cp16(da + lso + 64*LDR2, ga + (size_t)64*lda);
        cp16(db + lso + 64*LDR2, gb + (size_t)64*ldb);
        cp_commit();
    }

    int slot = 0, lslot = 2;
    for (int c = 0; c < nch; c++) {
        if (c >= nch - 1) cp_wait0(); else cp_wait1();
        __syncthreads();

        if (c + 2 < nch) {
            int k0 = (c + 2) * 32;
            int bk0 = k0 & bKmask;
            const __half* ga = Ab + (size_t)lrow*lda + k0 + lseg*8;
            const __half* gb = Bb + (size_t)lrow*ldb + bk0 + lseg*8;
            uint32_t da = sAu + lslot*(STG_ELEMS*2), db = sBu + lslot*(STG_ELEMS*2);
            cp16(da + lso, ga);            cp16(db + lso, gb);
            cp16(da + lso + 64*LDR2, ga + (size_t)64*lda);
            cp16(db + lso + 64*LDR2, gb + (size_t)64*ldb);
            cp_commit();
            lslot++; if (lslot == STAGES) lslot = 0;
        }

        uint32_t sa = sAu + slot*(STG_ELEMS*2);
        uint32_t sbb = sBu + slot*(STG_ELEMS*2);
        slot++; if (slot == STAGES) slot = 0;

        uint32_t bf[4][4];
        #pragma unroll
        for (int nt = 0; nt < 4; nt++) ldm4(bf[nt], sbb + boff + nt*(8*LDR2));

        #pragma unroll
        for (int ks = 0; ks < 2; ks++) {
            uint32_t af[4][4];
            #pragma unroll
            for (int mt = 0; mt < 4; mt++)
                ldm4(af[mt], sa + aoff + mt*(16*LDR2) + ks*32);
            #pragma unroll
            for (int mt = 0; mt < 4; mt++)
                #pragma unroll
                for (int nt = 0; nt < 4; nt++)
                    mma16816_f16(acc[mt][nt], af[mt], &bf[nt][ks*2]);
        }
    }
    __syncthreads();

    // -------- epilogue --------
    if (mode == 1) {
        // fp16 [hi|lo] output (pre-P)
        __half* base = outS + (size_t)zb*cZb + (size_t)zc*cZc;
        #pragma unroll
        for (int mt = 0; mt < 4; mt++) {
            int m = m0 + wm + mt*16 + ar;
            __half* p0 = base + (size_t)m*ldo;
            __half* p1 = p0 + (size_t)8*ldo;
            #pragma unroll
            for (int nt = 0; nt < 4; nt++) {
                int n = n0 + wn + nt*8 + ac;
                f16_hilo_pair(p0, n, loOff, acc[mt][nt][0], acc[mt][nt][1]);
                f16_hilo_pair(p1, n, loOff, acc[mt][nt][2], acc[mt][nt][3]);
            }
        }
    } else if (mode == 2) {
        // fp16 hi output; optional per-z bias and relu
        const float* bs = (zc == 1 && bias2) ? bias2 : bias;
        __half* base = outS + (size_t)zb*cZb + (size_t)zc*cZc;
        #pragma unroll
        for (int mt = 0; mt < 4; mt++) {
            int m = m0 + wm + mt*16 + ar;
            __half* p0 = base + (size_t)m*ldo;
            __half* p1 = p0 + (size_t)8*ldo;
            #pragma unroll
            for (int nt = 0; nt < 4; nt++) {
                int n = n0 + wn + nt*8 + ac;
                float v0 = acc[mt][nt][0], v1 = acc[mt][nt][1];
                float v2 = acc[mt][nt][2], v3 = acc[mt][nt][3];
                if (bs) { v0 += bs[n]; v1 += bs[n+1]; v2 += bs[n]; v3 += bs[n+1]; }
                if (relu) { v0 = fmaxf(v0,0.f); v1 = fmaxf(v1,0.f); v2 = fmaxf(v2,0.f); v3 = fmaxf(v3,0.f); }
                f16_hi_pair(p0, n, v0, v1);
                f16_hi_pair(p1, n, v2, v3);
            }
        }
    } else {
        // float strided output + rank-1 terms (stage2)
        float* base = outF + (size_t)zb*cZb + (size_t)zc*cZc;
        const float* uz = uArr + (size_t)z*512;
        const float* vz = vArr + (size_t)z*512;
        #pragma unroll
        for (int mt = 0; mt < 4; mt++) {
            int m = m0 + wm + mt*16 + ar;
            float u0 = uz[m], u1 = uz[m + 8];
            float* p0 = base + (size_t)m*ldcM;
            float* p1 = p0 + (size_t)8*ldcM;
            #pragma unroll
            for (int nt = 0; nt < 4; nt++) {
                int n = n0 + wn + nt*8 + ac;
                float vn0 = vz[n], vn1 = vz[n + 1];
                p0[(size_t)n*3]     = acc[mt][nt][0] + u0 + vn0;
                p0[(size_t)(n+1)*3] = acc[mt][nt][1] + u0 + vn1;
                p1[(size_t)n*3]     = acc[mt][nt][2] + u1 + vn0;
                p1[(size_t)(n+1)*3] = acc[mt][nt][3] + u1 + vn1;
            }
        }
    }
}

// -------------------- launcher --------------------
extern "C" void kernel_launch(void* const* d_in, const int* in_sizes, int n_in,
                              void* d_out, int out_size) {
    const float* ctx  = (const float*)d_in[0];
    const float* ques = (const float*)d_in[1];
    const float* wsim = (const float*)d_in[2];
    const float* W1s  = (const float*)d_in[3];
    const float* b1s  = (const float*)d_in[4];
    const float* W2s  = (const float*)d_in[5];
    const float* b2s  = (const float*)d_in[6];
    const float* W1e  = (const float*)d_in[7];
    const float* b1e  = (const float*)d_in[8];
    const float* W2e  = (const float*)d_in[9];
    const float* b2e  = (const float*)d_in[10];
    const float* Wb   = (const float*)d_in[11];
    float* out = (float*)d_out;

    float *q2, *rowmax, *q2c, *qv, *rv, *s0, *s1, *uq, *vq, *u, *v;
    __half *xs, *h1, *w1, *w2sf, *w2ef, *wbtf, *Pf, *Mtf, *Tf;
    cudaGetSymbolAddress((void**)&q2, g_q2);
    cudaGetSymbolAddress((void**)&rowmax, g_rowmax);
    cudaGetSymbolAddress((void**)&q2c, g_q2c);
    cudaGetSymbolAddress((void**)&qv, g_qv);
    cudaGetSymbolAddress((void**)&rv, g_rv);
    cudaGetSymbolAddress((void**)&s0, g_s0);
    cudaGetSymbolAddress((void**)&s1, g_s1);
    cudaGetSymbolAddress((void**)&uq, g_uq);
    cudaGetSymbolAddress((void**)&vq, g_vq);
    cudaGetSymbolAddress((void**)&u, g_u);
    cudaGetSymbolAddress((void**)&v, g_v);
    cudaGetSymbolAddress((void**)&xs, g_xs);
    cudaGetSymbolAddress((void**)&h1, g_h1);
    cudaGetSymbolAddress((void**)&w1, g_w1);
    cudaGetSymbolAddress((void**)&w2sf, g_w2sf);
    cudaGetSymbolAddress((void**)&w2ef, g_w2ef);
    cudaGetSymbolAddress((void**)&wbtf, g_wbtf);
    cudaGetSymbolAddress((void**)&Pf, g_Pf);
    cudaGetSymbolAddress((void**)&Mtf, g_Mtf);
    cudaGetSymbolAddress((void**)&Tf, g_Tf);

    __half* h1e = h1 + (size_t)ROWS*KHF;

    cudaFuncSetAttribute(mma_gemm, cudaFuncAttributeMaxDynamicSharedMemorySize, SMEM_BYTES);

    long long zero = 0;
    const int NOMASK = 0x7fffffff;

    // weight preps + rank-1 folding (independent of activations)
    prep_wT<<<dim3(16, 32, 2), dim3(32, 8)>>>(W1s, W1e, W1e, 512,
        w1, (size_t)512*KW1, 1024, KW1, 512);
    prep_wT<<<dim3(32, 32, 3), dim3(32, 8)>>>(Wb, Wb + 1025, Wb + 2050, 3075,
        wbtf, (size_t)1024*1024, 1024, 1024, 1024);
    prep_w2<<<dim3(512, 4), 256>>>(W2s, W2e, w2sf, w2ef);
    qr_kernel<<<dim3(1024, 3), 128>>>(Wb, b2s, b2e, qv, rv);
    scal_kernel<<<3, 256>>>(Wb, b2s, b2e, qv, s0, s1);
    uvq_kernel<<<dim3(512, 3), 128>>>(W2s, W2e, qv, rv, uq, vq);

    // pre-P: P_c = W2s(hi|lo) @ Wb00_c  -> fp16 [hi|lo], [512 x 2048] per c
    mma_gemm<<<dim3(8, 4, 3), 256, SMEM_BYTES>>>(
        w2sf, 2048, zero, zero,
        wbtf, 1024, zero, (long long)1024*1024, 1023,
        64, 3, 1, Pf, 2048, 1024, nullptr, nullptr, 0,
        nullptr, 0, zero, (long long)512*2048, nullptr, nullptr);
    // pre-Mt: Mt_c = W2e(hi|hi) @ P_c^T -> fp16 hi [512 x 512] per c
    mma_gemm<<<dim3(4, 4, 3), 256, SMEM_BYTES>>>(
        w2ef, 2048, zero, zero,
        Pf, 2048, zero, (long long)512*2048, NOMASK,
        64, 3, 2, Mtf, 512, 0, nullptr, nullptr, 0,
        nullptr, 0, zero, (long long)512*512, nullptr, nullptr);

    // attention front-end
    qdot_kernel<<<dim3(Bz, LQ), 32>>>(ques, wsim, q2);
    sim_softmax_c2q_kernel<<<ROWS, 256>>>(ctx, ques, wsim, q2, xs, rowmax);
    bsoftmax_q2c_kernel<<<Bz, 256>>>(ctx, rowmax, q2c);
    fillx4_kernel<<<ROWS, 256>>>(ctx, q2c, xs);

    // FFW1: h1[z] = relu(x @ W1[z] + b1[z]) fp16 hi, ld KHF
    mma_gemm<<<dim3(4, 64, 2), 256, SMEM_BYTES>>>(
        xs, KXF, zero, zero,
        w1, KW1, zero, (long long)512*KW1, NOMASK,
        32, 2, 2, h1, KHF, 0, b1s, b1e, 1,
        nullptr, 0, zero, (long long)ROWS*KHF, nullptr, nullptr);

    // rank-1 terms from h1
    uv_kernel<<<ROWS, 256>>>(h1, uq, vq, s0, s1, u, v);

    // stage1: T[z=b*3+c] = h1s_b @ Mt_c^T -> fp16 hi, K=512
    mma_gemm<<<dim3(4, 4, 48), 256, SMEM_BYTES>>>(
        h1, KHF, (long long)LC*KHF, zero,
        Mtf, 512, zero, (long long)512*512, NOMASK,
        16, 3, 2, Tf, KHF, 0, nullptr, nullptr, 0,
        nullptr, 0, (long long)3*LC*KHF, (long long)LC*KHF, nullptr, nullptr);

    // stage2: out[b,:,:,c] = T[z] @ h1e_b^T + U + V, K=512
    mma_gemm<<<dim3(4, 4, 48), 256, SMEM_BYTES>>>(
        Tf, KHF, (long long)3*LC*KHF, (long long)LC*KHF,
        h1e, KHF, (long long)LC*KHF, zero, NOMASK,
        16, 3, 4, nullptr, 0, 0, nullptr, nullptr, 0,
        out, LC*3, (long long)LC*LC*3, 1ll, u, v);
}

// round 15
// speedup vs baseline: 3.5638x; 1.0172x over previous
#include <cuda_runtime.h>
#include <cuda_fp16.h>
#include <cstdint>
#include <math.h>

// Problem constants
#define Bz   16
#define LC   512
#define LQ   64
#define Hd   256
#define ROWS (Bz*LC)     // 8192

#define KXF  1024        // x hi, K=1024
#define KW1  1024        // W1^T hi
#define KHF  512         // h1 hi, K=512

// -------------------- device scratch (zero-init .bss) --------------------
__device__ float g_q2[Bz*LQ];
__device__ float g_rowmax[ROWS];
__device__ float g_q2c[Bz*Hd];
__device__ float g_qv[3*1024];
__device__ float g_rv[3*1024];
__device__ float g_s0[3];
__device__ float g_s1[3];
__device__ float g_uq[3*512];
__device__ float g_vq[3*512];
__device__ float g_u[48*512];
__device__ float g_v[48*512];
__device__ float g_Pp[(size_t)4*3*512*1024];   // preP K-split partials (fp32)
__device__ float g_Mp[(size_t)4*3*512*512];    // preMt K-split partials (fp32)
__device__ float g_o3[(size_t)48*512*512];     // stage2 planes (fp32, coalesced)
__device__ __align__(16) __half g_xs [(size_t)ROWS*KXF];
__device__ __align__(16) __half g_h1 [(size_t)2*ROWS*KHF];   // [start,end] hi
__device__ __align__(16) __half g_w1 [(size_t)2*512*KW1];    // [W1s,W1e]^T hi
__device__ __align__(16) __half g_w2sf[(size_t)512*2048];    // W2s [hi|lo]
__device__ __align__(16) __half g_w2ef[(size_t)512*2048];    // W2e [hi|hi]
__device__ __align__(16) __half g_wbtf[(size_t)3*1024*1024]; // Wb00^T hi
__device__ __align__(16) __half g_Pf [(size_t)3*512*2048];   // P [hi|lo]
__device__ __align__(16) __half g_Mtf[(size_t)3*512*512];    // Mt hi
__device__ __align__(16) __half g_Tf [(size_t)48*LC*KHF];    // T hi

// -------------------- helpers --------------------
__device__ __forceinline__ uint32_t smem_u32(const void* p) {
    uint32_t a;
    asm("{ .reg .u64 t; cvta.to.shared.u64 t, %1; cvt.u32.u64 %0, t; }" : "=r"(a) : "l"(p));
    return a;
}
__device__ __forceinline__ void cp16(uint32_t saddr, const void* g) {
    asm volatile("cp.async.ca.shared.global [%0], [%1], 16;" :: "r"(saddr), "l"(g) : "memory");
}
__device__ __forceinline__ void cp_commit() { asm volatile("cp.async.commit_group;" ::: "memory"); }
__device__ __forceinline__ void cp_wait0()  { asm volatile("cp.async.wait_group 0;" ::: "memory"); }
__device__ __forceinline__ void cp_wait1()  { asm volatile("cp.async.wait_group 1;" ::: "memory"); }

__device__ __forceinline__ unsigned short h16bits(__half h) {
    return *reinterpret_cast<unsigned short*>(&h);
}
__device__ __forceinline__ void ldm4(uint32_t* r, uint32_t saddr) {
    asm volatile("ldmatrix.sync.aligned.m8n8.x4.shared.b16 {%0,%1,%2,%3}, [%4];"
                 : "=r"(r[0]), "=r"(r[1]), "=r"(r[2]), "=r"(r[3]) : "r"(saddr));
}
__device__ __forceinline__ void mma16816_f16(float* c, const uint32_t* a, const uint32_t* b) {
    asm volatile(
        "mma.sync.aligned.m16n8k16.row.col.f32.f16.f16.f32 "
        "{%0,%1,%2,%3}, {%4,%5,%6,%7}, {%8,%9}, {%0,%1,%2,%3};"
        : "+f"(c[0]), "+f"(c[1]), "+f"(c[2]), "+f"(c[3])
        : "r"(a[0]), "r"(a[1]), "r"(a[2]), "r"(a[3]), "r"(b[0]), "r"(b[1]));
}
__device__ __forceinline__ float blk_reduce(float s, float* sm, int t, int nw) {
    int w = t >> 5, l = t & 31;
    #pragma unroll
    for (int o = 16; o > 0; o >>= 1) s += __shfl_down_sync(0xffffffffu, s, o);
    if (l == 0) sm[w] = s;
    __syncthreads();
    float r = 0.f;
    if (t == 0) for (int k = 0; k < nw; k++) r += sm[k];
    return r;
}

// -------------------- attention front-end --------------------
__global__ void qdot_kernel(const float* __restrict__ ques, const float* __restrict__ wsim,
                            float* __restrict__ q2) {
    int b = blockIdx.x, j = blockIdx.y, l = threadIdx.x;
    const float* q = ques + ((size_t)(b*LQ + j))*Hd;
    float s = 0.f;
    #pragma unroll
    for (int u = 0; u < Hd/32; u++) s += q[l + u*32] * wsim[Hd + l + u*32];
    #pragma unroll
    for (int o = 16; o > 0; o >>= 1) s += __shfl_down_sync(0xffffffffu, s, o);
    if (l == 0) q2[b*LQ + j] = s;
}

__global__ void sim_softmax_c2q_kernel(const float* __restrict__ ctx,
                                       const float* __restrict__ ques,
                                       const float* __restrict__ wsim,
                                       const float* __restrict__ q2,
                                       __half* __restrict__ xs,
                                       float* __restrict__ rowmax) {
    int row = blockIdx.x, b = row >> 9;
    int t = threadIdx.x, w = t >> 5, l = t & 31;
    __shared__ float ctxs[Hd], cw3[Hd], simv[LQ], sred[8];
    __shared__ float c1s;

    const float* crow = ctx + (size_t)row * Hd;
    float cv = crow[t];
    ctxs[t] = cv;
    cw3[t]  = cv * wsim[2*Hd + t];

    float v = cv * wsim[t];
    #pragma unroll
    for (int o = 16; o > 0; o >>= 1) v += __shfl_down_sync(0xffffffffu, v, o);
    if (l == 0) sred[w] = v;
    __syncthreads();
    if (t == 0) { float s = 0.f; for (int u = 0; u < 8; u++) s += sred[u]; c1s = s; }
    __syncthreads();

    const float* qb = ques + (size_t)b * LQ * Hd;
    #pragma unroll
    for (int jj = 0; jj < 8; jj++) {
        int j = w * 8 + jj;
        const float* q = qb + (size_t)j * Hd;
        float s = 0.f;
        #pragma unroll
        for (int u = 0; u < Hd/32; u++) s += cw3[l + u*32] * q[l + u*32];
        #pragma unroll
        for (int o = 16; o > 0; o >>= 1) s += __shfl_down_sync(0xffffffffu, s, o);
        if (l == 0) simv[j] = c1s + q2[b*LQ + j] + s;
    }
    __syncthreads();

    if (t < 32) {
        float s0 = simv[t], s1v = simv[t + 32];
        float m = fmaxf(s0, s1v);
        #pragma unroll
        for (int o = 16; o > 0; o >>= 1) m = fmaxf(m, __shfl_xor_sync(0xffffffffu, m, o));
        if (t == 0) rowmax[row] = m;
        float e0 = expf(s0 - m), e1v = expf(s1v - m);
        float sum = e0 + e1v;
        #pragma unroll
        for (int o = 16; o > 0; o >>= 1) sum += __shfl_xor_sync(0xffffffffu, sum, o);
        float inv = 1.f / sum;
        simv[t] = e0 * inv; simv[t + 32] = e1v * inv;
    }
    __syncthreads();

    float acc = 0.f;
    #pragma unroll 8
    for (int j = 0; j < LQ; j++) acc += simv[j] * qb[(size_t)j*Hd + t];

    __half* xr = xs + (size_t)row * KXF;
    xr[t]        = __float2half_rn(ctxs[t]);
    xr[Hd + t]   = __float2half_rn(acc);
    xr[2*Hd + t] = __float2half_rn(ctxs[t] * acc);
}

__global__ void bsoftmax_q2c_kernel(const float* __restrict__ ctx,
                                    const float* __restrict__ rowmax,
                                    float* __restrict__ q2c) {
    int b = blockIdx.x, t = threadIdx.x;
    __shared__ float w[LC]; __shared__ float sred[8]; __shared__ float mshared, sshared;
    w[t] = rowmax[b*LC + t]; w[t + 256] = rowmax[b*LC + t + 256];
    __syncthreads();
    float m = fmaxf(w[t], w[t + 256]);
    #pragma unroll
    for (int o = 16; o > 0; o >>= 1) m = fmaxf(m, __shfl_xor_sync(0xffffffffu, m, o));
    if ((t & 31) == 0) sred[t >> 5] = m;
    __syncthreads();
    if (t == 0) { float mm = sred[0]; for (int u = 1; u < 8; u++) mm = fmaxf(mm, sred[u]); mshared = mm; }
    __syncthreads();
    m = mshared;
    float e0 = expf(w[t] - m), e1v = expf(w[t + 256] - m);
    float s = e0 + e1v;
    #pragma unroll
    for (int o = 16; o > 0; o >>= 1) s += __shfl_xor_sync(0xffffffffu, s, o);
    if ((t & 31) == 0) sred[t >> 5] = s;
    __syncthreads();
    if (t == 0) { float ss = 0.f; for (int u = 0; u < 8; u++) ss += sred[u]; sshared = ss; }
    __syncthreads();
    float inv = 1.f / sshared;
    w[t] = e0 * inv; w[t + 256] = e1v * inv;
    __syncthreads();
    float acc = 0.f;
    const float* cb = ctx + (size_t)b * LC * Hd;
    for (int i = 0; i < LC; i++) acc += w[i] * cb[(size_t)i*Hd + t];
    q2c[b*Hd + t] = acc;
}

__global__ void fillx4_kernel(const float* __restrict__ ctx,
                              const float* __restrict__ q2c,
                              __half* __restrict__ xs) {
    int row = blockIdx.x, t = threadIdx.x, b = row >> 9;
    float c = ctx[(size_t)row*Hd + t];
    xs[(size_t)row*KXF + 3*Hd + t] = __float2half_rn(c * q2c[b*Hd + t]);
}

// -------------------- rank-1 / bias folding (fp32, exact) --------------------
// qv[c][t] = Wb_row_t[0:1024]·b2e + Wb[t][c,1024]
__global__ void qv_kernel(const float* __restrict__ Wb, const float* __restrict__ b2e,
                          float* __restrict__ qv) {
    int t = blockIdx.x, c = blockIdx.y, l = threadIdx.x;   // block 128
    __shared__ float sm[4];
    const float* rowt = Wb + (size_t)t*3075 + c*1025;
    float a = 0.f;
    for (int j = l; j < 1024; j += 128) a += rowt[j] * b2e[j];
    float r = blk_reduce(a, sm, l, 4);
    if (l == 0) qv[c*1024 + t] = r + rowt[1024];
}

// rv[c][t] = b2s·Wb00_c[:,t] + w10[c][t]  (coalesced over t)
__global__ void rv_kernel(const float* __restrict__ Wb, const float* __restrict__ b2s,
                          float* __restrict__ rv) {
    int c = blockIdx.y;
    int t = blockIdx.x * 32 + threadIdx.x;   // 32 x-dim
    int ty = threadIdx.y;                    // 8
    __shared__ float sm[8][32];
    float a = 0.f;
    for (int j = ty; j < 1024; j += 8)
        a += b2s[j] * Wb[(size_t)j*3075 + c*1025 + t];
    sm[ty][threadIdx.x] = a;
    __syncthreads();
    if (ty == 0) {
        float s = 0.f;
        #pragma unroll
        for (int k = 0; k < 8; k++) s += sm[k][threadIdx.x];
        rv[c*1024 + t] = s + Wb[(size_t)1024*3075 + c*1025 + t];
    }
}

// s0_c = b2s·q_c + w11_c ; s1_c = b2e·w10_c
__global__ void scal_kernel(const float* __restrict__ Wb, const float* __restrict__ b2s,
                            const float* __restrict__ b2e, const float* __restrict__ qv,
                            float* __restrict__ s0, float* __restrict__ s1) {
    int c = blockIdx.x, t = threadIdx.x;   // block 256
    __shared__ float sm[8];
    float a0 = 0.f, a1 = 0.f;
    for (int k = t; k < 1024; k += 256) {
        a0 += b2s[k] * qv[c*1024 + k];
        a1 += b2e[k] * Wb[(size_t)1024*3075 + c*1025 + k];
    }
    float r0 = blk_reduce(a0, sm, t, 8);
    if (t == 0) s0[c] = r0 + Wb[(size_t)1024*3075 + c*1025 + 1024];
    __syncthreads();
    float r1 = blk_reduce(a1, sm, t, 8);
    if (t == 0) s1[c] = r1;
}

// uq_c[i] = W2s[i,:]·q_c ; vq_c[i] = W2e[i,:]·r_c
__global__ void uvq_kernel(const float* __restrict__ W2s, const float* __restrict__ W2e,
                           const float* __restrict__ qv, const float* __restrict__ rv,
                           float* __restrict__ uq, float* __restrict__ vq) {
    int i = blockIdx.x, c = blockIdx.y, l = threadIdx.x;   // block 128
    __shared__ float sm[4];
    float a0 = 0.f, a1 = 0.f;
    for (int k = l; k < 1024; k += 128) {
        a0 += W2s[(size_t)i*1024 + k] * qv[c*1024 + k];
        a1 += W2e[(size_t)i*1024 + k] * rv[c*1024 + k];
    }
    float r0 = blk_reduce(a0, sm, l, 4);
    if (l == 0) uq[c*512 + i] = r0;
    __syncthreads();
    float r1 = blk_reduce(a1, sm, l, 4);
    if (l == 0) vq[c*512 + i] = r1;
}

// U[z][x] = h1s·uq_c + s0_c ; V[z][y] = h1e·vq_c + s1_c
__global__ void uv_kernel(const __half* __restrict__ h1,
                          const float* __restrict__ uq, const float* __restrict__ vq,
                          const float* __restrict__ s0, const float* __restrict__ s1,
                          float* __restrict__ u, float* __restrict__ v) {
    int row = blockIdx.x, t = threadIdx.x, w = t >> 5, l = t & 31;
    int b = row >> 9, x = row & 511;
    const __half* hs = h1 + (size_t)row*KHF;
    const __half* he = h1 + (size_t)ROWS*KHF + (size_t)row*KHF;
    float a[6] = {0,0,0,0,0,0};
    for (int k = t; k < 512; k += 256) {
        float sv = __half2float(hs[k]);
        float ev = __half2float(he[k]);
        #pragma unroll
        for (int c = 0; c < 3; c++) {
            a[c]     += sv * uq[c*512 + k];
            a[3 + c] += ev * vq[c*512 + k];
        }
    }
    __shared__ float red[6][8];
    #pragma unroll
    for (int q = 0; q < 6; q++) {
        float s = a[q];
        #pragma unroll
        for (int o = 16; o > 0; o >>= 1) s += __shfl_down_sync(0xffffffffu, s, o);
        if (l == 0) red[q][w] = s;
    }
    __syncthreads();
    if (t < 6) {
        float s = 0.f;
        #pragma unroll
        for (int k = 0; k < 8; k++) s += red[t][k];
        if (t < 3) u[(b*3 + t)*512 + x] = s + s0[t];
        else       v[(b*3 + (t - 3))*512 + x] = s + s1[t - 3];
    }
}

// -------------------- weight preps --------------------
__global__ void prep_wT(const float* __restrict__ a0, const float* __restrict__ a1,
                        const float* __restrict__ a2, int srcLd,
                        __half* __restrict__ dst, size_t dstZ,
                        int Kreal, int Kpad, int Nrows) {
    const float* src = (blockIdx.z == 0) ? a0 : ((blockIdx.z == 1) ? a1 : a2);
    __half* d = dst + blockIdx.z * dstZ;
    __shared__ float tile[32][33];
    int k0 = blockIdx.y*32, n0 = blockIdx.x*32;
    int tx = threadIdx.x, ty = threadIdx.y;
    #pragma unroll
    for (int i = 0; i < 32; i += 8) {
        int k = k0 + ty + i, n = n0 + tx;
        tile[ty + i][tx] = (k < Kreal && n < Nrows) ? src[(size_t)k*srcLd + n] : 0.f;
    }
    __syncthreads();
    #pragma unroll
    for (int i = 0; i < 32; i += 8) {
        int n = n0 + ty + i, k = k0 + tx;
        if (n < Nrows)
            d[(size_t)n*Kpad + k] = __float2half_rn(tile[tx][ty + i]);
    }
}

__global__ void prep_w2(const float* __restrict__ W2s, const float* __restrict__ W2e,
                        __half* __restrict__ w2sf, __half* __restrict__ w2ef) {
    int i = blockIdx.x;
    int t = blockIdx.y*256 + threadIdx.x;
    float vs = W2s[(size_t)i*1024 + t];
    __half hs = __float2half_rn(vs);
    __half ls = __float2half_rn(vs - __half2float(hs));
    w2sf[(size_t)i*2048 + t] = hs;
    w2sf[(size_t)i*2048 + 1024 + t] = ls;
    float ve = W2e[(size_t)i*1024 + t];
    __half he = __float2half_rn(ve);
    w2ef[(size_t)i*2048 + t] = he;
    w2ef[(size_t)i*2048 + 1024 + t] = he;
}

// reduce 4 K-split partials -> Pf [hi|lo]
__global__ void reduceP_kernel(const float* __restrict__ Pp, __half* __restrict__ Pf) {
    size_t e = (size_t)blockIdx.x*256 + threadIdx.x;     // < 3*512*1024
    const size_t PL = (size_t)3*512*1024;
    float s = Pp[e] + Pp[e + PL] + Pp[e + 2*PL] + Pp[e + 3*PL];
    int c = e >> 19;                      // /(512*1024)
    int rem = e & 524287;
    int i = rem >> 10, t = rem & 1023;
    __half hi = __float2half_rn(s);
    __half lo = __float2half_rn(s - __half2float(hi));
    size_t base = (size_t)c*512*2048 + (size_t)i*2048 + t;
    Pf[base] = hi; Pf[base + 1024] = lo;
}

// reduce 4 K-split partials -> Mtf hi
__global__ void reduceMt_kernel(const float* __restrict__ Mp, __half* __restrict__ Mtf) {
    size_t e = (size_t)blockIdx.x*256 + threadIdx.x;     // < 3*512*512
    const size_t ML = (size_t)3*512*512;
    float s = Mp[e] + Mp[e + ML] + Mp[e + 2*ML] + Mp[e + 3*ML];
    Mtf[e] = __float2half_rn(s);
}

// interleave o3 planes -> out[b,x,y,c]
__global__ void interleave_kernel(const float* __restrict__ o3, float* __restrict__ out) {
    int row = blockIdx.x;                  // b*512 + x
    int b = row >> 9;
    int t = threadIdx.x;                   // 256; handles y = 2t, 2t+1
    const float* p0 = o3 + ((size_t)(b*3 + 0) << 18) + (size_t)(row & 511)*512;
    const float* p1 = p0 + (1ull << 18);
    const float* p2 = p0 + (2ull << 18);
    float2 a = *reinterpret_cast<const float2*>(p0 + 2*t);
    float2 c2 = *reinterpret_cast<const float2*>(p1 + 2*t);
    float2 d = *reinterpret_cast<const float2*>(p2 + 2*t);
    float* ob = out + (size_t)row*1536 + 6*t;
    ob[0] = a.x; ob[1] = c2.x; ob[2] = d.x;
    ob[3] = a.y; ob[4] = c2.y; ob[5] = d.y;
}

// -------------------- fp16 warp-mma GEMM --------------------
#define LDR 40
#define STAGES 3
#define STG_ELEMS (128*LDR)
#define SMEM_BYTES (STAGES*2*STG_ELEMS*2) // 61440

__device__ __forceinline__ void f16_hi_pair(__half* p, int n, float v0, float v1) {
    __half h0 = __float2half_rn(v0);
    __half h1 = __float2half_rn(v1);
    *reinterpret_cast<uint32_t*>(p + n) =
        (uint32_t)h16bits(h0) | ((uint32_t)h16bits(h1) << 16);
}

__global__ __launch_bounds__(256, 2)
void mma_gemm(const __half* __restrict__ A, int lda, long long aZb, long long aZc,
              const __half* __restrict__ B, int ldb, long long bZb, long long bZc,
              int bKmask, int kzc, int nch, int zdiv, int mode,
              __half* outS, int ldo,
              const float* bias, const float* bias2, int relu,
              float* outF, int ldcM, long long cZb, long long cZc,
              const float* uArr, const float* vArr)
{
    extern __shared__ __half smem_dyn[];
    const int LDR2 = LDR*2;

    int tid = threadIdx.x;
    int z = blockIdx.z, zb = z / zdiv, zc = z - zb * zdiv;
    const __half* Ab = A + (size_t)zb*aZb + (size_t)zc*aZc + (size_t)(blockIdx.y*128)*lda;
    const __half* Bb = B + (size_t)zb*bZb + (size_t)zc*bZc + (size_t)(blockIdx.x*128)*ldb;
    int kOff = zc * kzc;
    int m0 = blockIdx.y * 128, n0 = blockIdx.x * 128;

    int lane = tid & 31, wid = tid >> 5;
    int wm = (wid & 1) * 64, wn = (wid >> 1) * 32;
    int ar = lane >> 2, ac = (lane & 3) * 2;

    int lrow = tid >> 2, lseg = tid & 3;
    uint32_t sAu = smem_u32(smem_dyn);
    uint32_t sBu = sAu + STAGES*STG_ELEMS*2;
    uint32_t lso = lrow*LDR2 + lseg*16;

    uint32_t aoff = (uint32_t)(wm + (lane & 15))*LDR2 + (lane >> 4)*16;
    uint32_t boff = (uint32_t)(wn + (lane & 7))*LDR2 + (lane >> 3)*16;

    float acc[4][4][4];
    #pragma unroll
    for (int i = 0; i < 4; i++)
        #pragma unroll
        for (int j = 0; j < 4; j++)
            #pragma unroll
            for (int q = 0; q < 4; q++) acc[i][j][q] = 0.f;

    #pragma unroll
    for (int p = 0; p < 2; p++) {
        int k0 = p * 32;
        int bk0 = (k0 + kOff) & bKmask;
        const __half* ga = Ab + (size_t)lrow*lda + k0 + lseg*8;
        const __half* gb = Bb + (size_t)lrow*ldb + bk0 + lseg*8;
        uint32_t da = sAu + p*(STG_ELEMS*2), db = sBu + p*(STG_ELEMS*2);
        cp16(da + lso, ga);            cp16(db + lso, gb);
        cp16(da + lso + 64*LDR2, ga + (size_t)64*lda);
        cp16(db + lso + 64*LDR2, gb + (size_t)64*ldb);
        cp_commit();
    }

    int slot = 0, lslot = 2;
    for (int c = 0; c < nch; c++) {
        if (c >= nch - 1) cp_wait0(); else cp_wait1();
        __syncthreads();

        if (c + 2 < nch) {
            int k0 = (c + 2) * 32;
            int bk0 = (k0 + kOff) & bKmask;
            const __half* ga = Ab + (size_t)lrow*lda + k0 + lseg*8;
            const __half* gb = Bb + (size_t)lrow*ldb + bk0 + lseg*8;
            uint32_t da = sAu + lslot*(STG_ELEMS*2), db = sBu + lslot*(STG_ELEMS*2);
            cp16(da + lso, ga);            cp16(db + lso, gb);
            cp16(da + lso + 64*LDR2, ga + (size_t)64*lda);
            cp16(db + lso + 64*LDR2, gb + (size_t)64*ldb);
            cp_commit();
            lslot++; if (lslot == STAGES) lslot = 0;
        }

        uint32_t sa = sAu + slot*(STG_ELEMS*2);
        uint32_t sbb = sBu + slot*(STG_ELEMS*2);
        slot++; if (slot == STAGES) slot = 0;

        uint32_t bf[4][4];
        #pragma unroll
        for (int nt = 0; nt < 4; nt++) ldm4(bf[nt], sbb + boff + nt*(8*LDR2));

        #pragma unroll
        for (int ks = 0; ks < 2; ks++) {
            uint32_t af[4][4];
            #pragma unroll
            for (int mt = 0; mt < 4; mt++)
                ldm4(af[mt], sa + aoff + mt*(16*LDR2) + ks*32);
            #pragma unroll
            for (int mt = 0; mt < 4; mt++)
                #pragma unroll
                for (int nt = 0; nt < 4; nt++)
                    mma16816_f16(acc[mt][nt], af[mt], &bf[nt][ks*2]);
        }
    }
    __syncthreads();

    // -------- epilogue --------
    if (mode == 2) {
        // fp16 hi output; optional per-z bias and relu
        const float* bs = (zc == 1 && bias2) ? bias2 : bias;
        __half* base = outS + (size_t)zb*cZb + (size_t)zc*cZc;
        #pragma unroll
        for (int mt = 0; mt < 4; mt++) {
            int m = m0 + wm + mt*16 + ar;
            __half* p0 = base + (size_t)m*ldo;
            __half* p1 = p0 + (size_t)8*ldo;
            #pragma unroll
            for (int nt = 0; nt < 4; nt++) {
                int n = n0 + wn + nt*8 + ac;
                float v0 = acc[mt][nt][0], v1 = acc[mt][nt][1];
                float v2 = acc[mt][nt][2], v3 = acc[mt][nt][3];
                if (bs) { v0 += bs[n]; v1 += bs[n+1]; v2 += bs[n]; v3 += bs[n+1]; }
                if (relu) { v0 = fmaxf(v0,0.f); v1 = fmaxf(v1,0.f); v2 = fmaxf(v2,0.f); v3 = fmaxf(v3,0.f); }
                f16_hi_pair(p0, n, v0, v1);
                f16_hi_pair(p1, n, v2, v3);
            }
        }
    } else if (mode == 5) {
        // plain float output, stride 1
        float* base = outF + (size_t)zb*cZb + (size_t)zc*cZc;
        #pragma unroll
        for (int mt = 0; mt < 4; mt++) {
            int m = m0 + wm + mt*16 + ar;
            float* p0 = base + (size_t)m*ldcM;
            float* p1 = p0 + (size_t)8*ldcM;
            #pragma unroll
            for (int nt = 0; nt < 4; nt++) {
                int n = n0 + wn + nt*8 + ac;
                p0[n] = acc[mt][nt][0]; p0[n+1] = acc[mt][nt][1];
                p1[n] = acc[mt][nt][2]; p1[n+1] = acc[mt][nt][3];
            }
        }
    } else {
        // mode 7: float + u/v, stride 1 (stage2 -> o3 planes)
        float* base = outF + (size_t)zb*cZb + (size_t)zc*cZc;
        const float* uz = uArr + (size_t)z*512;
        const float* vz = vArr + (size_t)z*512;
        #pragma unroll
        for (int mt = 0; mt < 4; mt++) {
            int m = m0 + wm + mt*16 + ar;
            float u0 = uz[m], u1 = uz[m + 8];
            float* p0 = base + (size_t)m*ldcM;
            float* p1 = p0 + (size_t)8*ldcM;
            #pragma unroll
            for (int nt = 0; nt < 4; nt++) {
                int n = n0 + wn + nt*8 + ac;
                float vn0 = vz[n], vn1 = vz[n + 1];
                p0[n]   = acc[mt][nt][0] + u0 + vn0;
                p0[n+1] = acc[mt][nt][1] + u0 + vn1;
                p1[n]   = acc[mt][nt][2] + u1 + vn0;
                p1[n+1] = acc[mt][nt][3] + u1 + vn1;
            }
        }
    }
}

// -------------------- launcher --------------------
extern "C" void kernel_launch(void* const* d_in, const int* in_sizes, int n_in,
                              void* d_out, int out_size) {
    const float* ctx  = (const float*)d_in[0];
    const float* ques = (const float*)d_in[1];
    const float* wsim = (const float*)d_in[2];
    const float* W1s  = (const float*)d_in[3];
    const float* b1s  = (const float*)d_in[4];
    const float* W2s  = (const float*)d_in[5];
    const float* b2s  = (const float*)d_in[6];
    const float* W1e  = (const float*)d_in[7];
    const float* b1e  = (const float*)d_in[8];
    const float* W2e  = (const float*)d_in[9];
    const float* b2e  = (const float*)d_in[10];
    const float* Wb   = (const float*)d_in[11];
    float* out = (float*)d_out;

    float *q2, *rowmax, *q2c, *qv, *rv, *s0, *s1, *uq, *vq, *u, *v, *Pp, *Mp, *o3;
    __half *xs, *h1, *w1, *w2sf, *w2ef, *wbtf, *Pf, *Mtf, *Tf;
    cudaGetSymbolAddress((void**)&q2, g_q2);
    cudaGetSymbolAddress((void**)&rowmax, g_rowmax);
    cudaGetSymbolAddress((void**)&q2c, g_q2c);
    cudaGetSymbolAddress((void**)&qv, g_qv);
    cudaGetSymbolAddress((void**)&rv, g_rv);
    cudaGetSymbolAddress((void**)&s0, g_s0);
    cudaGetSymbolAddress((void**)&s1, g_s1);
    cudaGetSymbolAddress((void**)&uq, g_uq);
    cudaGetSymbolAddress((void**)&vq, g_vq);
    cudaGetSymbolAddress((void**)&u, g_u);
    cudaGetSymbolAddress((void**)&v, g_v);
    cudaGetSymbolAddress((void**)&Pp, g_Pp);
    cudaGetSymbolAddress((void**)&Mp, g_Mp);
    cudaGetSymbolAddress((void**)&o3, g_o3);
    cudaGetSymbolAddress((void**)&xs, g_xs);
    cudaGetSymbolAddress((void**)&h1, g_h1);
    cudaGetSymbolAddress((void**)&w1, g_w1);
    cudaGetSymbolAddress((void**)&w2sf, g_w2sf);
    cudaGetSymbolAddress((void**)&w2ef, g_w2ef);
    cudaGetSymbolAddress((void**)&wbtf, g_wbtf);
    cudaGetSymbolAddress((void**)&Pf, g_Pf);
    cudaGetSymbolAddress((void**)&Mtf, g_Mtf);
    cudaGetSymbolAddress((void**)&Tf, g_Tf);

    __half* h1e = h1 + (size_t)ROWS*KHF;

    cudaFuncSetAttribute(mma_gemm, cudaFuncAttributeMaxDynamicSharedMemorySize, SMEM_BYTES);

    long long zero = 0;
    const int NOMASK = 0x7fffffff;

    // weight preps + rank-1 folding
    prep_wT<<<dim3(16, 32, 2), dim3(32, 8)>>>(W1s, W1e, W1e, 512,
        w1, (size_t)512*KW1, 1024, KW1, 512);
    prep_wT<<<dim3(32, 32, 3), dim3(32, 8)>>>(Wb, Wb + 1025, Wb + 2050, 3075,
        wbtf, (size_t)1024*1024, 1024, 1024, 1024);
    prep_w2<<<dim3(512, 4), 256>>>(W2s, W2e, w2sf, w2ef);
    qv_kernel<<<dim3(1024, 3), 128>>>(Wb, b2e, qv);
    rv_kernel<<<dim3(32, 3), dim3(32, 8)>>>(Wb, b2s, rv);
    scal_kernel<<<3, 256>>>(Wb, b2s, b2e, qv, s0, s1);
    uvq_kernel<<<dim3(512, 3), 128>>>(W2s, W2e, qv, rv, uq, vq);

    // preP split-K: z = c*4 + s; partial[s][c] = W2s(cols s*512..)@wbt(cols (s*512+k)&1023)
    mma_gemm<<<dim3(8, 4, 12), 256, SMEM_BYTES>>>(
        w2sf, 2048, zero, 512ll,
        wbtf, 1024, (long long)1024*1024, zero, 1023, 512,
        16, 4, 5, nullptr, 0, nullptr, nullptr, 0,
        Pp, 1024, (long long)512*1024, (long long)3*512*1024, nullptr, nullptr);
    reduceP_kernel<<<(3*512*1024)/256, 256>>>(Pp, Pf);

    // preMt split-K: z = c*4 + s
    mma_gemm<<<dim3(4, 4, 12), 256, SMEM_BYTES>>>(
        w2ef, 2048, zero, 512ll,
        Pf, 2048, (long long)512*2048, 512ll, NOMASK, 0,
        16, 4, 5, nullptr, 0, nullptr, nullptr, 0,
        Mp, 512, (long long)512*512, (long long)3*512*512, nullptr, nullptr);
    reduceMt_kernel<<<(3*512*512)/256, 256>>>(Mp, Mtf);

    // attention front-end
    qdot_kernel<<<dim3(Bz, LQ), 32>>>(ques, wsim, q2);
    sim_softmax_c2q_kernel<<<ROWS, 256>>>(ctx, ques, wsim, q2, xs, rowmax);
    bsoftmax_q2c_kernel<<<Bz, 256>>>(ctx, rowmax, q2c);
    fillx4_kernel<<<ROWS, 256>>>(ctx, q2c, xs);

    // FFW1: h1[z] = relu(x @ W1[z] + b1[z]) fp16 hi
    mma_gemm<<<dim3(4, 64, 2), 256, SMEM_BYTES>>>(
        xs, KXF, zero, zero,
        w1, KW1, zero, (long long)512*KW1, NOMASK, 0,
        32, 2, 2, h1, KHF, b1s, b1e, 1,
        nullptr, 0, zero, (long long)ROWS*KHF, nullptr, nullptr);

    // rank-1 terms from h1
    uv_kernel<<<ROWS, 256>>>(h1, uq, vq, s0, s1, u, v);

    // stage1: T[z=b*3+c] = h1s_b @ Mt_c^T  -> fp16 hi, K=512
    mma_gemm<<<dim3(4, 4, 48), 256, SMEM_BYTES>>>(
        h1, KHF, (long long)LC*KHF, zero,
        Mtf, 512, zero, (long long)512*512, NOMASK, 0,
        16, 3, 2, Tf, KHF, nullptr, nullptr, 0,
        nullptr, 0, (long long)3*LC*KHF, (long long)LC*KHF, nullptr, nullptr);

    // stage2: o3[z] = T[z] @ h1e_b^T + U + V  (coalesced float planes)
    mma_gemm<<<dim3(4, 4, 48), 256, SMEM_BYTES>>>(
        Tf, KHF, (long long)3*LC*KHF, (long long)LC*KHF,
        h1e, KHF, (long long)LC*KHF, zero, NOMASK, 0,
        16, 3, 7, nullptr, 0, nullptr, nullptr, 0,
        o3, 512, (long long)3*512*512, (long long)512*512, u, v);

    // interleave planes -> out[b,x,y,c]
    interleave_kernel<<<ROWS, 256>>>(o3, out);
}

// round 16
// speedup vs baseline: 3.6535x; 1.0252x over previous
#include <cuda_runtime.h>
#include <cuda_fp16.h>
#include <cstdint>
#include <math.h>

// Problem constants
#define Bz   16
#define LC   512
#define LQ   64
#define Hd   256
#define ROWS (Bz*LC)     // 8192

#define KXF  1024        // x hi, K=1024
#define KW1  1024        // W1^T hi
#define KHF  512         // h1 hi, K=512

// -------------------- device scratch (zero-init .bss) --------------------
__device__ float g_q2[Bz*LQ];
__device__ float g_rowmax[ROWS];
__device__ float g_q2c[Bz*Hd];
__device__ float g_qv[3*1024];
__device__ float g_rv[3*1024];
__device__ float g_s0[3];
__device__ float g_s1[3];
__device__ float g_uq[3*512];
__device__ float g_vq[3*512];
__device__ float g_u[48*512];
__device__ float g_v[48*512];
__device__ float g_Pp[(size_t)4*3*512*1024];   // preP K-split partials (fp32)
__device__ float g_Mp[(size_t)4*3*512*512];    // preMt K-split partials (fp32)
__device__ __align__(16) __half g_xs [(size_t)ROWS*KXF];
__device__ __align__(16) __half g_h1 [(size_t)2*ROWS*KHF];   // [start,end] hi
__device__ __align__(16) __half g_w1 [(size_t)2*512*KW1];    // [W1s,W1e]^T hi
__device__ __align__(16) __half g_w2sf[(size_t)512*2048];    // W2s [hi|lo]
__device__ __align__(16) __half g_w2ef[(size_t)512*2048];    // W2e [hi|hi]
__device__ __align__(16) __half g_wbtf[(size_t)3*1024*1024]; // Wb00^T hi
__device__ __align__(16) __half g_Pf [(size_t)3*512*2048];   // P [hi|lo]
__device__ __align__(16) __half g_Mtf[(size_t)3*512*512];    // Mt hi
__device__ __align__(16) __half g_Tf [(size_t)48*LC*KHF];    // T hi

// -------------------- helpers --------------------
__device__ __forceinline__ uint32_t smem_u32(const void* p) {
    uint32_t a;
    asm("{ .reg .u64 t; cvta.to.shared.u64 t, %1; cvt.u32.u64 %0, t; }" : "=r"(a) : "l"(p));
    return a;
}
__device__ __forceinline__ void cp16(uint32_t saddr, const void* g) {
    asm volatile("cp.async.ca.shared.global [%0], [%1], 16;" :: "r"(saddr), "l"(g) : "memory");
}
__device__ __forceinline__ void cp_commit() { asm volatile("cp.async.commit_group;" ::: "memory"); }
__device__ __forceinline__ void cp_wait0()  { asm volatile("cp.async.wait_group 0;" ::: "memory"); }
__device__ __forceinline__ void cp_wait1()  { asm volatile("cp.async.wait_group 1;" ::: "memory"); }

__device__ __forceinline__ unsigned short h16bits(__half h) {
    return *reinterpret_cast<unsigned short*>(&h);
}
__device__ __forceinline__ void ldm4(uint32_t* r, uint32_t saddr) {
    asm volatile("ldmatrix.sync.aligned.m8n8.x4.shared.b16 {%0,%1,%2,%3}, [%4];"
                 : "=r"(r[0]), "=r"(r[1]), "=r"(r[2]), "=r"(r[3]) : "r"(saddr));
}
__device__ __forceinline__ void mma16816_f16(float* c, const uint32_t* a, const uint32_t* b) {
    asm volatile(
        "mma.sync.aligned.m16n8k16.row.col.f32.f16.f16.f32 "
        "{%0,%1,%2,%3}, {%4,%5,%6,%7}, {%8,%9}, {%0,%1,%2,%3};"
        : "+f"(c[0]), "+f"(c[1]), "+f"(c[2]), "+f"(c[3])
        : "r"(a[0]), "r"(a[1]), "r"(a[2]), "r"(a[3]), "r"(b[0]), "r"(b[1]));
}
__device__ __forceinline__ float blk_reduce(float s, float* sm, int t, int nw) {
    int w = t >> 5, l = t & 31;
    #pragma unroll
    for (int o = 16; o > 0; o >>= 1) s += __shfl_down_sync(0xffffffffu, s, o);
    if (l == 0) sm[w] = s;
    __syncthreads();
    float r = 0.f;
    if (t == 0) for (int k = 0; k < nw; k++) r += sm[k];
    return r;
}

// -------------------- attention front-end --------------------
__global__ void qdot_kernel(const float* __restrict__ ques, const float* __restrict__ wsim,
                            float* __restrict__ q2) {
    int b = blockIdx.x, j = blockIdx.y, l = threadIdx.x;
    const float* q = ques + ((size_t)(b*LQ + j))*Hd;
    float s = 0.f;
    #pragma unroll
    for (int u = 0; u < Hd/32; u++) s += q[l + u*32] * wsim[Hd + l + u*32];
    #pragma unroll
    for (int o = 16; o > 0; o >>= 1) s += __shfl_down_sync(0xffffffffu, s, o);
    if (l == 0) q2[b*LQ + j] = s;
}

__global__ void sim_softmax_c2q_kernel(const float* __restrict__ ctx,
                                       const float* __restrict__ ques,
                                       const float* __restrict__ wsim,
                                       const float* __restrict__ q2,
                                       __half* __restrict__ xs,
                                       float* __restrict__ rowmax) {
    int row = blockIdx.x, b = row >> 9;
    int t = threadIdx.x, w = t >> 5, l = t & 31;
    __shared__ float ctxs[Hd], cw3[Hd], simv[LQ], sred[8];
    __shared__ float c1s;

    const float* crow = ctx + (size_t)row * Hd;
    float cv = crow[t];
    ctxs[t] = cv;
    cw3[t]  = cv * wsim[2*Hd + t];

    float v = cv * wsim[t];
    #pragma unroll
    for (int o = 16; o > 0; o >>= 1) v += __shfl_down_sync(0xffffffffu, v, o);
    if (l == 0) sred[w] = v;
    __syncthreads();
    if (t == 0) { float s = 0.f; for (int u = 0; u < 8; u++) s += sred[u]; c1s = s; }
    __syncthreads();

    const float* qb = ques + (size_t)b * LQ * Hd;
    #pragma unroll
    for (int jj = 0; jj < 8; jj++) {
        int j = w * 8 + jj;
        const float* q = qb + (size_t)j * Hd;
        float s = 0.f;
        #pragma unroll
        for (int u = 0; u < Hd/32; u++) s += cw3[l + u*32] * q[l + u*32];
        #pragma unroll
        for (int o = 16; o > 0; o >>= 1) s += __shfl_down_sync(0xffffffffu, s, o);
        if (l == 0) simv[j] = c1s + q2[b*LQ + j] + s;
    }
    __syncthreads();

    if (t < 32) {
        float s0 = simv[t], s1v = simv[t + 32];
        float m = fmaxf(s0, s1v);
        #pragma unroll
        for (int o = 16; o > 0; o >>= 1) m = fmaxf(m, __shfl_xor_sync(0xffffffffu, m, o));
        if (t == 0) rowmax[row] = m;
        float e0 = expf(s0 - m), e1v = expf(s1v - m);
        float sum = e0 + e1v;
        #pragma unroll
        for (int o = 16; o > 0; o >>= 1) sum += __shfl_xor_sync(0xffffffffu, sum, o);
        float inv = 1.f / sum;
        simv[t] = e0 * inv; simv[t + 32] = e1v * inv;
    }
    __syncthreads();

    float acc = 0.f;
    #pragma unroll 8
    for (int j = 0; j < LQ; j++) acc += simv[j] * qb[(size_t)j*Hd + t];

    __half* xr = xs + (size_t)row * KXF;
    xr[t]        = __float2half_rn(ctxs[t]);
    xr[Hd + t]   = __float2half_rn(acc);
    xr[2*Hd + t] = __float2half_rn(ctxs[t] * acc);
}

__global__ void bsoftmax_q2c_kernel(const float* __restrict__ ctx,
                                    const float* __restrict__ rowmax,
                                    float* __restrict__ q2c) {
    int b = blockIdx.x, t = threadIdx.x;
    __shared__ float w[LC]; __shared__ float sred[8]; __shared__ float mshared, sshared;
    w[t] = rowmax[b*LC + t]; w[t + 256] = rowmax[b*LC + t + 256];
    __syncthreads();
    float m = fmaxf(w[t], w[t + 256]);
    #pragma unroll
    for (int o = 16; o > 0; o >>= 1) m = fmaxf(m, __shfl_xor_sync(0xffffffffu, m, o));
    if ((t & 31) == 0) sred[t >> 5] = m;
    __syncthreads();
    if (t == 0) { float mm = sred[0]; for (int u = 1; u < 8; u++) mm = fmaxf(mm, sred[u]); mshared = mm; }
    __syncthreads();
    m = mshared;
    float e0 = expf(w[t] - m), e1v = expf(w[t + 256] - m);
    float s = e0 + e1v;
    #pragma unroll
    for (int o = 16; o > 0; o >>= 1) s += __shfl_xor_sync(0xffffffffu, s, o);
    if ((t & 31) == 0) sred[t >> 5] = s;
    __syncthreads();
    if (t == 0) { float ss = 0.f; for (int u = 0; u < 8; u++) ss += sred[u]; sshared = ss; }
    __syncthreads();
    float inv = 1.f / sshared;
    w[t] = e0 * inv; w[t + 256] = e1v * inv;
    __syncthreads();
    float acc = 0.f;
    const float* cb = ctx + (size_t)b * LC * Hd;
    for (int i = 0; i < LC; i++) acc += w[i] * cb[(size_t)i*Hd + t];
    q2c[b*Hd + t] = acc;
}

__global__ void fillx4_kernel(const float* __restrict__ ctx,
                              const float* __restrict__ q2c,
                              __half* __restrict__ xs) {
    int row = blockIdx.x, t = threadIdx.x, b = row >> 9;
    float c = ctx[(size_t)row*Hd + t];
    xs[(size_t)row*KXF + 3*Hd + t] = __float2half_rn(c * q2c[b*Hd + t]);
}

// -------------------- rank-1 / bias folding (fp32, exact) --------------------
__global__ void qv_kernel(const float* __restrict__ Wb, const float* __restrict__ b2e,
                          float* __restrict__ qv) {
    int t = blockIdx.x, c = blockIdx.y, l = threadIdx.x;   // block 128
    __shared__ float sm[4];
    const float* rowt = Wb + (size_t)t*3075 + c*1025;
    float a = 0.f;
    for (int j = l; j < 1024; j += 128) a += rowt[j] * b2e[j];
    float r = blk_reduce(a, sm, l, 4);
    if (l == 0) qv[c*1024 + t] = r + rowt[1024];
}

__global__ void rv_kernel(const float* __restrict__ Wb, const float* __restrict__ b2s,
                          float* __restrict__ rv) {
    int c = blockIdx.y;
    int t = blockIdx.x * 32 + threadIdx.x;
    int ty = threadIdx.y;
    __shared__ float sm[8][32];
    float a = 0.f;
    for (int j = ty; j < 1024; j += 8)
        a += b2s[j] * Wb[(size_t)j*3075 + c*1025 + t];
    sm[ty][threadIdx.x] = a;
    __syncthreads();
    if (ty == 0) {
        float s = 0.f;
        #pragma unroll
        for (int k = 0; k < 8; k++) s += sm[k][threadIdx.x];
        rv[c*1024 + t] = s + Wb[(size_t)1024*3075 + c*1025 + t];
    }
}

__global__ void scal_kernel(const float* __restrict__ Wb, const float* __restrict__ b2s,
                            const float* __restrict__ b2e, const float* __restrict__ qv,
                            float* __restrict__ s0, float* __restrict__ s1) {
    int c = blockIdx.x, t = threadIdx.x;
    __shared__ float sm[8];
    float a0 = 0.f, a1 = 0.f;
    for (int k = t; k < 1024; k += 256) {
        a0 += b2s[k] * qv[c*1024 + k];
        a1 += b2e[k] * Wb[(size_t)1024*3075 + c*1025 + k];
    }
    float r0 = blk_reduce(a0, sm, t, 8);
    if (t == 0) s0[c] = r0 + Wb[(size_t)1024*3075 + c*1025 + 1024];
    __syncthreads();
    float r1 = blk_reduce(a1, sm, t, 8);
    if (t == 0) s1[c] = r1;
}

__global__ void uvq_kernel(const float* __restrict__ W2s, const float* __restrict__ W2e,
                           const float* __restrict__ qv, const float* __restrict__ rv,
                           float* __restrict__ uq, float* __restrict__ vq) {
    int i = blockIdx.x, c = blockIdx.y, l = threadIdx.x;
    __shared__ float sm[4];
    float a0 = 0.f, a1 = 0.f;
    for (int k = l; k < 1024; k += 128) {
        a0 += W2s[(size_t)i*1024 + k] * qv[c*1024 + k];
        a1 += W2e[(size_t)i*1024 + k] * rv[c*1024 + k];
    }
    float r0 = blk_reduce(a0, sm, l, 4);
    if (l == 0) uq[c*512 + i] = r0;
    __syncthreads();
    float r1 = blk_reduce(a1, sm, l, 4);
    if (l == 0) vq[c*512 + i] = r1;
}

__global__ void uv_kernel(const __half* __restrict__ h1,
                          const float* __restrict__ uq, const float* __restrict__ vq,
                          const float* __restrict__ s0, const float* __restrict__ s1,
                          float* __restrict__ u, float* __restrict__ v) {
    int row = blockIdx.x, t = threadIdx.x, w = t >> 5, l = t & 31;
    int b = row >> 9, x = row & 511;
    const __half* hs = h1 + (size_t)row*KHF;
    const __half* he = h1 + (size_t)ROWS*KHF + (size_t)row*KHF;
    float a[6] = {0,0,0,0,0,0};
    for (int k = t; k < 512; k += 256) {
        float sv = __half2float(hs[k]);
        float ev = __half2float(he[k]);
        #pragma unroll
        for (int c = 0; c < 3; c++) {
            a[c]     += sv * uq[c*512 + k];
            a[3 + c] += ev * vq[c*512 + k];
        }
    }
    __shared__ float red[6][8];
    #pragma unroll
    for (int q = 0; q < 6; q++) {
        float s = a[q];
        #pragma unroll
        for (int o = 16; o > 0; o >>= 1) s += __shfl_down_sync(0xffffffffu, s, o);
        if (l == 0) red[q][w] = s;
    }
    __syncthreads();
    if (t < 6) {
        float s = 0.f;
        #pragma unroll
        for (int k = 0; k < 8; k++) s += red[t][k];
        if (t < 3) u[(b*3 + t)*512 + x] = s + s0[t];
        else       v[(b*3 + (t - 3))*512 + x] = s + s1[t - 3];
    }
}

// -------------------- weight preps --------------------
__global__ void prep_wT(const float* __restrict__ a0, const float* __restrict__ a1,
                        const float* __restrict__ a2, int srcLd,
                        __half* __restrict__ dst, size_t dstZ,
                        int Kreal, int Kpad, int Nrows) {
    const float* src = (blockIdx.z == 0) ? a0 : ((blockIdx.z == 1) ? a1 : a2);
    __half* d = dst + blockIdx.z * dstZ;
    __shared__ float tile[32][33];
    int k0 = blockIdx.y*32, n0 = blockIdx.x*32;
    int tx = threadIdx.x, ty = threadIdx.y;
    #pragma unroll
    for (int i = 0; i < 32; i += 8) {
        int k = k0 + ty + i, n = n0 + tx;
        tile[ty + i][tx] = (k < Kreal && n < Nrows) ? src[(size_t)k*srcLd + n] : 0.f;
    }
    __syncthreads();
    #pragma unroll
    for (int i = 0; i < 32; i += 8) {
        int n = n0 + ty + i, k = k0 + tx;
        if (n < Nrows)
            d[(size_t)n*Kpad + k] = __float2half_rn(tile[tx][ty + i]);
    }
}

__global__ void prep_w2(const float* __restrict__ W2s, const float* __restrict__ W2e,
                        __half* __restrict__ w2sf, __half* __restrict__ w2ef) {
    int i = blockIdx.x;
    int t = blockIdx.y*256 + threadIdx.x;
    float vs = W2s[(size_t)i*1024 + t];
    __half hs = __float2half_rn(vs);
    __half ls = __float2half_rn(vs - __half2float(hs));
    w2sf[(size_t)i*2048 + t] = hs;
    w2sf[(size_t)i*2048 + 1024 + t] = ls;
    float ve = W2e[(size_t)i*1024 + t];
    __half he = __float2half_rn(ve);
    w2ef[(size_t)i*2048 + t] = he;
    w2ef[(size_t)i*2048 + 1024 + t] = he;
}

__global__ void reduceP_kernel(const float* __restrict__ Pp, __half* __restrict__ Pf) {
    size_t e = (size_t)blockIdx.x*256 + threadIdx.x;
    const size_t PL = (size_t)3*512*1024;
    float s = Pp[e] + Pp[e + PL] + Pp[e + 2*PL] + Pp[e + 3*PL];
    int c = e >> 19;
    int rem = e & 524287;
    int i = rem >> 10, t = rem & 1023;
    __half hi = __float2half_rn(s);
    __half lo = __float2half_rn(s - __half2float(hi));
    size_t base = (size_t)c*512*2048 + (size_t)i*2048 + t;
    Pf[base] = hi; Pf[base + 1024] = lo;
}

__global__ void reduceMt_kernel(const float* __restrict__ Mp, __half* __restrict__ Mtf) {
    size_t e = (size_t)blockIdx.x*256 + threadIdx.x;
    const size_t ML = (size_t)3*512*512;
    float s = Mp[e] + Mp[e + ML] + Mp[e + 2*ML] + Mp[e + 3*ML];
    Mtf[e] = __float2half_rn(s);
}

// -------------------- fp16 warp-mma GEMM --------------------
#define LDR 40
#define STAGES 3
#define STG_ELEMS (128*LDR)
#define SMEM_BYTES (STAGES*2*STG_ELEMS*2) // 61440

__device__ __forceinline__ void f16_hi_pair(__half* p, int n, float v0, float v1) {
    __half h0 = __float2half_rn(v0);
    __half h1 = __float2half_rn(v1);
    *reinterpret_cast<uint32_t*>(p + n) =
        (uint32_t)h16bits(h0) | ((uint32_t)h16bits(h1) << 16);
}

__global__ __launch_bounds__(256, 2)
void mma_gemm(const __half* __restrict__ A, int lda, long long aZb, long long aZc,
              const __half* __restrict__ B, int ldb, long long bZb, long long bZc,
              int bKmask, int kzc, int nch, int zdiv, int mode,
              __half* outS, int ldo,
              const float* bias, const float* bias2, int relu,
              float* outF, int ldcM, long long cZb, long long cZc,
              const float* uArr, const float* vArr)
{
    extern __shared__ __half smem_dyn[];
    const int LDR2 = LDR*2;

    int tid = threadIdx.x;
    int z = blockIdx.z, zb = z / zdiv, zc = z - zb * zdiv;
    const __half* Ab = A + (size_t)zb*aZb + (size_t)zc*aZc + (size_t)(blockIdx.y*128)*lda;
    const __half* Bb = B + (size_t)zb*bZb + (size_t)zc*bZc + (size_t)(blockIdx.x*128)*ldb;
    int kOff = zc * kzc;
    int m0 = blockIdx.y * 128, n0 = blockIdx.x * 128;

    int lane = tid & 31, wid = tid >> 5;
    int wm = (wid & 1) * 64, wn = (wid >> 1) * 32;
    int ar = lane >> 2, ac = (lane & 3) * 2;

    int lrow = tid >> 2, lseg = tid & 3;
    uint32_t sAu = smem_u32(smem_dyn);
    uint32_t sBu = sAu + STAGES*STG_ELEMS*2;
    uint32_t lso = lrow*LDR2 + lseg*16;

    uint32_t aoff = (uint32_t)(wm + (lane & 15))*LDR2 + (lane >> 4)*16;
    uint32_t boff = (uint32_t)(wn + (lane & 7))*LDR2 + (lane >> 3)*16;

    float acc[4][4][4];
    #pragma unroll
    for (int i = 0; i < 4; i++)
        #pragma unroll
        for (int j = 0; j < 4; j++)
            #pragma unroll
            for (int q = 0; q < 4; q++) acc[i][j][q] = 0.f;

    #pragma unroll
    for (int p = 0; p < 2; p++) {
        int k0 = p * 32;
        int bk0 = (k0 + kOff) & bKmask;
        const __half* ga = Ab + (size_t)lrow*lda + k0 + lseg*8;
        const __half* gb = Bb + (size_t)lrow*ldb + bk0 + lseg*8;
        uint32_t da = sAu + p*(STG_ELEMS*2), db = sBu + p*(STG_ELEMS*2);
        cp16(da + lso, ga);            cp16(db + lso, gb);
        cp16(da + lso + 64*LDR2, ga + (size_t)64*lda);
        cp16(db + lso + 64*LDR2, gb + (size_t)64*ldb);
        cp_commit();
    }

    int slot = 0, lslot = 2;
    for (int c = 0; c < nch; c++) {
        if (c >= nch - 1) cp_wait0(); else cp_wait1();
        __syncthreads();

        if (c + 2 < nch) {
            int k0 = (c + 2) * 32;
            int bk0 = (k0 + kOff) & bKmask;
            const __half* ga = Ab + (size_t)lrow*lda + k0 + lseg*8;
            const __half* gb = Bb + (size_t)lrow*ldb + bk0 + lseg*8;
            uint32_t da = sAu + lslot*(STG_ELEMS*2), db = sBu + lslot*(STG_ELEMS*2);
            cp16(da + lso, ga);            cp16(db + lso, gb);
            cp16(da + lso + 64*LDR2, ga + (size_t)64*lda);
            cp16(db + lso + 64*LDR2, gb + (size_t)64*ldb);
            cp_commit();
            lslot++; if (lslot == STAGES) lslot = 0;
        }

        uint32_t sa = sAu + slot*(STG_ELEMS*2);
        uint32_t sbb = sBu + slot*(STG_ELEMS*2);
        slot++; if (slot == STAGES) slot = 0;

        uint32_t bf[4][4];
        #pragma unroll
        for (int nt = 0; nt < 4; nt++) ldm4(bf[nt], sbb + boff + nt*(8*LDR2));

        #pragma unroll
        for (int ks = 0; ks < 2; ks++) {
            uint32_t af[4][4];
            #pragma unroll
            for (int mt = 0; mt < 4; mt++)
                ldm4(af[mt], sa + aoff + mt*(16*LDR2) + ks*32);
            #pragma unroll
            for (int mt = 0; mt < 4; mt++)
                #pragma unroll
                for (int nt = 0; nt < 4; nt++)
                    mma16816_f16(acc[mt][nt], af[mt], &bf[nt][ks*2]);
        }
    }
    __syncthreads();

    // -------- epilogue --------
    if (mode == 2) {
        // fp16 hi output; optional per-z bias and relu
        const float* bs = (zc == 1 && bias2) ? bias2 : bias;
        __half* base = outS + (size_t)zb*cZb + (size_t)zc*cZc;
        #pragma unroll
        for (int mt = 0; mt < 4; mt++) {
            int m = m0 + wm + mt*16 + ar;
            __half* p0 = base + (size_t)m*ldo;
            __half* p1 = p0 + (size_t)8*ldo;
            #pragma unroll
            for (int nt = 0; nt < 4; nt++) {
                int n = n0 + wn + nt*8 + ac;
                float v0 = acc[mt][nt][0], v1 = acc[mt][nt][1];
                float v2 = acc[mt][nt][2], v3 = acc[mt][nt][3];
                if (bs) { v0 += bs[n]; v1 += bs[n+1]; v2 += bs[n]; v3 += bs[n+1]; }
                if (relu) { v0 = fmaxf(v0,0.f); v1 = fmaxf(v1,0.f); v2 = fmaxf(v2,0.f); v3 = fmaxf(v3,0.f); }
                f16_hi_pair(p0, n, v0, v1);
                f16_hi_pair(p1, n, v2, v3);
            }
        }
    } else if (mode == 5) {
        // plain float output, stride 1 (split-K partials)
        float* base = outF + (size_t)zb*cZb + (size_t)zc*cZc;
        #pragma unroll
        for (int mt = 0; mt < 4; mt++) {
            int m = m0 + wm + mt*16 + ar;
            float* p0 = base + (size_t)m*ldcM;
            float* p1 = p0 + (size_t)8*ldcM;
            #pragma unroll
            for (int nt = 0; nt < 4; nt++) {
                int n = n0 + wn + nt*8 + ac;
                p0[n] = acc[mt][nt][0]; p0[n+1] = acc[mt][nt][1];
                p1[n] = acc[mt][nt][2]; p1[n+1] = acc[mt][nt][3];
            }
        }
    } else {
        // mode 4: float interleaved (col stride 3) + u/v  (stage2 -> out)
        float* base = outF + (size_t)zb*cZb + (size_t)zc*cZc;
        const float* uz = uArr + (size_t)z*512;
        const float* vz = vArr + (size_t)z*512;
        #pragma unroll
        for (int mt = 0; mt < 4; mt++) {
            int m = m0 + wm + mt*16 + ar;
            float u0 = uz[m], u1 = uz[m + 8];
            float* p0 = base + (size_t)m*ldcM;
            float* p1 = p0 + (size_t)8*ldcM;
            #pragma unroll
            for (int nt = 0; nt < 4; nt++) {
                int n = n0 + wn + nt*8 + ac;
                float vn0 = vz[n], vn1 = vz[n + 1];
                p0[(size_t)n*3]     = acc[mt][nt][0] + u0 + vn0;
                p0[(size_t)(n+1)*3] = acc[mt][nt][1] + u0 + vn1;
                p1[(size_t)n*3]     = acc[mt][nt][2] + u1 + vn0;
                p1[(size_t)(n+1)*3] = acc[mt][nt][3] + u1 + vn1;
            }
        }
    }
}

// -------------------- launcher --------------------
extern "C" void kernel_launch(void* const* d_in, const int* in_sizes, int n_in,
                              void* d_out, int out_size) {
    const float* ctx  = (const float*)d_in[0];
    const float* ques = (const float*)d_in[1];
    const float* wsim = (const float*)d_in[2];
    const float* W1s  = (const float*)d_in[3];
    const float* b1s  = (const float*)d_in[4];
    const float* W2s  = (const float*)d_in[5];
    const float* b2s  = (const float*)d_in[6];
    const float* W1e  = (const float*)d_in[7];
    const float* b1e  = (const float*)d_in[8];
    const float* W2e  = (const float*)d_in[9];
    const float* b2e  = (const float*)d_in[10];
    const float* Wb   = (const float*)d_in[11];
    float* out = (float*)d_out;

    float *q2, *rowmax, *q2c, *qv, *rv, *s0, *s1, *uq, *vq, *u, *v, *Pp, *Mp;
    __half *xs, *h1, *w1, *w2sf, *w2ef, *wbtf, *Pf, *Mtf, *Tf;
    cudaGetSymbolAddress((void**)&q2, g_q2);
    cudaGetSymbolAddress((void**)&rowmax, g_rowmax);
    cudaGetSymbolAddress((void**)&q2c, g_q2c);
    cudaGetSymbolAddress((void**)&qv, g_qv);
    cudaGetSymbolAddress((void**)&rv, g_rv);
    cudaGetSymbolAddress((void**)&s0, g_s0);
    cudaGetSymbolAddress((void**)&s1, g_s1);
    cudaGetSymbolAddress((void**)&uq, g_uq);
    cudaGetSymbolAddress((void**)&vq, g_vq);
    cudaGetSymbolAddress((void**)&u, g_u);
    cudaGetSymbolAddress((void**)&v, g_v);
    cudaGetSymbolAddress((void**)&Pp, g_Pp);
    cudaGetSymbolAddress((void**)&Mp, g_Mp);
    cudaGetSymbolAddress((void**)&xs, g_xs);
    cudaGetSymbolAddress((void**)&h1, g_h1);
    cudaGetSymbolAddress((void**)&w1, g_w1);
    cudaGetSymbolAddress((void**)&w2sf, g_w2sf);
    cudaGetSymbolAddress((void**)&w2ef, g_w2ef);
    cudaGetSymbolAddress((void**)&wbtf, g_wbtf);
    cudaGetSymbolAddress((void**)&Pf, g_Pf);
    cudaGetSymbolAddress((void**)&Mtf, g_Mtf);
    cudaGetSymbolAddress((void**)&Tf, g_Tf);

    __half* h1e = h1 + (size_t)ROWS*KHF;

    cudaFuncSetAttribute(mma_gemm, cudaFuncAttributeMaxDynamicSharedMemorySize, SMEM_BYTES);

    long long zero = 0;
    const int NOMASK = 0x7fffffff;

    // weight preps + rank-1 folding
    prep_wT<<<dim3(16, 32, 2), dim3(32, 8)>>>(W1s, W1e, W1e, 512,
        w1, (size_t)512*KW1, 1024, KW1, 512);
    prep_wT<<<dim3(32, 32, 3), dim3(32, 8)>>>(Wb, Wb + 1025, Wb + 2050, 3075,
        wbtf, (size_t)1024*1024, 1024, 1024, 1024);
    prep_w2<<<dim3(512, 4), 256>>>(W2s, W2e, w2sf, w2ef);
    qv_kernel<<<dim3(1024, 3), 128>>>(Wb, b2e, qv);
    rv_kernel<<<dim3(32, 3), dim3(32, 8)>>>(Wb, b2s, rv);
    scal_kernel<<<3, 256>>>(Wb, b2s, b2e, qv, s0, s1);
    uvq_kernel<<<dim3(512, 3), 128>>>(W2s, W2e, qv, rv, uq, vq);

    // preP split-K: z = c*4 + s
    mma_gemm<<<dim3(8, 4, 12), 256, SMEM_BYTES>>>(
        w2sf, 2048, zero, 512ll,
        wbtf, 1024, (long long)1024*1024, zero, 1023, 512,
        16, 4, 5, nullptr, 0, nullptr, nullptr, 0,
        Pp, 1024, (long long)512*1024, (long long)3*512*1024, nullptr, nullptr);
    reduceP_kernel<<<(3*512*1024)/256, 256>>>(Pp, Pf);

    // preMt split-K: z = c*4 + s
    mma_gemm<<<dim3(4, 4, 12), 256, SMEM_BYTES>>>(
        w2ef, 2048, zero, 512ll,
        Pf, 2048, (long long)512*2048, 512ll, NOMASK, 0,
        16, 4, 5, nullptr, 0, nullptr, nullptr, 0,
        Mp, 512, (long long)512*512, (long long)3*512*512, nullptr, nullptr);
    reduceMt_kernel<<<(3*512*512)/256, 256>>>(Mp, Mtf);

    // attention front-end
    qdot_kernel<<<dim3(Bz, LQ), 32>>>(ques, wsim, q2);
    sim_softmax_c2q_kernel<<<ROWS, 256>>>(ctx, ques, wsim, q2, xs, rowmax);
    bsoftmax_q2c_kernel<<<Bz, 256>>>(ctx, rowmax, q2c);
    fillx4_kernel<<<ROWS, 256>>>(ctx, q2c, xs);

    // FFW1: h1[z] = relu(x @ W1[z] + b1[z]) fp16 hi
    mma_gemm<<<dim3(4, 64, 2), 256, SMEM_BYTES>>>(
        xs, KXF, zero, zero,
        w1, KW1, zero, (long long)512*KW1, NOMASK, 0,
        32, 2, 2, h1, KHF, b1s, b1e, 1,
        nullptr, 0, zero, (long long)ROWS*KHF, nullptr, nullptr);

    // rank-1 terms from h1
    uv_kernel<<<ROWS, 256>>>(h1, uq, vq, s0, s1, u, v);

    // stage1: T[z=b*3+c] = h1s_b @ Mt_c^T  -> fp16 hi, K=512
    mma_gemm<<<dim3(4, 4, 48), 256, SMEM_BYTES>>>(
        h1, KHF, (long long)LC*KHF, zero,
        Mtf, 512, zero, (long long)512*512, NOMASK, 0,
        16, 3, 2, Tf, KHF, nullptr, nullptr, 0,
        nullptr, 0, (long long)3*LC*KHF, (long long)LC*KHF, nullptr, nullptr);

    // stage2: out[b,:,:,c] = T[z] @ h1e_b^T + U + V  (direct interleaved write)
    mma_gemm<<<dim3(4, 4, 48), 256, SMEM_BYTES>>>(
        Tf, KHF, (long long)3*LC*KHF, (long long)LC*KHF,
        h1e, KHF, (long long)LC*KHF, zero, NOMASK, 0,
        16, 3, 4, nullptr, 0, nullptr, nullptr, 0,
        out, LC*3, (long long)LC*LC*3, 1ll, u, v);
}

// round 17
// speedup vs baseline: 3.8140x; 1.0439x over previous
#include <cuda_runtime.h>
#include <cuda_fp16.h>
#include <cstdint>
#include <math.h>

// Problem constants
#define Bz   16
#define LC   512
#define LQ   64
#define Hd   256
#define ROWS (Bz*LC)     // 8192

#define KXF  1024        // x hi, K=1024
#define KW1  1024        // W1^T hi
#define KHF  512         // h1 hi, K=512

// -------------------- device scratch (zero-init .bss) --------------------
__device__ float g_q2[Bz*LQ];
__device__ float g_rowmax[ROWS];
__device__ float g_q2c[Bz*Hd];
__device__ float g_qv[3*1024];
__device__ float g_rv[3*1024];
__device__ float g_qvp[(size_t)3*1024*32];
__device__ float g_rvp[(size_t)3*1024*32];
__device__ float g_s0[3];
__device__ float g_s1[3];
__device__ float g_uq[3*512];
__device__ float g_vq[3*512];
__device__ float g_u[48*512];
__device__ float g_v[48*512];
__device__ float g_Pp[(size_t)4*3*512*1024];   // preP K-split partials (fp32)
__device__ float g_Mp[(size_t)4*3*512*512];    // preMt K-split partials (fp32)
__device__ __align__(16) __half g_xs [(size_t)ROWS*KXF];
__device__ __align__(16) __half g_h1 [(size_t)2*ROWS*KHF];   // [start,end] hi
__device__ __align__(16) __half g_w1 [(size_t)2*512*KW1];    // [W1s,W1e]^T hi
__device__ __align__(16) __half g_w2sf[(size_t)512*1024];    // W2s hi
__device__ __align__(16) __half g_w2ef[(size_t)512*2048];    // W2e [hi|hi]
__device__ __align__(16) __half g_wbtf[(size_t)3*1024*1024]; // Wb00^T hi
__device__ __align__(16) __half g_Pf [(size_t)3*512*2048];   // P [hi|lo]
__device__ __align__(16) __half g_Mtf[(size_t)3*512*512];    // Mt hi
__device__ __align__(16) __half g_Tf [(size_t)48*LC*KHF];    // T hi

// -------------------- helpers --------------------
__device__ __forceinline__ uint32_t smem_u32(const void* p) {
    uint32_t a;
    asm("{ .reg .u64 t; cvta.to.shared.u64 t, %1; cvt.u32.u64 %0, t; }" : "=r"(a) : "l"(p));
    return a;
}
__device__ __forceinline__ void cp16(uint32_t saddr, const void* g) {
    asm volatile("cp.async.ca.shared.global [%0], [%1], 16;" :: "r"(saddr), "l"(g) : "memory");
}
__device__ __forceinline__ void cp_commit() { asm volatile("cp.async.commit_group;" ::: "memory"); }
__device__ __forceinline__ void cp_wait0()  { asm volatile("cp.async.wait_group 0;" ::: "memory"); }
__device__ __forceinline__ void cp_wait1()  { asm volatile("cp.async.wait_group 1;" ::: "memory"); }

__device__ __forceinline__ unsigned short h16bits(__half h) {
    return *reinterpret_cast<unsigned short*>(&h);
}
__device__ __forceinline__ void ldm4(uint32_t* r, uint32_t saddr) {
    asm volatile("ldmatrix.sync.aligned.m8n8.x4.shared.b16 {%0,%1,%2,%3}, [%4];"
                 : "=r"(r[0]), "=r"(r[1]), "=r"(r[2]), "=r"(r[3]) : "r"(saddr));
}
__device__ __forceinline__ void mma16816_f16(float* c, const uint32_t* a, const uint32_t* b) {
    asm volatile(
        "mma.sync.aligned.m16n8k16.row.col.f32.f16.f16.f32 "
        "{%0,%1,%2,%3}, {%4,%5,%6,%7}, {%8,%9}, {%0,%1,%2,%3};"
        : "+f"(c[0]), "+f"(c[1]), "+f"(c[2]), "+f"(c[3])
        : "r"(a[0]), "r"(a[1]), "r"(a[2]), "r"(a[3]), "r"(b[0]), "r"(b[1]));
}
__device__ __forceinline__ float blk_reduce(float s, float* sm, int t, int nw) {
    int w = t >> 5, l = t & 31;
    #pragma unroll
    for (int o = 16; o > 0; o >>= 1) s += __shfl_down_sync(0xffffffffu, s, o);
    if (l == 0) sm[w] = s;
    __syncthreads();
    float r = 0.f;
    if (t == 0) for (int k = 0; k < nw; k++) r += sm[k];
    return r;
}

// -------------------- attention front-end --------------------
__global__ void qdot_kernel(const float* __restrict__ ques, const float* __restrict__ wsim,
                            float* __restrict__ q2) {
    int b = blockIdx.x, j = blockIdx.y, l = threadIdx.x;
    const float* q = ques + ((size_t)(b*LQ + j))*Hd;
    float s = 0.f;
    #pragma unroll
    for (int u = 0; u < Hd/32; u++) s += q[l + u*32] * wsim[Hd + l + u*32];
    #pragma unroll
    for (int o = 16; o > 0; o >>= 1) s += __shfl_down_sync(0xffffffffu, s, o);
    if (l == 0) q2[b*LQ + j] = s;
}

__global__ void sim_softmax_c2q_kernel(const float* __restrict__ ctx,
                                       const float* __restrict__ ques,
                                       const float* __restrict__ wsim,
                                       const float* __restrict__ q2,
                                       __half* __restrict__ xs,
                                       float* __restrict__ rowmax) {
    int row = blockIdx.x, b = row >> 9;
    int t = threadIdx.x, w = t >> 5, l = t & 31;
    __shared__ float ctxs[Hd], cw3[Hd], simv[LQ], sred[8];
    __shared__ float c1s;

    const float* crow = ctx + (size_t)row * Hd;
    float cv = crow[t];
    ctxs[t] = cv;
    cw3[t]  = cv * wsim[2*Hd + t];

    float v = cv * wsim[t];
    #pragma unroll
    for (int o = 16; o > 0; o >>= 1) v += __shfl_down_sync(0xffffffffu, v, o);
    if (l == 0) sred[w] = v;
    __syncthreads();
    if (t == 0) { float s = 0.f; for (int u = 0; u < 8; u++) s += sred[u]; c1s = s; }
    __syncthreads();

    const float* qb = ques + (size_t)b * LQ * Hd;
    #pragma unroll
    for (int jj = 0; jj < 8; jj++) {
        int j = w * 8 + jj;
        const float* q = qb + (size_t)j * Hd;
        float s = 0.f;
        #pragma unroll
        for (int u = 0; u < Hd/32; u++) s += cw3[l + u*32] * q[l + u*32];
        #pragma unroll
        for (int o = 16; o > 0; o >>= 1) s += __shfl_down_sync(0xffffffffu, s, o);
        if (l == 0) simv[j] = c1s + q2[b*LQ + j] + s;
    }
    __syncthreads();

    if (t < 32) {
        float s0 = simv[t], s1v = simv[t + 32];
        float m = fmaxf(s0, s1v);
        #pragma unroll
        for (int o = 16; o > 0; o >>= 1) m = fmaxf(m, __shfl_xor_sync(0xffffffffu, m, o));
        if (t == 0) rowmax[row] = m;
        float e0 = expf(s0 - m), e1v = expf(s1v - m);
        float sum = e0 + e1v;
        #pragma unroll
        for (int o = 16; o > 0; o >>= 1) sum += __shfl_xor_sync(0xffffffffu, sum, o);
        float inv = 1.f / sum;
        simv[t] = e0 * inv; simv[t + 32] = e1v * inv;
    }
    __syncthreads();

    float acc = 0.f;
    #pragma unroll 8
    for (int j = 0; j < LQ; j++) acc += simv[j] * qb[(size_t)j*Hd + t];

    __half* xr = xs + (size_t)row * KXF;
    xr[t]        = __float2half_rn(ctxs[t]);
    xr[Hd + t]   = __float2half_rn(acc);
    xr[2*Hd + t] = __float2half_rn(ctxs[t] * acc);
}

__global__ void bsoftmax_q2c_kernel(const float* __restrict__ ctx,
                                    const float* __restrict__ rowmax,
                                    float* __restrict__ q2c) {
    int b = blockIdx.x, t = threadIdx.x;
    __shared__ float w[LC]; __shared__ float sred[8]; __shared__ float mshared, sshared;
    w[t] = rowmax[b*LC + t]; w[t + 256] = rowmax[b*LC + t + 256];
    __syncthreads();
    float m = fmaxf(w[t], w[t + 256]);
    #pragma unroll
    for (int o = 16; o > 0; o >>= 1) m = fmaxf(m, __shfl_xor_sync(0xffffffffu, m, o));
    if ((t & 31) == 0) sred[t >> 5] = m;
    __syncthreads();
    if (t == 0) { float mm = sred[0]; for (int u = 1; u < 8; u++) mm = fmaxf(mm, sred[u]); mshared = mm; }
    __syncthreads();
    m = mshared;
    float e0 = expf(w[t] - m), e1v = expf(w[t + 256] - m);
    float s = e0 + e1v;
    #pragma unroll
    for (int o = 16; o > 0; o >>= 1) s += __shfl_xor_sync(0xffffffffu, s, o);
    if ((t & 31) == 0) sred[t >> 5] = s;
    __syncthreads();
    if (t == 0) { float ss = 0.f; for (int u = 0; u < 8; u++) ss += sred[u]; sshared = ss; }
    __syncthreads();
    float inv = 1.f / sshared;
    w[t] = e0 * inv; w[t + 256] = e1v * inv;
    __syncthreads();
    float acc = 0.f;
    const float* cb = ctx + (size_t)b * LC * Hd;
    for (int i = 0; i < LC; i++) acc += w[i] * cb[(size_t)i*Hd + t];
    q2c[b*Hd + t] = acc;
}

__global__ void fillx4_kernel(const float* __restrict__ ctx,
                              const float* __restrict__ q2c,
                              __half* __restrict__ xs) {
    int row = blockIdx.x, t = threadIdx.x, b = row >> 9;
    float c = ctx[(size_t)row*Hd + t];
    xs[(size_t)row*KXF + 3*Hd + t] = __float2half_rn(c * q2c[b*Hd + t]);
}

// -------------------- fused Wb pass: transpose + qv/rv partials --------------------
// grid (32 ktile, 32 ttile, 3), block (32, 8)
__global__ void wb_fused(const float* __restrict__ Wb,
                         const float* __restrict__ b2s, const float* __restrict__ b2e,
                         __half* __restrict__ wbtf,
                         float* __restrict__ qvp, float* __restrict__ rvp) {
    int c = blockIdx.z;
    int k0 = blockIdx.x*32, t0 = blockIdx.y*32;
    int tx = threadIdx.x, ty = threadIdx.y;
    __shared__ float tile[32][33];
    #pragma unroll
    for (int i = 0; i < 32; i += 8) {
        int t = t0 + ty + i;
        tile[ty + i][tx] = Wb[(size_t)t*3075 + c*1025 + k0 + tx];
    }
    __syncthreads();
    // transposed fp16 write: wbtf[c][k][t]
    __half* wb = wbtf + (size_t)c*1024*1024;
    #pragma unroll
    for (int i = 0; i < 32; i += 8)
        wb[(size_t)(k0 + ty + i)*1024 + t0 + tx] = __float2half_rn(tile[tx][ty + i]);
    // qv partial: per t (=tx), sum over k
    float aq = 0.f;
    for (int k = ty; k < 32; k += 8) aq += tile[tx][k] * b2e[k0 + k];
    // rv partial: per k (=tx), sum over t
    float ar = 0.f;
    for (int t = ty; t < 32; t += 8) ar += b2s[t0 + t] * tile[t][tx];
    __shared__ float rq[8][32], rr[8][32];
    rq[ty][tx] = aq; rr[ty][tx] = ar;
    __syncthreads();
    if (ty == 0) {
        float s = 0.f;
        #pragma unroll
        for (int k = 0; k < 8; k++) s += rq[k][tx];
        qvp[((size_t)(c*1024 + t0 + tx))*32 + blockIdx.x] = s;
    }
    if (ty == 1) {
        float s = 0.f;
        #pragma unroll
        for (int k = 0; k < 8; k++) s += rr[k][tx];
        rvp[((size_t)(c*1024 + k0 + tx))*32 + blockIdx.y] = s;
    }
}

__global__ void qr_reduce(const float* __restrict__ Wb,
                          const float* __restrict__ qvp, const float* __restrict__ rvp,
                          float* __restrict__ qv, float* __restrict__ rv) {
    int e = blockIdx.x*256 + threadIdx.x;      // < 3*1024
    int c = e >> 10, t = e & 1023;
    float s = 0.f, s2 = 0.f;
    #pragma unroll 8
    for (int k = 0; k < 32; k++) { s += qvp[(size_t)e*32 + k]; s2 += rvp[(size_t)e*32 + k]; }
    qv[e] = s + Wb[(size_t)t*3075 + c*1025 + 1024];
    rv[e] = s2 + Wb[(size_t)1024*3075 + c*1025 + t];
}

__global__ void scal_kernel(const float* __restrict__ Wb, const float* __restrict__ b2s,
                            const float* __restrict__ b2e, const float* __restrict__ qv,
                            float* __restrict__ s0, float* __restrict__ s1) {
    int c = blockIdx.x, t = threadIdx.x;
    __shared__ float sm[8];
    float a0 = 0.f, a1 = 0.f;
    for (int k = t; k < 1024; k += 256) {
        a0 += b2s[k] * qv[c*1024 + k];
        a1 += b2e[k] * Wb[(size_t)1024*3075 + c*1025 + k];
    }
    float r0 = blk_reduce(a0, sm, t, 8);
    if (t == 0) s0[c] = r0 + Wb[(size_t)1024*3075 + c*1025 + 1024];
    __syncthreads();
    float r1 = blk_reduce(a1, sm, t, 8);
    if (t == 0) s1[c] = r1;
}

__global__ void uvq_kernel(const float* __restrict__ W2s, const float* __restrict__ W2e,
                           const float* __restrict__ qv, const float* __restrict__ rv,
                           float* __restrict__ uq, float* __restrict__ vq) {
    int i = blockIdx.x, c = blockIdx.y, l = threadIdx.x;
    __shared__ float sm[4];
    float a0 = 0.f, a1 = 0.f;
    for (int k = l; k < 1024; k += 128) {
        a0 += W2s[(size_t)i*1024 + k] * qv[c*1024 + k];
        a1 += W2e[(size_t)i*1024 + k] * rv[c*1024 + k];
    }
    float r0 = blk_reduce(a0, sm, l, 4);
    if (l == 0) uq[c*512 + i] = r0;
    __syncthreads();
    float r1 = blk_reduce(a1, sm, l, 4);
    if (l == 0) vq[c*512 + i] = r1;
}

__global__ void uv_kernel(const __half* __restrict__ h1,
                          const float* __restrict__ uq, const float* __restrict__ vq,
                          const float* __restrict__ s0, const float* __restrict__ s1,
                          float* __restrict__ u, float* __restrict__ v) {
    int row = blockIdx.x, t = threadIdx.x, w = t >> 5, l = t & 31;
    int b = row >> 9, x = row & 511;
    const __half* hs = h1 + (size_t)row*KHF;
    const __half* he = h1 + (size_t)ROWS*KHF + (size_t)row*KHF;
    float a[6] = {0,0,0,0,0,0};
    for (int k = t; k < 512; k += 256) {
        float sv = __half2float(hs[k]);
        float ev = __half2float(he[k]);
        #pragma unroll
        for (int c = 0; c < 3; c++) {
            a[c]     += sv * uq[c*512 + k];
            a[3 + c] += ev * vq[c*512 + k];
        }
    }
    __shared__ float red[6][8];
    #pragma unroll
    for (int q = 0; q < 6; q++) {
        float s = a[q];
        #pragma unroll
        for (int o = 16; o > 0; o >>= 1) s += __shfl_down_sync(0xffffffffu, s, o);
        if (l == 0) red[q][w] = s;
    }
    __syncthreads();
    if (t < 6) {
        float s = 0.f;
        #pragma unroll
        for (int k = 0; k < 8; k++) s += red[t][k];
        if (t < 3) u[(b*3 + t)*512 + x] = s + s0[t];
        else       v[(b*3 + (t - 3))*512 + x] = s + s1[t - 3];
    }
}

// -------------------- weight preps --------------------
__global__ void prep_wT(const float* __restrict__ a0, const float* __restrict__ a1,
                        const float* __restrict__ a2, int srcLd,
                        __half* __restrict__ dst, size_t dstZ,
                        int Kreal, int Kpad, int Nrows) {
    const float* src = (blockIdx.z == 0) ? a0 : ((blockIdx.z == 1) ? a1 : a2);
    __half* d = dst + blockIdx.z * dstZ;
    __shared__ float tile[32][33];
    int k0 = blockIdx.y*32, n0 = blockIdx.x*32;
    int tx = threadIdx.x, ty = threadIdx.y;
    #pragma unroll
    for (int i = 0; i < 32; i += 8) {
        int k = k0 + ty + i, n = n0 + tx;
        tile[ty + i][tx] = (k < Kreal && n < Nrows) ? src[(size_t)k*srcLd + n] : 0.f;
    }
    __syncthreads();
    #pragma unroll
    for (int i = 0; i < 32; i += 8) {
        int n = n0 + ty + i, k = k0 + tx;
        if (n < Nrows)
            d[(size_t)n*Kpad + k] = __float2half_rn(tile[tx][ty + i]);
    }
}

// W2s -> hi [512x1024]; W2e -> [hi|hi] [512x2048]
__global__ void prep_w2(const float* __restrict__ W2s, const float* __restrict__ W2e,
                        __half* __restrict__ w2sf, __half* __restrict__ w2ef) {
    int i = blockIdx.x;
    int t = blockIdx.y*256 + threadIdx.x;
    w2sf[(size_t)i*1024 + t] = __float2half_rn(W2s[(size_t)i*1024 + t]);
    float ve = W2e[(size_t)i*1024 + t];
    __half he = __float2half_rn(ve);
    w2ef[(size_t)i*2048 + t] = he;
    w2ef[(size_t)i*2048 + 1024 + t] = he;
}

__global__ void reduceP_kernel(const float* __restrict__ Pp, __half* __restrict__ Pf) {
    size_t e = (size_t)blockIdx.x*256 + threadIdx.x;
    const size_t PL = (size_t)3*512*1024;
    float s = Pp[e] + Pp[e + PL] + Pp[e + 2*PL] + Pp[e + 3*PL];
    int c = e >> 19;
    int rem = e & 524287;
    int i = rem >> 10, t = rem & 1023;
    __half hi = __float2half_rn(s);
    __half lo = __float2half_rn(s - __half2float(hi));
    size_t base = (size_t)c*512*2048 + (size_t)i*2048 + t;
    Pf[base] = hi; Pf[base + 1024] = lo;
}

__global__ void reduceMt_kernel(const float* __restrict__ Mp, __half* __restrict__ Mtf) {
    size_t e = (size_t)blockIdx.x*256 + threadIdx.x;
    const size_t ML = (size_t)3*512*512;
    float s = Mp[e] + Mp[e + ML] + Mp[e + 2*ML] + Mp[e + 3*ML];
    Mtf[e] = __float2half_rn(s);
}

// -------------------- fp16 warp-mma GEMM --------------------
#define LDR 40
#define STAGES 3
#define STG_ELEMS (128*LDR)
#define SMEM_BYTES (STAGES*2*STG_ELEMS*2) // 61440

__device__ __forceinline__ void f16_hi_pair(__half* p, int n, float v0, float v1) {
    __half h0 = __float2half_rn(v0);
    __half h1 = __float2half_rn(v1);
    *reinterpret_cast<uint32_t*>(p + n) =
        (uint32_t)h16bits(h0) | ((uint32_t)h16bits(h1) << 16);
}

__global__ __launch_bounds__(256, 2)
void mma_gemm(const __half* __restrict__ A, int lda, long long aZb, long long aZc,
              const __half* __restrict__ B, int ldb, long long bZb, long long bZc,
              int bKmask, int kzc, int nch, int zdiv, int mode,
              __half* outS, int ldo,
              const float* bias, const float* bias2, int relu,
              float* outF, int ldcM, long long cZb, long long cZc,
              const float* uArr, const float* vArr)
{
    extern __shared__ __half smem_dyn[];
    const int LDR2 = LDR*2;

    int tid = threadIdx.x;
    int z = blockIdx.z, zb = z / zdiv, zc = z - zb * zdiv;
    const __half* Ab = A + (size_t)zb*aZb + (size_t)zc*aZc + (size_t)(blockIdx.y*128)*lda;
    const __half* Bb = B + (size_t)zb*bZb + (size_t)zc*bZc + (size_t)(blockIdx.x*128)*ldb;
    int kOff = zc * kzc;
    int m0 = blockIdx.y * 128, n0 = blockIdx.x * 128;

    int lane = tid & 31, wid = tid >> 5;
    int wm = (wid & 1) * 64, wn = (wid >> 1) * 32;
    int ar = lane >> 2, ac = (lane & 3) * 2;

    int lrow = tid >> 2, lseg = tid & 3;
    uint32_t sAu = smem_u32(smem_dyn);
    uint32_t sBu = sAu + STAGES*STG_ELEMS*2;
    uint32_t lso = lrow*LDR2 + lseg*16;

    uint32_t aoff = (uint32_t)(wm + (lane & 15))*LDR2 + (lane >> 4)*16;
    uint32_t boff = (uint32_t)(wn + (lane & 7))*LDR2 + (lane >> 3)*16;

    float acc[4][4][4];
    #pragma unroll
    for (int i = 0; i < 4; i++)
        #pragma unroll
        for (int j = 0; j < 4; j++)
            #pragma unroll
            for (int q = 0; q < 4; q++) acc[i][j][q] = 0.f;

    #pragma unroll
    for (int p = 0; p < 2; p++) {
        int k0 = p * 32;
        int bk0 = (k0 + kOff) & bKmask;
        const __half* ga = Ab + (size_t)lrow*lda + k0 + lseg*8;
        const __half* gb = Bb + (size_t)lrow*ldb + bk0 + lseg*8;
        uint32_t da = sAu + p*(STG_ELEMS*2), db = sBu + p*(STG_ELEMS*2);
        cp16(da + lso, ga);            cp16(db + lso, gb);
        cp16(da + lso + 64*LDR2, ga + (size_t)64*lda);
        cp16(db + lso + 64*LDR2, gb + (size_t)64*ldb);
        cp_commit();
    }

    int slot = 0, lslot = 2;
    for (int c = 0; c < nch; c++) {
        if (c >= nch - 1) cp_wait0(); else cp_wait1();
        __syncthreads();

        if (c + 2 < nch) {
            int k0 = (c + 2) * 32;
            int bk0 = (k0 + kOff) & bKmask;
            const __half* ga = Ab + (size_t)lrow*lda + k0 + lseg*8;
            const __half* gb = Bb + (size_t)lrow*ldb + bk0 + lseg*8;
            uint32_t da = sAu + lslot*(STG_ELEMS*2), db = sBu + lslot*(STG_ELEMS*2);
            cp16(da + lso, ga);            cp16(db + lso, gb);
            cp16(da + lso + 64*LDR2, ga + (size_t)64*lda);
            cp16(db + lso + 64*LDR2, gb + (size_t)64*ldb);
            cp_commit();
            lslot++; if (lslot == STAGES) lslot = 0;
        }

        uint32_t sa = sAu + slot*(STG_ELEMS*2);
        uint32_t sbb = sBu + slot*(STG_ELEMS*2);
        slot++; if (slot == STAGES) slot = 0;

        uint32_t bf[4][4];
        #pragma unroll
        for (int nt = 0; nt < 4; nt++) ldm4(bf[nt], sbb + boff + nt*(8*LDR2));

        #pragma unroll
        for (int ks = 0; ks < 2; ks++) {
            uint32_t af[4][4];
            #pragma unroll
            for (int mt = 0; mt < 4; mt++)
                ldm4(af[mt], sa + aoff + mt*(16*LDR2) + ks*32);
            #pragma unroll
            for (int mt = 0; mt < 4; mt++)
                #pragma unroll
                for (int nt = 0; nt < 4; nt++)
                    mma16816_f16(acc[mt][nt], af[mt], &bf[nt][ks*2]);
        }
    }
    __syncthreads();

    // -------- epilogue --------
    if (mode == 2) {
        const float* bs = (zc == 1 && bias2) ? bias2 : bias;
        __half* base = outS + (size_t)zb*cZb + (size_t)zc*cZc;
        #pragma unroll
        for (int mt = 0; mt < 4; mt++) {
            int m = m0 + wm + mt*16 + ar;
            __half* p0 = base + (size_t)m*ldo;
            __half* p1 = p0 + (size_t)8*ldo;
            #pragma unroll
            for (int nt = 0; nt < 4; nt++) {
                int n = n0 + wn + nt*8 + ac;
                float v0 = acc[mt][nt][0], v1 = acc[mt][nt][1];
                float v2 = acc[mt][nt][2], v3 = acc[mt][nt][3];
                if (bs) { v0 += bs[n]; v1 += bs[n+1]; v2 += bs[n]; v3 += bs[n+1]; }
                if (relu) { v0 = fmaxf(v0,0.f); v1 = fmaxf(v1,0.f); v2 = fmaxf(v2,0.f); v3 = fmaxf(v3,0.f); }
                f16_hi_pair(p0, n, v0, v1);
                f16_hi_pair(p1, n, v2, v3);
            }
        }
    } else if (mode == 5) {
        float* base = outF + (size_t)zb*cZb + (size_t)zc*cZc;
        #pragma unroll
        for (int mt = 0; mt < 4; mt++) {
            int m = m0 + wm + mt*16 + ar;
            float* p0 = base + (size_t)m*ldcM;
            float* p1 = p0 + (size_t)8*ldcM;
            #pragma unroll
            for (int nt = 0; nt < 4; nt++) {
                int n = n0 + wn + nt*8 + ac;
                p0[n] = acc[mt][nt][0]; p0[n+1] = acc[mt][nt][1];
                p1[n] = acc[mt][nt][2]; p1[n+1] = acc[mt][nt][3];
            }
        }
    } else {
        // mode 4: float interleaved (col stride 3) + u/v
        float* base = outF + (size_t)zb*cZb + (size_t)zc*cZc;
        const float* uz = uArr + (size_t)z*512;
        const float* vz = vArr + (size_t)z*512;
        #pragma unroll
        for (int mt = 0; mt < 4; mt++) {
            int m = m0 + wm + mt*16 + ar;
            float u0 = uz[m], u1 = uz[m + 8];
            float* p0 = base + (size_t)m*ldcM;
            float* p1 = p0 + (size_t)8*ldcM;
            #pragma unroll
            for (int nt = 0; nt < 4; nt++) {
                int n = n0 + wn + nt*8 + ac;
                float vn0 = vz[n], vn1 = vz[n + 1];
                p0[(size_t)n*3]     = acc[mt][nt][0] + u0 + vn0;
                p0[(size_t)(n+1)*3] = acc[mt][nt][1] + u0 + vn1;
                p1[(size_t)n*3]     = acc[mt][nt][2] + u1 + vn0;
                p1[(size_t)(n+1)*3] = acc[mt][nt][3] + u1 + vn1;
            }
        }
    }
}

// -------------------- launcher --------------------
extern "C" void kernel_launch(void* const* d_in, const int* in_sizes, int n_in,
                              void* d_out, int out_size) {
    const float* ctx  = (const float*)d_in[0];
    const float* ques = (const float*)d_in[1];
    const float* wsim = (const float*)d_in[2];
    const float* W1s  = (const float*)d_in[3];
    const float* b1s  = (const float*)d_in[4];
    const float* W2s  = (const float*)d_in[5];
    const float* b2s  = (const float*)d_in[6];
    const float* W1e  = (const float*)d_in[7];
    const float* b1e  = (const float*)d_in[8];
    const float* W2e  = (const float*)d_in[9];
    const float* b2e  = (const float*)d_in[10];
    const float* Wb   = (const float*)d_in[11];
    float* out = (float*)d_out;

    float *q2, *rowmax, *q2c, *qv, *rv, *qvp, *rvp, *s0, *s1, *uq, *vq, *u, *v, *Pp, *Mp;
    __half *xs, *h1, *w1, *w2sf, *w2ef, *wbtf, *Pf, *Mtf, *Tf;
    cudaGetSymbolAddress((void**)&q2, g_q2);
    cudaGetSymbolAddress((void**)&rowmax, g_rowmax);
    cudaGetSymbolAddress((void**)&q2c, g_q2c);
    cudaGetSymbolAddress((void**)&qv, g_qv);
    cudaGetSymbolAddress((void**)&rv, g_rv);
    cudaGetSymbolAddress((void**)&qvp, g_qvp);
    cudaGetSymbolAddress((void**)&rvp, g_rvp);
    cudaGetSymbolAddress((void**)&s0, g_s0);
    cudaGetSymbolAddress((void**)&s1, g_s1);
    cudaGetSymbolAddress((void**)&uq, g_uq);
    cudaGetSymbolAddress((void**)&vq, g_vq);
    cudaGetSymbolAddress((void**)&u, g_u);
    cudaGetSymbolAddress((void**)&v, g_v);
    cudaGetSymbolAddress((void**)&Pp, g_Pp);
    cudaGetSymbolAddress((void**)&Mp, g_Mp);
    cudaGetSymbolAddress((void**)&xs, g_xs);
    cudaGetSymbolAddress((void**)&h1, g_h1);
    cudaGetSymbolAddress((void**)&w1, g_w1);
    cudaGetSymbolAddress((void**)&w2sf, g_w2sf);
    cudaGetSymbolAddress((void**)&w2ef, g_w2ef);
    cudaGetSymbolAddress((void**)&wbtf, g_wbtf);
    cudaGetSymbolAddress((void**)&Pf, g_Pf);
    cudaGetSymbolAddress((void**)&Mtf, g_Mtf);
    cudaGetSymbolAddress((void**)&Tf, g_Tf);

    __half* h1e = h1 + (size_t)ROWS*KHF;

    cudaFuncSetAttribute(mma_gemm, cudaFuncAttributeMaxDynamicSharedMemorySize, SMEM_BYTES);

    long long zero = 0;
    const int NOMASK = 0x7fffffff;

    // fused Wb pass: wbt transpose + qv/rv partials (single Wb read)
    wb_fused<<<dim3(32, 32, 3), dim3(32, 8)>>>(Wb, b2s, b2e, wbtf, qvp, rvp);
    qr_reduce<<<12, 256>>>(Wb, qvp, rvp, qv, rv);
    prep_wT<<<dim3(16, 32, 2), dim3(32, 8)>>>(W1s, W1e, W1e, 512,
        w1, (size_t)512*KW1, 1024, KW1, 512);
    prep_w2<<<dim3(512, 4), 256>>>(W2s, W2e, w2sf, w2ef);
    scal_kernel<<<3, 256>>>(Wb, b2s, b2e, qv, s0, s1);
    uvq_kernel<<<dim3(512, 3), 128>>>(W2s, W2e, qv, rv, uq, vq);

    // preP split-K (W2s hi, K=1024, 4 splits of 256): z = c*4 + s
    mma_gemm<<<dim3(8, 4, 12), 256, SMEM_BYTES>>>(
        w2sf, 1024, zero, 256ll,
        wbtf, 1024, (long long)1024*1024, zero, 1023, 256,
        8, 4, 5, nullptr, 0, nullptr, nullptr, 0,
        Pp, 1024, (long long)512*1024, (long long)3*512*1024, nullptr, nullptr);
    reduceP_kernel<<<(3*512*1024)/256, 256>>>(Pp, Pf);

    // preMt split-K (W2e hi|hi x P hi|lo over 2048, 4 splits of 512)
    mma_gemm<<<dim3(4, 4, 12), 256, SMEM_BYTES>>>(
        w2ef, 2048, zero, 512ll,
        Pf, 2048, (long long)512*2048, 512ll, NOMASK, 0,
        16, 4, 5, nullptr, 0, nullptr, nullptr, 0,
        Mp, 512, (long long)512*512, (long long)3*512*512, nullptr, nullptr);
    reduceMt_kernel<<<(3*512*512)/256, 256>>>(Mp, Mtf);

    // attention front-end
    qdot_kernel<<<dim3(Bz, LQ), 32>>>(ques, wsim, q2);
    sim_softmax_c2q_kernel<<<ROWS, 256>>>(ctx, ques, wsim, q2, xs, rowmax);
    bsoftmax_q2c_kernel<<<Bz, 256>>>(ctx, rowmax, q2c);
    fillx4_kernel<<<ROWS, 256>>>(ctx, q2c, xs);

    // FFW1: h1[z] = relu(x @ W1[z] + b1[z]) fp16 hi
    mma_gemm<<<dim3(4, 64, 2), 256, SMEM_BYTES>>>(
        xs, KXF, zero, zero,
        w1, KW1, zero, (long long)512*KW1, NOMASK, 0,
        32, 2, 2, h1, KHF, b1s, b1e, 1,
        nullptr, 0, zero, (long long)ROWS*KHF, nullptr, nullptr);

    // rank-1 terms from h1
    uv_kernel<<<ROWS, 256>>>(h1, uq, vq, s0, s1, u, v);

    // stage1: T[z=b*3+c] = h1s_b @ Mt_c^T  -> fp16 hi, K=512
    mma_gemm<<<dim3(4, 4, 48), 256, SMEM_BYTES>>>(
        h1, KHF, (long long)LC*KHF, zero,
        Mtf, 512, zero, (long long)512*512, NOMASK, 0,
        16, 3, 2, Tf, KHF, nullptr, nullptr, 0,
        nullptr, 0, (long long)3*LC*KHF, (long long)LC*KHF, nullptr, nullptr);

    // stage2: out[b,:,:,c] = T[z] @ h1e_b^T + U + V  (direct interleaved write)
    mma_gemm<<<dim3(4, 4, 48), 256, SMEM_BYTES>>>(
        Tf, KHF, (long long)3*LC*KHF, (long long)LC*KHF,
        h1e, KHF, (long long)LC*KHF, zero, NOMASK, 0,
        16, 3, 4, nullptr, 0, nullptr, nullptr, 0,
        out, LC*3, (long long)LC*LC*3, 1ll, u, v);
}